// round 6
// baseline (speedup 1.0000x reference)
#include <cuda_runtime.h>
#include <cuda_bf16.h>
#include <math.h>
#include <stdint.h>

// Problem constants: B=8, T=512, N=128, F=16, H=32, L=4
#define BTNH_ 16777216ull   // 8*512*128*32

// Scratch (allocation-free: static device globals)
__device__ float g_xa[16777216];
__device__ float g_xb[16777216];
__device__ float g_xres[16777216];
__device__ float g_tcn[4ull * 16777216ull];  // [l][b][t][n][o]

// ---------------------------------------------------------------------------
// K1: input projection (measured 100us, unchanged)
// ---------------------------------------------------------------------------
__global__ void __launch_bounds__(256) k_inproj(const float* __restrict__ X,
                                                const float* __restrict__ in_w,
                                                const float* __restrict__ in_b) {
    __shared__ float sw[1536];
    __shared__ float sb[96];
    for (int i = threadIdx.x; i < 1536; i += 256) sw[i] = in_w[i];
    if (threadIdx.x < 96) sb[threadIdx.x] = in_b[threadIdx.x];
    __syncthreads();

    int o = threadIdx.x & 31;
    int rsub = threadIdx.x >> 5;
#pragma unroll
    for (int gph = 0; gph < 8; gph++) {
        int row = blockIdx.x * 64 + gph * 8 + rsub;
        const float4* xr = (const float4*)(X + (size_t)row * 16);
        float4 v0 = xr[0], v1 = xr[1], v2 = xr[2], v3 = xr[3];
        float x[16] = {v0.x, v0.y, v0.z, v0.w, v1.x, v1.y, v1.z, v1.w,
                       v2.x, v2.y, v2.z, v2.w, v3.x, v3.y, v3.z, v3.w};
        float a0 = sb[o], a1 = sb[32 + o], a2 = sb[64 + o];
#pragma unroll
        for (int f = 0; f < 16; f++) {
            float xv = x[f];
            a0 = fmaf(xv, sw[f * 96 + o], a0);
            a1 = fmaf(xv, sw[f * 96 + 32 + o], a1);
            a2 = fmaf(xv, sw[f * 96 + 64 + o], a2);
        }
        size_t p = (size_t)row * 32 + o;
        g_xa[p] = a0;
        g_xb[p] = a1;
        g_xres[p] = a2;
    }
}

// ---------------------------------------------------------------------------
// K2: gated dilated causal convs, 4tau x 8o tiles (round-5 form, unchanged)
// ---------------------------------------------------------------------------
#define CVX_SXA 0
#define CVX_SXB 16896
#define CVX_WA  33792
#define CVX_WB  35840
#define CVX_BA  37888
#define CVX_BB  37920
#define CVX_TOT 37952

template <int D>
__device__ __forceinline__ void conv8x4(const float* __restrict__ S,
                                        const float* __restrict__ W,
                                        const float* __restrict__ Bv,
                                        int tau0, int o0, float acc[32]) {
    float b0[8];
#pragma unroll
    for (int u = 0; u < 8; u++) b0[u] = Bv[o0 + u];
#pragma unroll
    for (int t = 0; t < 4; t++)
#pragma unroll
        for (int u = 0; u < 8; u++) acc[t * 8 + u] = b0[u];

#pragma unroll 4
    for (int c = 0; c < 32; c++) {
        const float* row = S + c * 528 + 16 + tau0;
        float4 x1 = *(const float4*)row;
        float xs1[4] = {x1.x, x1.y, x1.z, x1.w};
        float xs0[4];
        if (D == 1) {
            float p = row[-1];
            xs0[0] = p; xs0[1] = x1.x; xs0[2] = x1.y; xs0[3] = x1.z;
        } else if (D == 2) {
            float2 p = *(const float2*)(row - 2);
            xs0[0] = p.x; xs0[1] = p.y; xs0[2] = x1.x; xs0[3] = x1.y;
        } else {
            float4 p = *(const float4*)(row - D);
            xs0[0] = p.x; xs0[1] = p.y; xs0[2] = p.z; xs0[3] = p.w;
        }
        float4 wa = *(const float4*)(W + c * 32 + o0);
        float4 wb = *(const float4*)(W + c * 32 + o0 + 4);
        float4 va = *(const float4*)(W + 1024 + c * 32 + o0);
        float4 vb = *(const float4*)(W + 1024 + c * 32 + o0 + 4);
        float w0v[8] = {wa.x, wa.y, wa.z, wa.w, wb.x, wb.y, wb.z, wb.w};
        float w1v[8] = {va.x, va.y, va.z, va.w, vb.x, vb.y, vb.z, vb.w};
#pragma unroll
        for (int t = 0; t < 4; t++)
#pragma unroll
            for (int u = 0; u < 8; u++)
                acc[t * 8 + u] =
                    fmaf(w1v[u], xs1[t], fmaf(w0v[u], xs0[t], acc[t * 8 + u]));
    }
}

template <int D>
__device__ __forceinline__ void conv_layer(const float* __restrict__ sm,
                                           float* __restrict__ outp,
                                           int tau0, int o0) {
    float ta[32];
    conv8x4<D>(sm + CVX_SXA, sm + CVX_WA, sm + CVX_BA, tau0, o0, ta);
#pragma unroll
    for (int k = 0; k < 32; k++) {
        float t = __expf(-2.f * fabsf(ta[k]));
        float r = (1.f - t) / (1.f + t);
        ta[k] = copysignf(r, ta[k]);
    }
    float sg[32];
    conv8x4<D>(sm + CVX_SXB, sm + CVX_WB, sm + CVX_BB, tau0, o0, sg);
#pragma unroll
    for (int k = 0; k < 32; k++) {
        float s = 1.f / (1.f + __expf(-sg[k]));
        sg[k] = ta[k] * s;
    }
#pragma unroll
    for (int t = 0; t < 4; t++) {
        float* p = outp + (size_t)t * 4096;
        ((float4*)p)[0] = make_float4(sg[t * 8 + 0], sg[t * 8 + 1],
                                      sg[t * 8 + 2], sg[t * 8 + 3]);
        ((float4*)p)[1] = make_float4(sg[t * 8 + 4], sg[t * 8 + 5],
                                      sg[t * 8 + 6], sg[t * 8 + 7]);
    }
}

__global__ void __launch_bounds__(512) k_conv(const float* __restrict__ ct_w,
                                              const float* __restrict__ ct_b,
                                              const float* __restrict__ cs_w,
                                              const float* __restrict__ cs_b) {
    extern __shared__ float sm[];
    int tid = threadIdx.x;
    int bn = blockIdx.x;
    int b = bn >> 7, n = bn & 127;
    int ty = tid & 127, tx = tid >> 7;
    int tau0 = ty * 4, o0 = tx * 8;

    if (tid < 512) {
        int c = tid >> 4, m = tid & 15;
        sm[CVX_SXA + c * 528 + m] = 0.f;
        sm[CVX_SXB + c * 528 + m] = 0.f;
    }
    const float* xa = g_xa + (size_t)bn * 16384;
    const float* xb = g_xb + (size_t)bn * 16384;
    for (int i = tid; i < 4096; i += 512) {
        float4 va = ((const float4*)xa)[i];
        float4 vb = ((const float4*)xb)[i];
        int tau = i >> 3, c0 = (i & 7) * 4;
        float* pa = sm + CVX_SXA + c0 * 528 + 16 + tau;
        float* pb = sm + CVX_SXB + c0 * 528 + 16 + tau;
        pa[0] = va.x; pa[528] = va.y; pa[1056] = va.z; pa[1584] = va.w;
        pb[0] = vb.x; pb[528] = vb.y; pb[1056] = vb.z; pb[1584] = vb.w;
    }

    float* outp0 = g_tcn + ((size_t)((b * 512 + tau0) * 128 + n)) * 32 + o0;

    for (int l = 0; l < 4; l++) {
        __syncthreads();
        for (int i = tid; i < 2048; i += 512) {
            sm[CVX_WA + i] = ct_w[l * 2048 + i];
            sm[CVX_WB + i] = cs_w[l * 2048 + i];
        }
        if (tid < 32) {
            sm[CVX_BA + tid] = ct_b[l * 32 + tid];
            sm[CVX_BB + tid] = cs_b[l * 32 + tid];
        }
        __syncthreads();
        float* outp = outp0 + (size_t)l * BTNH_;
        if (l == 0) conv_layer<1>(sm, outp, tau0, o0);
        else if (l == 1) conv_layer<2>(sm, outp, tau0, o0);
        else if (l == 2) conv_layer<4>(sm, outp, tau0, o0);
        else conv_layer<8>(sm, outp, tau0, o0);
    }
}

// ---------------------------------------------------------------------------
// K3: A-mix via mma.sync.m16n8k16 bf16 (split hi/lo, 3 passes) + SIMT epilogue.
// 128 threads (4 warps) per (b,t) CTA; warp w owns m-rows [32w, 32w+32).
// smem byte offsets:
#define SAH_B   0         // A hi bf16 [128][136]  (272B pitch, ldmatrix-clean)
#define SAL_B   34816     // A lo bf16 [128][136]
#define SXT_B   69632     // X^T fp32 [32][132]
#define SAX_B   86528     // AX fp32 [128][36]
#define WG_B    104960    // gcn_w fp32 [4][1024]
#define WS_B    121344
#define WR_B    137728
#define W1_B    154112    // [1024]
#define W2_B    158208    // [512]
#define BG_B    160256    // [128]
#define BS_B    160768
#define BR_B    161280
#define B1_B    161792    // [32]
#define B2_B    161920    // [16]
#define K3_SMEM 161984

__device__ __forceinline__ uint32_t smem_u32(const void* p) {
    uint32_t a;
    asm("{ .reg .u64 t; cvta.to.shared.u64 t, %1; cvt.u32.u64 %0, t; }"
        : "=r"(a) : "l"(p));
    return a;
}
__device__ __forceinline__ void ldmat4(uint32_t r[4], uint32_t addr) {
    asm volatile("ldmatrix.sync.aligned.m8n8.x4.shared.b16 {%0,%1,%2,%3}, [%4];"
                 : "=r"(r[0]), "=r"(r[1]), "=r"(r[2]), "=r"(r[3]) : "r"(addr));
}
__device__ __forceinline__ void mma16816(float d[4], const uint32_t a[4],
                                         uint32_t b0, uint32_t b1) {
    asm volatile(
        "mma.sync.aligned.m16n8k16.row.col.f32.bf16.bf16.f32 "
        "{%0,%1,%2,%3}, {%4,%5,%6,%7}, {%8,%9}, {%0,%1,%2,%3};"
        : "+f"(d[0]), "+f"(d[1]), "+f"(d[2]), "+f"(d[3])
        : "r"(a[0]), "r"(a[1]), "r"(a[2]), "r"(a[3]), "r"(b0), "r"(b1));
}
__device__ __forceinline__ uint32_t pack_bf16(__nv_bfloat16 lo, __nv_bfloat16 hi) {
    return (uint32_t)__bfloat16_as_ushort(lo) |
           ((uint32_t)__bfloat16_as_ushort(hi) << 16);
}

__global__ void __launch_bounds__(128) k_layers_m(
    const float* __restrict__ A, const float* __restrict__ gcn_w,
    const float* __restrict__ gcn_b, const float* __restrict__ res_w,
    const float* __restrict__ res_b, const float* __restrict__ skip_w,
    const float* __restrict__ skip_b, const float* __restrict__ out1_w,
    const float* __restrict__ out1_b, const float* __restrict__ out2_w,
    const float* __restrict__ out2_b, float* __restrict__ out) {
    extern __shared__ char smem[];
    uint32_t sbase = smem_u32(smem);
    int tid = threadIdx.x;
    int lane = tid & 31;
    int wid = tid >> 5;
    int bt = blockIdx.x;
    size_t base = (size_t)bt * 4096;

    // ---- stage A as bf16 hi/lo into ldmatrix layout (once) ----
    {
        for (int i = tid; i < 4096; i += 128) {
            int row = i >> 5, c4 = (i & 31) * 4;
            float4 v = ((const float4*)A)[i];
            __nv_bfloat16 h0 = __float2bfloat16(v.x);
            __nv_bfloat16 h1 = __float2bfloat16(v.y);
            __nv_bfloat16 h2 = __float2bfloat16(v.z);
            __nv_bfloat16 h3 = __float2bfloat16(v.w);
            __nv_bfloat16 l0 = __float2bfloat16(v.x - __bfloat162float(h0));
            __nv_bfloat16 l1 = __float2bfloat16(v.y - __bfloat162float(h1));
            __nv_bfloat16 l2 = __float2bfloat16(v.z - __bfloat162float(h2));
            __nv_bfloat16 l3 = __float2bfloat16(v.w - __bfloat162float(h3));
            uint32_t* ph = (uint32_t*)(smem + SAH_B + (row * 136 + c4) * 2);
            uint32_t* pl = (uint32_t*)(smem + SAL_B + (row * 136 + c4) * 2);
            ph[0] = pack_bf16(h0, h1); ph[1] = pack_bf16(h2, h3);
            pl[0] = pack_bf16(l0, l1); pl[1] = pack_bf16(l2, l3);
        }
        // weights
        float* wg = (float*)(smem + WG_B);
        float* ws = (float*)(smem + WS_B);
        float* wr = (float*)(smem + WR_B);
        for (int i = tid; i < 4096; i += 128) {
            wg[i] = gcn_w[i]; ws[i] = skip_w[i]; wr[i] = res_w[i];
        }
        float* w1 = (float*)(smem + W1_B);
        for (int i = tid; i < 1024; i += 128) w1[i] = out1_w[i];
        float* w2 = (float*)(smem + W2_B);
        for (int i = tid; i < 512; i += 128) w2[i] = out2_w[i];
        if (tid < 128) {
            ((float*)(smem + BG_B))[tid] = gcn_b[tid];
            ((float*)(smem + BS_B))[tid] = skip_b[tid];
            ((float*)(smem + BR_B))[tid] = res_b[tid];
        }
        if (tid < 32) ((float*)(smem + B1_B))[tid] = out1_b[tid];
        if (tid < 16) ((float*)(smem + B2_B))[tid] = out2_b[tid];
    }

    // ---- x_res row (thread = graph node i), persistent ----
    float xres[32];
    {
        const float4* xr = (const float4*)(g_xres + base + (size_t)tid * 32);
#pragma unroll
        for (int q = 0; q < 8; q++) {
            float4 v = xr[q];
            xres[4 * q] = v.x; xres[4 * q + 1] = v.y;
            xres[4 * q + 2] = v.z; xres[4 * q + 3] = v.w;
        }
    }
    float skip[32];
#pragma unroll
    for (int q = 0; q < 32; q++) skip[q] = 0.f;

    // ldmatrix base addresses for this lane (row part)
    int lrow = lane & 15, khalf = lane >> 4;
    uint32_t amh_base = sbase + SAH_B + (uint32_t)(((wid * 32 + lrow) * 136 + khalf * 8) * 2);
    uint32_t aml_base = sbase + SAL_B + (uint32_t)(((wid * 32 + lrow) * 136 + khalf * 8) * 2);
    float* sXT = (float*)(smem + SXT_B);
    float* sAX = (float*)(smem + SAX_B);
    int bn = lane >> 2;          // n within tile group
    int bk = (lane & 3) * 2;     // k pair base

    for (int l = 0; l < 4; l++) {
        // ---- write X^T (fp32) ----
#pragma unroll
        for (int o = 0; o < 32; o++) sXT[o * 132 + tid] = xres[o];
        __syncthreads();  // (1) X^T + (first iter) A/weights staged

        // ---- MMA phase: acc = A @ X  (split bf16, 3 passes) ----
        float acc[2][4][4];
#pragma unroll
        for (int mt = 0; mt < 2; mt++)
#pragma unroll
            for (int nt = 0; nt < 4; nt++)
#pragma unroll
                for (int q = 0; q < 4; q++) acc[mt][nt][q] = 0.f;

#pragma unroll
        for (int ks = 0; ks < 8; ks++) {
            uint32_t Bh[4][2], Bl[4][2];
#pragma unroll
            for (int nt = 0; nt < 4; nt++) {
                const float* p = sXT + (nt * 8 + bn) * 132 + ks * 16 + bk;
                float2 xa = *(const float2*)p;
                float2 xb = *(const float2*)(p + 8);
                __nv_bfloat16 h0 = __float2bfloat16(xa.x);
                __nv_bfloat16 h1 = __float2bfloat16(xa.y);
                __nv_bfloat16 h2 = __float2bfloat16(xb.x);
                __nv_bfloat16 h3 = __float2bfloat16(xb.y);
                Bh[nt][0] = pack_bf16(h0, h1);
                Bh[nt][1] = pack_bf16(h2, h3);
                Bl[nt][0] = pack_bf16(
                    __float2bfloat16(xa.x - __bfloat162float(h0)),
                    __float2bfloat16(xa.y - __bfloat162float(h1)));
                Bl[nt][1] = pack_bf16(
                    __float2bfloat16(xb.x - __bfloat162float(h2)),
                    __float2bfloat16(xb.y - __bfloat162float(h3)));
            }
            uint32_t ah[2][4], al[2][4];
#pragma unroll
            for (int mt = 0; mt < 2; mt++) {
                ldmat4(ah[mt], amh_base + (uint32_t)(mt * 16 * 136 * 2 + ks * 32));
                ldmat4(al[mt], aml_base + (uint32_t)(mt * 16 * 136 * 2 + ks * 32));
            }
#pragma unroll
            for (int mt = 0; mt < 2; mt++)
#pragma unroll
                for (int nt = 0; nt < 4; nt++) {
                    mma16816(acc[mt][nt], ah[mt], Bh[nt][0], Bh[nt][1]);
                    mma16816(acc[mt][nt], ah[mt], Bl[nt][0], Bl[nt][1]);
                    mma16816(acc[mt][nt], al[mt], Bh[nt][0], Bh[nt][1]);
                }
        }
        // ---- store AX frags to smem ----
#pragma unroll
        for (int mt = 0; mt < 2; mt++)
#pragma unroll
            for (int nt = 0; nt < 4; nt++) {
                int r0 = wid * 32 + mt * 16 + (lane >> 2);
                int c = nt * 8 + (lane & 3) * 2;
                *(float2*)&sAX[r0 * 36 + c] =
                    make_float2(acc[mt][nt][0], acc[mt][nt][1]);
                *(float2*)&sAX[(r0 + 8) * 36 + c] =
                    make_float2(acc[mt][nt][2], acc[mt][nt][3]);
            }
        __syncthreads();  // (2) AX visible; X^T reads complete

        // ---- SIMT epilogue, thread = row i ----
        float ax[32];
        {
            const float4* ap = (const float4*)&sAX[tid * 36];
#pragma unroll
            for (int q = 0; q < 8; q++) {
                float4 v = ap[q];
                ax[4 * q] = v.x; ax[4 * q + 1] = v.y;
                ax[4 * q + 2] = v.z; ax[4 * q + 3] = v.w;
            }
        }
        const float* wg = (const float*)(smem + WG_B) + l * 1024;
        const float* bg = (const float*)(smem + BG_B) + l * 32;
        float h[32];
#pragma unroll
        for (int q = 0; q < 32; q++) h[q] = bg[q];
#pragma unroll 4
        for (int o = 0; o < 32; o++) {
            float av = ax[o];
            const float4* wrow = (const float4*)(wg + o * 32);
#pragma unroll
            for (int q = 0; q < 8; q++) {
                float4 w = wrow[q];
                h[4 * q] = fmaf(av, w.x, h[4 * q]);
                h[4 * q + 1] = fmaf(av, w.y, h[4 * q + 1]);
                h[4 * q + 2] = fmaf(av, w.z, h[4 * q + 2]);
                h[4 * q + 3] = fmaf(av, w.w, h[4 * q + 3]);
            }
        }
        {
            const float4* tp =
                (const float4*)(g_tcn + (size_t)l * BTNH_ + base + (size_t)tid * 32);
#pragma unroll
            for (int q = 0; q < 8; q++) {
                float4 v = tp[q];
                h[4 * q] += v.x; h[4 * q + 1] += v.y;
                h[4 * q + 2] += v.z; h[4 * q + 3] += v.w;
            }
        }
        const float* ws = (const float*)(smem + WS_B) + l * 1024;
        const float* bs = (const float*)(smem + BS_B) + l * 32;
#pragma unroll
        for (int q = 0; q < 32; q++) skip[q] += bs[q];
#pragma unroll 4
        for (int o = 0; o < 32; o++) {
            float hv = h[o];
            const float4* wrow = (const float4*)(ws + o * 32);
#pragma unroll
            for (int q = 0; q < 8; q++) {
                float4 w = wrow[q];
                skip[4 * q] = fmaf(hv, w.x, skip[4 * q]);
                skip[4 * q + 1] = fmaf(hv, w.y, skip[4 * q + 1]);
                skip[4 * q + 2] = fmaf(hv, w.z, skip[4 * q + 2]);
                skip[4 * q + 3] = fmaf(hv, w.w, skip[4 * q + 3]);
            }
        }
        const float* wr = (const float*)(smem + WR_B) + l * 1024;
        const float* br = (const float*)(smem + BR_B) + l * 32;
#pragma unroll
        for (int q = 0; q < 32; q++) xres[q] += br[q];
#pragma unroll 4
        for (int o = 0; o < 32; o++) {
            float hv = h[o];
            const float4* wrow = (const float4*)(wr + o * 32);
#pragma unroll
            for (int q = 0; q < 8; q++) {
                float4 w = wrow[q];
                xres[4 * q] = fmaf(hv, w.x, xres[4 * q]);
                xres[4 * q + 1] = fmaf(hv, w.y, xres[4 * q + 1]);
                xres[4 * q + 2] = fmaf(hv, w.z, xres[4 * q + 2]);
                xres[4 * q + 3] = fmaf(hv, w.w, xres[4 * q + 3]);
            }
        }
    }

    // ---- head ----
#pragma unroll
    for (int q = 0; q < 32; q++) skip[q] = fmaxf(skip[q], 0.f);
    const float* w1 = (const float*)(smem + W1_B);
    const float* b1 = (const float*)(smem + B1_B);
    float h2[32];
#pragma unroll
    for (int q = 0; q < 32; q++) h2[q] = b1[q];
#pragma unroll 4
    for (int o = 0; o < 32; o++) {
        float sv = skip[o];
        const float4* wrow = (const float4*)(w1 + o * 32);
#pragma unroll
        for (int q = 0; q < 8; q++) {
            float4 w = wrow[q];
            h2[4 * q] = fmaf(sv, w.x, h2[4 * q]);
            h2[4 * q + 1] = fmaf(sv, w.y, h2[4 * q + 1]);
            h2[4 * q + 2] = fmaf(sv, w.z, h2[4 * q + 2]);
            h2[4 * q + 3] = fmaf(sv, w.w, h2[4 * q + 3]);
        }
    }
#pragma unroll
    for (int q = 0; q < 32; q++) h2[q] = fmaxf(h2[q], 0.f);

    const float* w2 = (const float*)(smem + W2_B);
    const float* b2 = (const float*)(smem + B2_B);
    float oacc[16];
#pragma unroll
    for (int q = 0; q < 16; q++) oacc[q] = b2[q];
#pragma unroll 4
    for (int o = 0; o < 32; o++) {
        float hv = h2[o];
        const float4* wrow = (const float4*)(w2 + o * 16);
#pragma unroll
        for (int q = 0; q < 4; q++) {
            float4 w = wrow[q];
            oacc[4 * q] = fmaf(hv, w.x, oacc[4 * q]);
            oacc[4 * q + 1] = fmaf(hv, w.y, oacc[4 * q + 1]);
            oacc[4 * q + 2] = fmaf(hv, w.z, oacc[4 * q + 2]);
            oacc[4 * q + 3] = fmaf(hv, w.w, oacc[4 * q + 3]);
        }
    }
    {
        float4* op = (float4*)(out + (size_t)bt * 2048 + (size_t)tid * 16);
#pragma unroll
        for (int q = 0; q < 4; q++)
            op[q] = make_float4(oacc[4 * q], oacc[4 * q + 1], oacc[4 * q + 2],
                                oacc[4 * q + 3]);
    }
}

// ---------------------------------------------------------------------------
extern "C" void kernel_launch(void* const* d_in, const int* in_sizes, int n_in,
                              void* d_out, int out_size) {
    const float* X = (const float*)d_in[0];
    const float* A = (const float*)d_in[1];
    const float* in_w = (const float*)d_in[2];
    const float* in_b = (const float*)d_in[3];
    const float* ct_w = (const float*)d_in[4];
    const float* ct_b = (const float*)d_in[5];
    const float* cs_w = (const float*)d_in[6];
    const float* cs_b = (const float*)d_in[7];
    const float* gcn_w = (const float*)d_in[8];
    const float* gcn_b = (const float*)d_in[9];
    const float* res_w = (const float*)d_in[10];
    const float* res_b = (const float*)d_in[11];
    const float* skip_w = (const float*)d_in[12];
    const float* skip_b = (const float*)d_in[13];
    const float* out1_w = (const float*)d_in[14];
    const float* out1_b = (const float*)d_in[15];
    const float* out2_w = (const float*)d_in[16];
    const float* out2_b = (const float*)d_in[17];
    float* out = (float*)d_out;

    cudaFuncSetAttribute(k_conv, cudaFuncAttributeMaxDynamicSharedMemorySize,
                         CVX_TOT * 4);
    cudaFuncSetAttribute(k_layers_m, cudaFuncAttributeMaxDynamicSharedMemorySize,
                         K3_SMEM);

    k_inproj<<<8192, 256>>>(X, in_w, in_b);
    k_conv<<<1024, 512, CVX_TOT * 4>>>(ct_w, ct_b, cs_w, cs_b);
    k_layers_m<<<4096, 128, K3_SMEM>>>(A, gcn_w, gcn_b, res_w, res_b, skip_w,
                                       skip_b, out1_w, out1_b, out2_w, out2_b,
                                       out);
}

// round 7
// speedup vs baseline: 1.0557x; 1.0557x over previous
#include <cuda_runtime.h>
#include <cuda_bf16.h>
#include <math.h>
#include <stdint.h>

// Problem constants: B=8, T=512, N=128, F=16, H=32, L=4
#define BTNH_ 16777216ull   // 8*512*128*32

// Scratch (allocation-free: static device globals)
__device__ float g_xa[16777216];
__device__ float g_xb[16777216];
__device__ float g_xres[16777216];
__device__ float g_tcn[4ull * 16777216ull];  // [l][b][t][n][o]

// ---------------------------------------------------------------------------
// K1: input projection (measured 100us, unchanged)
// ---------------------------------------------------------------------------
__global__ void __launch_bounds__(256) k_inproj(const float* __restrict__ X,
                                                const float* __restrict__ in_w,
                                                const float* __restrict__ in_b) {
    __shared__ float sw[1536];
    __shared__ float sb[96];
    for (int i = threadIdx.x; i < 1536; i += 256) sw[i] = in_w[i];
    if (threadIdx.x < 96) sb[threadIdx.x] = in_b[threadIdx.x];
    __syncthreads();

    int o = threadIdx.x & 31;
    int rsub = threadIdx.x >> 5;
#pragma unroll
    for (int gph = 0; gph < 8; gph++) {
        int row = blockIdx.x * 64 + gph * 8 + rsub;
        const float4* xr = (const float4*)(X + (size_t)row * 16);
        float4 v0 = xr[0], v1 = xr[1], v2 = xr[2], v3 = xr[3];
        float x[16] = {v0.x, v0.y, v0.z, v0.w, v1.x, v1.y, v1.z, v1.w,
                       v2.x, v2.y, v2.z, v2.w, v3.x, v3.y, v3.z, v3.w};
        float a0 = sb[o], a1 = sb[32 + o], a2 = sb[64 + o];
#pragma unroll
        for (int f = 0; f < 16; f++) {
            float xv = x[f];
            a0 = fmaf(xv, sw[f * 96 + o], a0);
            a1 = fmaf(xv, sw[f * 96 + 32 + o], a1);
            a2 = fmaf(xv, sw[f * 96 + 64 + o], a2);
        }
        size_t p = (size_t)row * 32 + o;
        g_xa[p] = a0;
        g_xb[p] = a1;
        g_xres[p] = a2;
    }
}

// ---------------------------------------------------------------------------
// K2: gated dilated causal convs, 4tau x 8o tiles (round-5 form, unchanged)
// ---------------------------------------------------------------------------
#define CVX_SXA 0
#define CVX_SXB 16896
#define CVX_WA  33792
#define CVX_WB  35840
#define CVX_BA  37888
#define CVX_BB  37920
#define CVX_TOT 37952

template <int D>
__device__ __forceinline__ void conv8x4(const float* __restrict__ S,
                                        const float* __restrict__ W,
                                        const float* __restrict__ Bv,
                                        int tau0, int o0, float acc[32]) {
    float b0[8];
#pragma unroll
    for (int u = 0; u < 8; u++) b0[u] = Bv[o0 + u];
#pragma unroll
    for (int t = 0; t < 4; t++)
#pragma unroll
        for (int u = 0; u < 8; u++) acc[t * 8 + u] = b0[u];

#pragma unroll 4
    for (int c = 0; c < 32; c++) {
        const float* row = S + c * 528 + 16 + tau0;
        float4 x1 = *(const float4*)row;
        float xs1[4] = {x1.x, x1.y, x1.z, x1.w};
        float xs0[4];
        if (D == 1) {
            float p = row[-1];
            xs0[0] = p; xs0[1] = x1.x; xs0[2] = x1.y; xs0[3] = x1.z;
        } else if (D == 2) {
            float2 p = *(const float2*)(row - 2);
            xs0[0] = p.x; xs0[1] = p.y; xs0[2] = x1.x; xs0[3] = x1.y;
        } else {
            float4 p = *(const float4*)(row - D);
            xs0[0] = p.x; xs0[1] = p.y; xs0[2] = p.z; xs0[3] = p.w;
        }
        float4 wa = *(const float4*)(W + c * 32 + o0);
        float4 wb = *(const float4*)(W + c * 32 + o0 + 4);
        float4 va = *(const float4*)(W + 1024 + c * 32 + o0);
        float4 vb = *(const float4*)(W + 1024 + c * 32 + o0 + 4);
        float w0v[8] = {wa.x, wa.y, wa.z, wa.w, wb.x, wb.y, wb.z, wb.w};
        float w1v[8] = {va.x, va.y, va.z, va.w, vb.x, vb.y, vb.z, vb.w};
#pragma unroll
        for (int t = 0; t < 4; t++)
#pragma unroll
            for (int u = 0; u < 8; u++)
                acc[t * 8 + u] =
                    fmaf(w1v[u], xs1[t], fmaf(w0v[u], xs0[t], acc[t * 8 + u]));
    }
}

template <int D>
__device__ __forceinline__ void conv_layer(const float* __restrict__ sm,
                                           float* __restrict__ outp,
                                           int tau0, int o0) {
    float ta[32];
    conv8x4<D>(sm + CVX_SXA, sm + CVX_WA, sm + CVX_BA, tau0, o0, ta);
#pragma unroll
    for (int k = 0; k < 32; k++) {
        float t = __expf(-2.f * fabsf(ta[k]));
        float r = (1.f - t) / (1.f + t);
        ta[k] = copysignf(r, ta[k]);
    }
    float sg[32];
    conv8x4<D>(sm + CVX_SXB, sm + CVX_WB, sm + CVX_BB, tau0, o0, sg);
#pragma unroll
    for (int k = 0; k < 32; k++) {
        float s = 1.f / (1.f + __expf(-sg[k]));
        sg[k] = ta[k] * s;
    }
#pragma unroll
    for (int t = 0; t < 4; t++) {
        float* p = outp + (size_t)t * 4096;
        ((float4*)p)[0] = make_float4(sg[t * 8 + 0], sg[t * 8 + 1],
                                      sg[t * 8 + 2], sg[t * 8 + 3]);
        ((float4*)p)[1] = make_float4(sg[t * 8 + 4], sg[t * 8 + 5],
                                      sg[t * 8 + 6], sg[t * 8 + 7]);
    }
}

__global__ void __launch_bounds__(512) k_conv(const float* __restrict__ ct_w,
                                              const float* __restrict__ ct_b,
                                              const float* __restrict__ cs_w,
                                              const float* __restrict__ cs_b) {
    extern __shared__ float sm[];
    int tid = threadIdx.x;
    int bn = blockIdx.x;
    int b = bn >> 7, n = bn & 127;
    int ty = tid & 127, tx = tid >> 7;
    int tau0 = ty * 4, o0 = tx * 8;

    if (tid < 512) {
        int c = tid >> 4, m = tid & 15;
        sm[CVX_SXA + c * 528 + m] = 0.f;
        sm[CVX_SXB + c * 528 + m] = 0.f;
    }
    const float* xa = g_xa + (size_t)bn * 16384;
    const float* xb = g_xb + (size_t)bn * 16384;
    for (int i = tid; i < 4096; i += 512) {
        float4 va = ((const float4*)xa)[i];
        float4 vb = ((const float4*)xb)[i];
        int tau = i >> 3, c0 = (i & 7) * 4;
        float* pa = sm + CVX_SXA + c0 * 528 + 16 + tau;
        float* pb = sm + CVX_SXB + c0 * 528 + 16 + tau;
        pa[0] = va.x; pa[528] = va.y; pa[1056] = va.z; pa[1584] = va.w;
        pb[0] = vb.x; pb[528] = vb.y; pb[1056] = vb.z; pb[1584] = vb.w;
    }

    float* outp0 = g_tcn + ((size_t)((b * 512 + tau0) * 128 + n)) * 32 + o0;

    for (int l = 0; l < 4; l++) {
        __syncthreads();
        for (int i = tid; i < 2048; i += 512) {
            sm[CVX_WA + i] = ct_w[l * 2048 + i];
            sm[CVX_WB + i] = cs_w[l * 2048 + i];
        }
        if (tid < 32) {
            sm[CVX_BA + tid] = ct_b[l * 32 + tid];
            sm[CVX_BB + tid] = cs_b[l * 32 + tid];
        }
        __syncthreads();
        float* outp = outp0 + (size_t)l * BTNH_;
        if (l == 0) conv_layer<1>(sm, outp, tau0, o0);
        else if (l == 1) conv_layer<2>(sm, outp, tau0, o0);
        else if (l == 2) conv_layer<4>(sm, outp, tau0, o0);
        else conv_layer<8>(sm, outp, tau0, o0);
    }
}

// ---------------------------------------------------------------------------
// K3 v2: HMMA A-mix with smem-staged bf16 X-split + ldmatrix B; SIMT epilogue
// with weights via broadcast __ldg (keeps smem at 107KB -> 2 CTAs/SM).
// 128 threads per (b,t) CTA; warp w owns m-rows [32w, 32w+32).
// ---------------------------------------------------------------------------
#define SAH_B   0         // A hi bf16 [128][136] (272B pitch)
#define SAL_B   34816     // A lo bf16 [128][136]
#define SXH_B   69632     // X^T hi bf16 [32 n][136 k]
#define SXL_B   78336     // X^T lo bf16
#define SAX_B   87040     // AX fp32 [128][36]
#define BG_B    105472    // gcn_b [4][32] f32
#define BS_B    105984
#define BR_B    106496
#define B1_B    107008    // [32]
#define B2_B    107136    // [16]
#define K3_SMEM 107200

__device__ __forceinline__ uint32_t smem_u32(const void* p) {
    uint32_t a;
    asm("{ .reg .u64 t; cvta.to.shared.u64 t, %1; cvt.u32.u64 %0, t; }"
        : "=r"(a) : "l"(p));
    return a;
}
__device__ __forceinline__ void ldmat4(uint32_t r[4], uint32_t addr) {
    asm volatile("ldmatrix.sync.aligned.m8n8.x4.shared.b16 {%0,%1,%2,%3}, [%4];"
                 : "=r"(r[0]), "=r"(r[1]), "=r"(r[2]), "=r"(r[3]) : "r"(addr));
}
__device__ __forceinline__ void mma16816(float d[4], const uint32_t a[4],
                                         uint32_t b0, uint32_t b1) {
    asm volatile(
        "mma.sync.aligned.m16n8k16.row.col.f32.bf16.bf16.f32 "
        "{%0,%1,%2,%3}, {%4,%5,%6,%7}, {%8,%9}, {%0,%1,%2,%3};"
        : "+f"(d[0]), "+f"(d[1]), "+f"(d[2]), "+f"(d[3])
        : "r"(a[0]), "r"(a[1]), "r"(a[2]), "r"(a[3]), "r"(b0), "r"(b1));
}
__device__ __forceinline__ uint32_t pack_bf16(__nv_bfloat16 lo, __nv_bfloat16 hi) {
    return (uint32_t)__bfloat16_as_ushort(lo) |
           ((uint32_t)__bfloat16_as_ushort(hi) << 16);
}

__global__ void __launch_bounds__(128, 2) k_layers_m(
    const float* __restrict__ A, const float* __restrict__ gcn_w,
    const float* __restrict__ gcn_b, const float* __restrict__ res_w,
    const float* __restrict__ res_b, const float* __restrict__ skip_w,
    const float* __restrict__ skip_b, const float* __restrict__ out1_w,
    const float* __restrict__ out1_b, const float* __restrict__ out2_w,
    const float* __restrict__ out2_b, float* __restrict__ out) {
    extern __shared__ char smem[];
    uint32_t sbase = smem_u32(smem);
    int tid = threadIdx.x;
    int lane = tid & 31;
    int wid = tid >> 5;
    int bt = blockIdx.x;
    size_t base = (size_t)bt * 4096;

    // ---- stage A as bf16 hi/lo into ldmatrix layout (once) ----
    for (int i = tid; i < 4096; i += 128) {
        int row = i >> 5, c4 = (i & 31) * 4;
        float4 v = ((const float4*)A)[i];
        __nv_bfloat16 h0 = __float2bfloat16(v.x);
        __nv_bfloat16 h1 = __float2bfloat16(v.y);
        __nv_bfloat16 h2 = __float2bfloat16(v.z);
        __nv_bfloat16 h3 = __float2bfloat16(v.w);
        __nv_bfloat16 l0 = __float2bfloat16(v.x - __bfloat162float(h0));
        __nv_bfloat16 l1 = __float2bfloat16(v.y - __bfloat162float(h1));
        __nv_bfloat16 l2 = __float2bfloat16(v.z - __bfloat162float(h2));
        __nv_bfloat16 l3 = __float2bfloat16(v.w - __bfloat162float(h3));
        uint32_t* ph = (uint32_t*)(smem + SAH_B + (row * 136 + c4) * 2);
        uint32_t* pl = (uint32_t*)(smem + SAL_B + (row * 136 + c4) * 2);
        ph[0] = pack_bf16(h0, h1); ph[1] = pack_bf16(h2, h3);
        pl[0] = pack_bf16(l0, l1); pl[1] = pack_bf16(l2, l3);
    }
    // biases
    if (tid < 128) {
        ((float*)(smem + BG_B))[tid] = gcn_b[tid];
        ((float*)(smem + BS_B))[tid] = skip_b[tid];
        ((float*)(smem + BR_B))[tid] = res_b[tid];
    }
    if (tid < 32) ((float*)(smem + B1_B))[tid] = out1_b[tid];
    if (tid < 16) ((float*)(smem + B2_B))[tid] = out2_b[tid];

    // ---- x_res row (thread = graph node i), persistent ----
    float xres[32];
    {
        const float4* xr = (const float4*)(g_xres + base + (size_t)tid * 32);
#pragma unroll
        for (int q = 0; q < 8; q++) {
            float4 v = xr[q];
            xres[4 * q] = v.x; xres[4 * q + 1] = v.y;
            xres[4 * q + 2] = v.z; xres[4 * q + 3] = v.w;
        }
    }
    float skip[32];
#pragma unroll
    for (int q = 0; q < 32; q++) skip[q] = 0.f;

    // ---- ldmatrix lane addressing ----
    // A (row-major m16k16): lanes 0-15 -> rows 0..15 @ k-lo, 16-31 -> rows @ k-hi
    int lrow = lane & 15, khalf = lane >> 4;
    uint32_t amh_base =
        sbase + SAH_B + (uint32_t)(((wid * 32 + lrow) * 136 + khalf * 8) * 2);
    uint32_t aml_base =
        sbase + SAL_B + (uint32_t)(((wid * 32 + lrow) * 136 + khalf * 8) * 2);
    // B ([n][k] tile): lanes 0-7:nt_lo@k-lo, 8-15:nt_lo@k-hi, 16-23:nt_hi@k-lo,
    // 24-31:nt_hi@k-hi
    int bn_row = ((lane >> 4) << 3) + (lane & 7);
    int bk_half = (lane >> 3) & 1;
    uint32_t bh_base =
        sbase + SXH_B + (uint32_t)((bn_row * 136 + bk_half * 8) * 2);
    uint32_t bl_base =
        sbase + SXL_B + (uint32_t)((bn_row * 136 + bk_half * 8) * 2);
    float* sAX = (float*)(smem + SAX_B);

    for (int l = 0; l < 4; l++) {
        // ---- write X-split (thread = node j = tid, column j of [n][k]) ----
#pragma unroll
        for (int o = 0; o < 32; o++) {
            float v = xres[o];
            __nv_bfloat16 hi = __float2bfloat16(v);
            __nv_bfloat16 lo = __float2bfloat16(v - __bfloat162float(hi));
            *(__nv_bfloat16*)(smem + SXH_B + (o * 136 + tid) * 2) = hi;
            *(__nv_bfloat16*)(smem + SXL_B + (o * 136 + tid) * 2) = lo;
        }
        __syncthreads();  // (1) X-split (+ first-iter A/bias staging) visible

        // ---- MMA: acc = A @ X  (split bf16, 3 passes), warp: 2 mtiles x 4 nt
        float acc[2][4][4];
#pragma unroll
        for (int mt = 0; mt < 2; mt++)
#pragma unroll
            for (int nt = 0; nt < 4; nt++)
#pragma unroll
                for (int q = 0; q < 4; q++) acc[mt][nt][q] = 0.f;

#pragma unroll
        for (int ks = 0; ks < 8; ks++) {
            uint32_t kb = (uint32_t)(ks * 32);  // k-chunk byte offset
            uint32_t ah[2][4], al[2][4], bh[2][4], bl[2][4];
            ldmat4(ah[0], amh_base + kb);
            ldmat4(ah[1], amh_base + 16 * 272 + kb);
            ldmat4(al[0], aml_base + kb);
            ldmat4(al[1], aml_base + 16 * 272 + kb);
            ldmat4(bh[0], bh_base + kb);
            ldmat4(bh[1], bh_base + 16 * 272 + kb);
            ldmat4(bl[0], bl_base + kb);
            ldmat4(bl[1], bl_base + 16 * 272 + kb);
#pragma unroll
            for (int mt = 0; mt < 2; mt++)
#pragma unroll
                for (int nt = 0; nt < 4; nt++) {
                    uint32_t b0h = bh[nt >> 1][(nt & 1) * 2];
                    uint32_t b1h = bh[nt >> 1][(nt & 1) * 2 + 1];
                    uint32_t b0l = bl[nt >> 1][(nt & 1) * 2];
                    uint32_t b1l = bl[nt >> 1][(nt & 1) * 2 + 1];
                    mma16816(acc[mt][nt], ah[mt], b0h, b1h);
                    mma16816(acc[mt][nt], ah[mt], b0l, b1l);
                    mma16816(acc[mt][nt], al[mt], b0h, b1h);
                }
        }
        // ---- store AX frags ----
#pragma unroll
        for (int mt = 0; mt < 2; mt++)
#pragma unroll
            for (int nt = 0; nt < 4; nt++) {
                int r0 = wid * 32 + mt * 16 + (lane >> 2);
                int c = nt * 8 + (lane & 3) * 2;
                *(float2*)&sAX[r0 * 36 + c] =
                    make_float2(acc[mt][nt][0], acc[mt][nt][1]);
                *(float2*)&sAX[(r0 + 8) * 36 + c] =
                    make_float2(acc[mt][nt][2], acc[mt][nt][3]);
            }
        __syncthreads();  // (2) AX visible; X-split reads complete

        // ---- SIMT epilogue, thread = row i; weights via broadcast __ldg ----
        float ax[32];
        {
            const float4* ap = (const float4*)&sAX[tid * 36];
#pragma unroll
            for (int q = 0; q < 8; q++) {
                float4 v = ap[q];
                ax[4 * q] = v.x; ax[4 * q + 1] = v.y;
                ax[4 * q + 2] = v.z; ax[4 * q + 3] = v.w;
            }
        }
        const float* bg = (const float*)(smem + BG_B) + l * 32;
        float h[32];
#pragma unroll
        for (int q = 0; q < 32; q++) h[q] = bg[q];
#pragma unroll 4
        for (int o = 0; o < 32; o++) {
            float av = ax[o];
            const float4* wrow = (const float4*)(gcn_w + l * 1024 + o * 32);
#pragma unroll
            for (int q = 0; q < 8; q++) {
                float4 w = __ldg(wrow + q);
                h[4 * q] = fmaf(av, w.x, h[4 * q]);
                h[4 * q + 1] = fmaf(av, w.y, h[4 * q + 1]);
                h[4 * q + 2] = fmaf(av, w.z, h[4 * q + 2]);
                h[4 * q + 3] = fmaf(av, w.w, h[4 * q + 3]);
            }
        }
        {
            const float4* tp =
                (const float4*)(g_tcn + (size_t)l * BTNH_ + base + (size_t)tid * 32);
#pragma unroll
            for (int q = 0; q < 8; q++) {
                float4 v = tp[q];
                h[4 * q] += v.x; h[4 * q + 1] += v.y;
                h[4 * q + 2] += v.z; h[4 * q + 3] += v.w;
            }
        }
        const float* bs = (const float*)(smem + BS_B) + l * 32;
#pragma unroll
        for (int q = 0; q < 32; q++) skip[q] += bs[q];
#pragma unroll 4
        for (int o = 0; o < 32; o++) {
            float hv = h[o];
            const float4* wrow = (const float4*)(skip_w + l * 1024 + o * 32);
#pragma unroll
            for (int q = 0; q < 8; q++) {
                float4 w = __ldg(wrow + q);
                skip[4 * q] = fmaf(hv, w.x, skip[4 * q]);
                skip[4 * q + 1] = fmaf(hv, w.y, skip[4 * q + 1]);
                skip[4 * q + 2] = fmaf(hv, w.z, skip[4 * q + 2]);
                skip[4 * q + 3] = fmaf(hv, w.w, skip[4 * q + 3]);
            }
        }
        const float* br = (const float*)(smem + BR_B) + l * 32;
#pragma unroll
        for (int q = 0; q < 32; q++) xres[q] += br[q];
#pragma unroll 4
        for (int o = 0; o < 32; o++) {
            float hv = h[o];
            const float4* wrow = (const float4*)(res_w + l * 1024 + o * 32);
#pragma unroll
            for (int q = 0; q < 8; q++) {
                float4 w = __ldg(wrow + q);
                xres[4 * q] = fmaf(hv, w.x, xres[4 * q]);
                xres[4 * q + 1] = fmaf(hv, w.y, xres[4 * q + 1]);
                xres[4 * q + 2] = fmaf(hv, w.z, xres[4 * q + 2]);
                xres[4 * q + 3] = fmaf(hv, w.w, xres[4 * q + 3]);
            }
        }
    }

    // ---- head ----
#pragma unroll
    for (int q = 0; q < 32; q++) skip[q] = fmaxf(skip[q], 0.f);
    const float* b1 = (const float*)(smem + B1_B);
    float h2[32];
#pragma unroll
    for (int q = 0; q < 32; q++) h2[q] = b1[q];
#pragma unroll 4
    for (int o = 0; o < 32; o++) {
        float sv = skip[o];
        const float4* wrow = (const float4*)(out1_w + o * 32);
#pragma unroll
        for (int q = 0; q < 8; q++) {
            float4 w = __ldg(wrow + q);
            h2[4 * q] = fmaf(sv, w.x, h2[4 * q]);
            h2[4 * q + 1] = fmaf(sv, w.y, h2[4 * q + 1]);
            h2[4 * q + 2] = fmaf(sv, w.z, h2[4 * q + 2]);
            h2[4 * q + 3] = fmaf(sv, w.w, h2[4 * q + 3]);
        }
    }
#pragma unroll
    for (int q = 0; q < 32; q++) h2[q] = fmaxf(h2[q], 0.f);

    const float* b2 = (const float*)(smem + B2_B);
    float oacc[16];
#pragma unroll
    for (int q = 0; q < 16; q++) oacc[q] = b2[q];
#pragma unroll 4
    for (int o = 0; o < 32; o++) {
        float hv = h2[o];
        const float4* wrow = (const float4*)(out2_w + o * 16);
#pragma unroll
        for (int q = 0; q < 4; q++) {
            float4 w = __ldg(wrow + q);
            oacc[4 * q] = fmaf(hv, w.x, oacc[4 * q]);
            oacc[4 * q + 1] = fmaf(hv, w.y, oacc[4 * q + 1]);
            oacc[4 * q + 2] = fmaf(hv, w.z, oacc[4 * q + 2]);
            oacc[4 * q + 3] = fmaf(hv, w.w, oacc[4 * q + 3]);
        }
    }
    {
        float4* op = (float4*)(out + (size_t)bt * 2048 + (size_t)tid * 16);
#pragma unroll
        for (int q = 0; q < 4; q++)
            op[q] = make_float4(oacc[4 * q], oacc[4 * q + 1], oacc[4 * q + 2],
                                oacc[4 * q + 3]);
    }
}

// ---------------------------------------------------------------------------
extern "C" void kernel_launch(void* const* d_in, const int* in_sizes, int n_in,
                              void* d_out, int out_size) {
    const float* X = (const float*)d_in[0];
    const float* A = (const float*)d_in[1];
    const float* in_w = (const float*)d_in[2];
    const float* in_b = (const float*)d_in[3];
    const float* ct_w = (const float*)d_in[4];
    const float* ct_b = (const float*)d_in[5];
    const float* cs_w = (const float*)d_in[6];
    const float* cs_b = (const float*)d_in[7];
    const float* gcn_w = (const float*)d_in[8];
    const float* gcn_b = (const float*)d_in[9];
    const float* res_w = (const float*)d_in[10];
    const float* res_b = (const float*)d_in[11];
    const float* skip_w = (const float*)d_in[12];
    const float* skip_b = (const float*)d_in[13];
    const float* out1_w = (const float*)d_in[14];
    const float* out1_b = (const float*)d_in[15];
    const float* out2_w = (const float*)d_in[16];
    const float* out2_b = (const float*)d_in[17];
    float* out = (float*)d_out;

    cudaFuncSetAttribute(k_conv, cudaFuncAttributeMaxDynamicSharedMemorySize,
                         CVX_TOT * 4);
    cudaFuncSetAttribute(k_layers_m, cudaFuncAttributeMaxDynamicSharedMemorySize,
                         K3_SMEM);

    k_inproj<<<8192, 256>>>(X, in_w, in_b);
    k_conv<<<1024, 512, CVX_TOT * 4>>>(ct_w, ct_b, cs_w, cs_b);
    k_layers_m<<<4096, 128, K3_SMEM>>>(A, gcn_w, gcn_b, res_w, res_b, skip_w,
                                       skip_b, out1_w, out1_b, out2_w, out2_b,
                                       out);
}

// round 9
// speedup vs baseline: 1.3515x; 1.2802x over previous
#include <cuda_runtime.h>
#include <cuda_bf16.h>
#include <math.h>
#include <stdint.h>

// Problem constants: B=8, T=512, N=128, F=16, H=32, L=4
#define BTNH_ 16777216ull   // 8*512*128*32

// Scratch (allocation-free: static device globals)
__device__ float g_xa[16777216];
__device__ float g_xb[16777216];
__device__ float g_xres[16777216];
__device__ float g_tcn[4ull * 16777216ull];  // [l][b][t][n][o]

// ---------------------------------------------------------------------------
// K1: input projection (measured 100us, unchanged)
// ---------------------------------------------------------------------------
__global__ void __launch_bounds__(256) k_inproj(const float* __restrict__ X,
                                                const float* __restrict__ in_w,
                                                const float* __restrict__ in_b) {
    __shared__ float sw[1536];
    __shared__ float sb[96];
    for (int i = threadIdx.x; i < 1536; i += 256) sw[i] = in_w[i];
    if (threadIdx.x < 96) sb[threadIdx.x] = in_b[threadIdx.x];
    __syncthreads();

    int o = threadIdx.x & 31;
    int rsub = threadIdx.x >> 5;
#pragma unroll
    for (int gph = 0; gph < 8; gph++) {
        int row = blockIdx.x * 64 + gph * 8 + rsub;
        const float4* xr = (const float4*)(X + (size_t)row * 16);
        float4 v0 = xr[0], v1 = xr[1], v2 = xr[2], v3 = xr[3];
        float x[16] = {v0.x, v0.y, v0.z, v0.w, v1.x, v1.y, v1.z, v1.w,
                       v2.x, v2.y, v2.z, v2.w, v3.x, v3.y, v3.z, v3.w};
        float a0 = sb[o], a1 = sb[32 + o], a2 = sb[64 + o];
#pragma unroll
        for (int f = 0; f < 16; f++) {
            float xv = x[f];
            a0 = fmaf(xv, sw[f * 96 + o], a0);
            a1 = fmaf(xv, sw[f * 96 + 32 + o], a1);
            a2 = fmaf(xv, sw[f * 96 + 64 + o], a2);
        }
        size_t p = (size_t)row * 32 + o;
        g_xa[p] = a0;
        g_xb[p] = a1;
        g_xres[p] = a2;
    }
}

// ---------------------------------------------------------------------------
// K2: gated dilated causal convs, 4tau x 8o tiles (round-5 form, unchanged)
// ---------------------------------------------------------------------------
#define CVX_SXA 0
#define CVX_SXB 16896
#define CVX_WA  33792
#define CVX_WB  35840
#define CVX_BA  37888
#define CVX_BB  37920
#define CVX_TOT 37952

template <int D>
__device__ __forceinline__ void conv8x4(const float* __restrict__ S,
                                        const float* __restrict__ W,
                                        const float* __restrict__ Bv,
                                        int tau0, int o0, float acc[32]) {
    float b0[8];
#pragma unroll
    for (int u = 0; u < 8; u++) b0[u] = Bv[o0 + u];
#pragma unroll
    for (int t = 0; t < 4; t++)
#pragma unroll
        for (int u = 0; u < 8; u++) acc[t * 8 + u] = b0[u];

#pragma unroll 4
    for (int c = 0; c < 32; c++) {
        const float* row = S + c * 528 + 16 + tau0;
        float4 x1 = *(const float4*)row;
        float xs1[4] = {x1.x, x1.y, x1.z, x1.w};
        float xs0[4];
        if (D == 1) {
            float p = row[-1];
            xs0[0] = p; xs0[1] = x1.x; xs0[2] = x1.y; xs0[3] = x1.z;
        } else if (D == 2) {
            float2 p = *(const float2*)(row - 2);
            xs0[0] = p.x; xs0[1] = p.y; xs0[2] = x1.x; xs0[3] = x1.y;
        } else {
            float4 p = *(const float4*)(row - D);
            xs0[0] = p.x; xs0[1] = p.y; xs0[2] = p.z; xs0[3] = p.w;
        }
        float4 wa = *(const float4*)(W + c * 32 + o0);
        float4 wb = *(const float4*)(W + c * 32 + o0 + 4);
        float4 va = *(const float4*)(W + 1024 + c * 32 + o0);
        float4 vb = *(const float4*)(W + 1024 + c * 32 + o0 + 4);
        float w0v[8] = {wa.x, wa.y, wa.z, wa.w, wb.x, wb.y, wb.z, wb.w};
        float w1v[8] = {va.x, va.y, va.z, va.w, vb.x, vb.y, vb.z, vb.w};
#pragma unroll
        for (int t = 0; t < 4; t++)
#pragma unroll
            for (int u = 0; u < 8; u++)
                acc[t * 8 + u] =
                    fmaf(w1v[u], xs1[t], fmaf(w0v[u], xs0[t], acc[t * 8 + u]));
    }
}

template <int D>
__device__ __forceinline__ void conv_layer(const float* __restrict__ sm,
                                           float* __restrict__ outp,
                                           int tau0, int o0) {
    float ta[32];
    conv8x4<D>(sm + CVX_SXA, sm + CVX_WA, sm + CVX_BA, tau0, o0, ta);
#pragma unroll
    for (int k = 0; k < 32; k++) {
        float t = __expf(-2.f * fabsf(ta[k]));
        float r = (1.f - t) / (1.f + t);
        ta[k] = copysignf(r, ta[k]);
    }
    float sg[32];
    conv8x4<D>(sm + CVX_SXB, sm + CVX_WB, sm + CVX_BB, tau0, o0, sg);
#pragma unroll
    for (int k = 0; k < 32; k++) {
        float s = 1.f / (1.f + __expf(-sg[k]));
        sg[k] = ta[k] * s;
    }
#pragma unroll
    for (int t = 0; t < 4; t++) {
        float* p = outp + (size_t)t * 4096;
        ((float4*)p)[0] = make_float4(sg[t * 8 + 0], sg[t * 8 + 1],
                                      sg[t * 8 + 2], sg[t * 8 + 3]);
        ((float4*)p)[1] = make_float4(sg[t * 8 + 4], sg[t * 8 + 5],
                                      sg[t * 8 + 6], sg[t * 8 + 7]);
    }
}

__global__ void __launch_bounds__(512) k_conv(const float* __restrict__ ct_w,
                                              const float* __restrict__ ct_b,
                                              const float* __restrict__ cs_w,
                                              const float* __restrict__ cs_b) {
    extern __shared__ float sm[];
    int tid = threadIdx.x;
    int bn = blockIdx.x;
    int b = bn >> 7, n = bn & 127;
    int ty = tid & 127, tx = tid >> 7;
    int tau0 = ty * 4, o0 = tx * 8;

    if (tid < 512) {
        int c = tid >> 4, m = tid & 15;
        sm[CVX_SXA + c * 528 + m] = 0.f;
        sm[CVX_SXB + c * 528 + m] = 0.f;
    }
    const float* xa = g_xa + (size_t)bn * 16384;
    const float* xb = g_xb + (size_t)bn * 16384;
    for (int i = tid; i < 4096; i += 512) {
        float4 va = ((const float4*)xa)[i];
        float4 vb = ((const float4*)xb)[i];
        int tau = i >> 3, c0 = (i & 7) * 4;
        float* pa = sm + CVX_SXA + c0 * 528 + 16 + tau;
        float* pb = sm + CVX_SXB + c0 * 528 + 16 + tau;
        pa[0] = va.x; pa[528] = va.y; pa[1056] = va.z; pa[1584] = va.w;
        pb[0] = vb.x; pb[528] = vb.y; pb[1056] = vb.z; pb[1584] = vb.w;
    }

    float* outp0 = g_tcn + ((size_t)((b * 512 + tau0) * 128 + n)) * 32 + o0;

    for (int l = 0; l < 4; l++) {
        __syncthreads();
        for (int i = tid; i < 2048; i += 512) {
            sm[CVX_WA + i] = ct_w[l * 2048 + i];
            sm[CVX_WB + i] = cs_w[l * 2048 + i];
        }
        if (tid < 32) {
            sm[CVX_BA + tid] = ct_b[l * 32 + tid];
            sm[CVX_BB + tid] = cs_b[l * 32 + tid];
        }
        __syncthreads();
        float* outp = outp0 + (size_t)l * BTNH_;
        if (l == 0) conv_layer<1>(sm, outp, tau0, o0);
        else if (l == 1) conv_layer<2>(sm, outp, tau0, o0);
        else if (l == 2) conv_layer<4>(sm, outp, tau0, o0);
        else conv_layer<8>(sm, outp, tau0, o0);
    }
}

// ---------------------------------------------------------------------------
// K3 v3b: HMMA A-mix + warp-tiled SIMT epilogue (round-8 + missing barrier).
// 256 threads (8 warps) per (b,t) CTA; MMA: warp g computes m-tile rows
// [16g,16g+16).  Epilogue: warp g, lane o, rows [16g,16g+16).
// smem (bytes):
#define SAH_B   0         // A hi bf16 [128][136] (272B pitch, ldmatrix)
#define SAL_B   34816     // A lo bf16
#define SX_B    69632     // x_res fp32 [128][33] = 16896
#define SXH_B   86528     // X^T hi bf16 [32][136] = 8704
#define SXL_B   95232     // X^T lo bf16            = 8704
#define SAX_B   86528     // overlay: AX fp32 [128][36] = 18432 (ends 104960)
#define K3_SMEM 104960

__device__ __forceinline__ uint32_t smem_u32(const void* p) {
    uint32_t a;
    asm("{ .reg .u64 t; cvta.to.shared.u64 t, %1; cvt.u32.u64 %0, t; }"
        : "=r"(a) : "l"(p));
    return a;
}
__device__ __forceinline__ void ldmat4(uint32_t r[4], uint32_t addr) {
    asm volatile("ldmatrix.sync.aligned.m8n8.x4.shared.b16 {%0,%1,%2,%3}, [%4];"
                 : "=r"(r[0]), "=r"(r[1]), "=r"(r[2]), "=r"(r[3]) : "r"(addr));
}
__device__ __forceinline__ void mma16816(float d[4], const uint32_t a[4],
                                         uint32_t b0, uint32_t b1) {
    asm volatile(
        "mma.sync.aligned.m16n8k16.row.col.f32.bf16.bf16.f32 "
        "{%0,%1,%2,%3}, {%4,%5,%6,%7}, {%8,%9}, {%0,%1,%2,%3};"
        : "+f"(d[0]), "+f"(d[1]), "+f"(d[2]), "+f"(d[3])
        : "r"(a[0]), "r"(a[1]), "r"(a[2]), "r"(a[3]), "r"(b0), "r"(b1));
}
__device__ __forceinline__ uint32_t pack_bf16(__nv_bfloat16 lo, __nv_bfloat16 hi) {
    return (uint32_t)__bfloat16_as_ushort(lo) |
           ((uint32_t)__bfloat16_as_ushort(hi) << 16);
}

__global__ void __launch_bounds__(256, 2) k_layers_h(
    const float* __restrict__ A, const float* __restrict__ gcn_w,
    const float* __restrict__ gcn_b, const float* __restrict__ res_w,
    const float* __restrict__ res_b, const float* __restrict__ skip_w,
    const float* __restrict__ skip_b, const float* __restrict__ out1_w,
    const float* __restrict__ out1_b, const float* __restrict__ out2_w,
    const float* __restrict__ out2_b, float* __restrict__ out) {
    extern __shared__ char smem[];
    uint32_t sbase = smem_u32(smem);
    int tid = threadIdx.x;
    int lane = tid & 31;
    int g = tid >> 5;          // warp id 0..7
    int o = lane;              // epilogue: lane = output channel
    int row0 = g * 16;
    int bt = blockIdx.x;
    size_t base = (size_t)bt * 4096;

    float* sX = (float*)(smem + SX_B);    // pitch 33
    float* sAX = (float*)(smem + SAX_B);  // pitch 36 (overlay on SXH/SXL)

    // ---- stage A as bf16 hi/lo into ldmatrix layout (once) ----
    for (int i = tid; i < 4096; i += 256) {
        int row = i >> 5, c4 = (i & 31) * 4;
        float4 v = ((const float4*)A)[i];
        __nv_bfloat16 h0 = __float2bfloat16(v.x);
        __nv_bfloat16 h1 = __float2bfloat16(v.y);
        __nv_bfloat16 h2 = __float2bfloat16(v.z);
        __nv_bfloat16 h3 = __float2bfloat16(v.w);
        __nv_bfloat16 l0 = __float2bfloat16(v.x - __bfloat162float(h0));
        __nv_bfloat16 l1 = __float2bfloat16(v.y - __bfloat162float(h1));
        __nv_bfloat16 l2 = __float2bfloat16(v.z - __bfloat162float(h2));
        __nv_bfloat16 l3 = __float2bfloat16(v.w - __bfloat162float(h3));
        uint32_t* ph = (uint32_t*)(smem + SAH_B + (row * 136 + c4) * 2);
        uint32_t* pl = (uint32_t*)(smem + SAL_B + (row * 136 + c4) * 2);
        ph[0] = pack_bf16(h0, h1); ph[1] = pack_bf16(h2, h3);
        pl[0] = pack_bf16(l0, l1); pl[1] = pack_bf16(l2, l3);
    }
    // ---- stage x_res into sX (pitch 33) ----
    for (int i = tid; i < 4096; i += 256) {
        int j = i >> 5, oo = i & 31;
        sX[j * 33 + oo] = g_xres[base + i];
    }
    __syncthreads();  // (0) staging visible BEFORE first X-split read of sX
                      // (round-8 bug: this barrier was missing -> race)

    // ---- ldmatrix lane addressing ----
    int lrow = lane & 15, khalf = lane >> 4;
    uint32_t amh_base =
        sbase + SAH_B + (uint32_t)(((row0 + lrow) * 136 + khalf * 8) * 2);
    uint32_t aml_base =
        sbase + SAL_B + (uint32_t)(((row0 + lrow) * 136 + khalf * 8) * 2);
    int bn_row = ((lane >> 4) << 3) + (lane & 7);
    int bk_half = (lane >> 3) & 1;
    uint32_t bh_base =
        sbase + SXH_B + (uint32_t)((bn_row * 136 + bk_half * 8) * 2);
    uint32_t bl_base =
        sbase + SXL_B + (uint32_t)((bn_row * 136 + bk_half * 8) * 2);

    // X-split phase params: thread t -> node j = t&127, o-range half
    int xj = tid & 127;
    int xo0 = (tid >> 7) * 16;

    float skip[16];
#pragma unroll
    for (int ii = 0; ii < 16; ii++) skip[ii] = 0.f;

    for (int l = 0; l < 4; l++) {
        // ---- X-split: sX -> SXH/SXL (bf16 hi/lo), [n][k]-major ----
#pragma unroll
        for (int oo = 0; oo < 16; oo++) {
            int oc = xo0 + oo;
            float v = sX[xj * 33 + oc];
            __nv_bfloat16 hi = __float2bfloat16(v);
            __nv_bfloat16 lo = __float2bfloat16(v - __bfloat162float(hi));
            *(__nv_bfloat16*)(smem + SXH_B + (oc * 136 + xj) * 2) = hi;
            *(__nv_bfloat16*)(smem + SXL_B + (oc * 136 + xj) * 2) = lo;
        }
        __syncthreads();  // (1) X-split visible

        // ---- MMA: warp g computes AX rows [16g,16g+16), all 32 cols ----
        float acc[4][4];
#pragma unroll
        for (int nt = 0; nt < 4; nt++)
#pragma unroll
            for (int q = 0; q < 4; q++) acc[nt][q] = 0.f;

#pragma unroll
        for (int ks = 0; ks < 8; ks++) {
            uint32_t kb = (uint32_t)(ks * 32);
            uint32_t ah[4], al[4], bh[2][4], bl[2][4];
            ldmat4(ah, amh_base + kb);
            ldmat4(al, aml_base + kb);
            ldmat4(bh[0], bh_base + kb);
            ldmat4(bh[1], bh_base + 16 * 272 + kb);
            ldmat4(bl[0], bl_base + kb);
            ldmat4(bl[1], bl_base + 16 * 272 + kb);
#pragma unroll
            for (int nt = 0; nt < 4; nt++) {
                uint32_t b0h = bh[nt >> 1][(nt & 1) * 2];
                uint32_t b1h = bh[nt >> 1][(nt & 1) * 2 + 1];
                uint32_t b0l = bl[nt >> 1][(nt & 1) * 2];
                uint32_t b1l = bl[nt >> 1][(nt & 1) * 2 + 1];
                mma16816(acc[nt], ah, b0h, b1h);
                mma16816(acc[nt], ah, b0l, b1l);
                mma16816(acc[nt], al, b0h, b1h);
            }
        }
        __syncthreads();  // (2) all warps' ldmatrix reads done before overlay

        // ---- store AX frags into sAX (pitch 36) ----
#pragma unroll
        for (int nt = 0; nt < 4; nt++) {
            int r0 = row0 + (lane >> 2);
            int c = nt * 8 + (lane & 3) * 2;
            *(float2*)&sAX[r0 * 36 + c] = make_float2(acc[nt][0], acc[nt][1]);
            *(float2*)&sAX[(r0 + 8) * 36 + c] = make_float2(acc[nt][2], acc[nt][3]);
        }
        __syncthreads();  // (3) sAX visible

        // ---- epilogue (round-2 form): warp g, lane o, rows [16g,16g+16) ----
        float w[32];
#pragma unroll
        for (int c = 0; c < 32; c++) w[c] = __ldg(&gcn_w[l * 1024 + c * 32 + o]);
        float bq = __ldg(&gcn_b[l * 32 + o]);
        const float* tcnp = g_tcn + (size_t)l * BTNH_ + base;
        float h[16];
#pragma unroll
        for (int ii = 0; ii < 16; ii++) {
            float s = bq;
            const float* rowp = &sAX[(row0 + ii) * 36];
#pragma unroll
            for (int c4 = 0; c4 < 8; c4++) {
                float4 v = *(const float4*)&rowp[c4 * 4];
                s = fmaf(v.x, w[4 * c4 + 0],
                    fmaf(v.y, w[4 * c4 + 1],
                    fmaf(v.z, w[4 * c4 + 2], fmaf(v.w, w[4 * c4 + 3], s))));
            }
            h[ii] = s + tcnp[(row0 + ii) * 32 + o];
        }
        __syncwarp();
#pragma unroll
        for (int ii = 0; ii < 16; ii++) sAX[(row0 + ii) * 36 + o] = h[ii];
        __syncwarp();

#pragma unroll
        for (int c = 0; c < 32; c++) w[c] = __ldg(&skip_w[l * 1024 + c * 32 + o]);
        float bs = __ldg(&skip_b[l * 32 + o]);
#pragma unroll
        for (int ii = 0; ii < 16; ii++) {
            float s = bs;
            const float* rowp = &sAX[(row0 + ii) * 36];
#pragma unroll
            for (int c4 = 0; c4 < 8; c4++) {
                float4 v = *(const float4*)&rowp[c4 * 4];
                s = fmaf(v.x, w[4 * c4 + 0],
                    fmaf(v.y, w[4 * c4 + 1],
                    fmaf(v.z, w[4 * c4 + 2], fmaf(v.w, w[4 * c4 + 3], s))));
            }
            skip[ii] += s;
        }

#pragma unroll
        for (int c = 0; c < 32; c++) w[c] = __ldg(&res_w[l * 1024 + c * 32 + o]);
        float br = __ldg(&res_b[l * 32 + o]);
        float xn[16];
#pragma unroll
        for (int ii = 0; ii < 16; ii++) {
            float s = br;
            const float* rowp = &sAX[(row0 + ii) * 36];
#pragma unroll
            for (int c4 = 0; c4 < 8; c4++) {
                float4 v = *(const float4*)&rowp[c4 * 4];
                s = fmaf(v.x, w[4 * c4 + 0],
                    fmaf(v.y, w[4 * c4 + 1],
                    fmaf(v.z, w[4 * c4 + 2], fmaf(v.w, w[4 * c4 + 3], s))));
            }
            xn[ii] = s + sX[(row0 + ii) * 33 + o];
        }
        __syncthreads();  // (4) everyone done reading sX / sAX
#pragma unroll
        for (int ii = 0; ii < 16; ii++) sX[(row0 + ii) * 33 + o] = xn[ii];
        __syncthreads();  // (5) sX update visible (next layer X-split reads it)
    }

    // ---- head: relu(skip) @ out1 -> relu -> @ out2 ----
#pragma unroll
    for (int ii = 0; ii < 16; ii++)
        sAX[(row0 + ii) * 36 + o] = fmaxf(skip[ii], 0.f);
    __syncwarp();

    float w1r[32];
#pragma unroll
    for (int c = 0; c < 32; c++) w1r[c] = __ldg(&out1_w[c * 32 + o]);
    float b1 = __ldg(&out1_b[o]);
    float h2[16];
#pragma unroll
    for (int ii = 0; ii < 16; ii++) {
        float s = b1;
        const float* rowp = &sAX[(row0 + ii) * 36];
#pragma unroll
        for (int c4 = 0; c4 < 8; c4++) {
            float4 v = *(const float4*)&rowp[c4 * 4];
            s = fmaf(v.x, w1r[4 * c4 + 0],
                fmaf(v.y, w1r[4 * c4 + 1],
                fmaf(v.z, w1r[4 * c4 + 2], fmaf(v.w, w1r[4 * c4 + 3], s))));
        }
        h2[ii] = fmaxf(s, 0.f);
    }
    __syncwarp();
#pragma unroll
    for (int ii = 0; ii < 16; ii++) sAX[(row0 + ii) * 36 + o] = h2[ii];
    __syncwarp();

    if (o < 16) {
        float w2r[32];
#pragma unroll
        for (int c = 0; c < 32; c++) w2r[c] = __ldg(&out2_w[c * 16 + o]);
        float b2 = __ldg(&out2_b[o]);
        float* op = out + (size_t)bt * 2048;
#pragma unroll
        for (int ii = 0; ii < 16; ii++) {
            float s = b2;
            const float* rowp = &sAX[(row0 + ii) * 36];
#pragma unroll
            for (int c4 = 0; c4 < 8; c4++) {
                float4 v = *(const float4*)&rowp[c4 * 4];
                s = fmaf(v.x, w2r[4 * c4 + 0],
                    fmaf(v.y, w2r[4 * c4 + 1],
                    fmaf(v.z, w2r[4 * c4 + 2], fmaf(v.w, w2r[4 * c4 + 3], s))));
            }
            op[(row0 + ii) * 16 + o] = s;
        }
    }
}

// ---------------------------------------------------------------------------
extern "C" void kernel_launch(void* const* d_in, const int* in_sizes, int n_in,
                              void* d_out, int out_size) {
    const float* X = (const float*)d_in[0];
    const float* A = (const float*)d_in[1];
    const float* in_w = (const float*)d_in[2];
    const float* in_b = (const float*)d_in[3];
    const float* ct_w = (const float*)d_in[4];
    const float* ct_b = (const float*)d_in[5];
    const float* cs_w = (const float*)d_in[6];
    const float* cs_b = (const float*)d_in[7];
    const float* gcn_w = (const float*)d_in[8];
    const float* gcn_b = (const float*)d_in[9];
    const float* res_w = (const float*)d_in[10];
    const float* res_b = (const float*)d_in[11];
    const float* skip_w = (const float*)d_in[12];
    const float* skip_b = (const float*)d_in[13];
    const float* out1_w = (const float*)d_in[14];
    const float* out1_b = (const float*)d_in[15];
    const float* out2_w = (const float*)d_in[16];
    const float* out2_b = (const float*)d_in[17];
    float* out = (float*)d_out;

    cudaFuncSetAttribute(k_conv, cudaFuncAttributeMaxDynamicSharedMemorySize,
                         CVX_TOT * 4);
    cudaFuncSetAttribute(k_layers_h, cudaFuncAttributeMaxDynamicSharedMemorySize,
                         K3_SMEM);

    k_inproj<<<8192, 256>>>(X, in_w, in_b);
    k_conv<<<1024, 512, CVX_TOT * 4>>>(ct_w, ct_b, cs_w, cs_b);
    k_layers_h<<<4096, 256, K3_SMEM>>>(A, gcn_w, gcn_b, res_w, res_b, skip_w,
                                       skip_b, out1_w, out1_b, out2_w, out2_b,
                                       out);
}

// round 10
// speedup vs baseline: 1.5499x; 1.1468x over previous
#include <cuda_runtime.h>
#include <cuda_bf16.h>
#include <math.h>
#include <stdint.h>

// Problem constants: B=8, T=512, N=128, F=16, H=32, L=4
#define BTNH_ 16777216ull   // 8*512*128*32

// Scratch (allocation-free: static device globals)
__device__ float g_xa[16777216];
__device__ float g_xb[16777216];
__device__ float g_xres[16777216];
__device__ float g_tcn[4ull * 16777216ull];  // [l][b][t][n][o]

// ====================== common helpers ======================
__device__ __forceinline__ uint32_t smem_u32(const void* p) {
    uint32_t a;
    asm("{ .reg .u64 t; cvta.to.shared.u64 t, %1; cvt.u32.u64 %0, t; }"
        : "=r"(a) : "l"(p));
    return a;
}
__device__ __forceinline__ void ldmat4(uint32_t r[4], uint32_t addr) {
    asm volatile("ldmatrix.sync.aligned.m8n8.x4.shared.b16 {%0,%1,%2,%3}, [%4];"
                 : "=r"(r[0]), "=r"(r[1]), "=r"(r[2]), "=r"(r[3]) : "r"(addr));
}
__device__ __forceinline__ void mma16816(float d[4], const uint32_t a[4],
                                         uint32_t b0, uint32_t b1) {
    asm volatile(
        "mma.sync.aligned.m16n8k16.row.col.f32.bf16.bf16.f32 "
        "{%0,%1,%2,%3}, {%4,%5,%6,%7}, {%8,%9}, {%0,%1,%2,%3};"
        : "+f"(d[0]), "+f"(d[1]), "+f"(d[2]), "+f"(d[3])
        : "r"(a[0]), "r"(a[1]), "r"(a[2]), "r"(a[3]), "r"(b0), "r"(b1));
}
__device__ __forceinline__ uint32_t pack_bf16(__nv_bfloat16 lo, __nv_bfloat16 hi) {
    return (uint32_t)__bfloat16_as_ushort(lo) |
           ((uint32_t)__bfloat16_as_ushort(hi) << 16);
}

// ---------------------------------------------------------------------------
// K1: input projection (measured 100us, unchanged)
// ---------------------------------------------------------------------------
__global__ void __launch_bounds__(256) k_inproj(const float* __restrict__ X,
                                                const float* __restrict__ in_w,
                                                const float* __restrict__ in_b) {
    __shared__ float sw[1536];
    __shared__ float sb[96];
    for (int i = threadIdx.x; i < 1536; i += 256) sw[i] = in_w[i];
    if (threadIdx.x < 96) sb[threadIdx.x] = in_b[threadIdx.x];
    __syncthreads();

    int o = threadIdx.x & 31;
    int rsub = threadIdx.x >> 5;
#pragma unroll
    for (int gph = 0; gph < 8; gph++) {
        int row = blockIdx.x * 64 + gph * 8 + rsub;
        const float4* xr = (const float4*)(X + (size_t)row * 16);
        float4 v0 = xr[0], v1 = xr[1], v2 = xr[2], v3 = xr[3];
        float x[16] = {v0.x, v0.y, v0.z, v0.w, v1.x, v1.y, v1.z, v1.w,
                       v2.x, v2.y, v2.z, v2.w, v3.x, v3.y, v3.z, v3.w};
        float a0 = sb[o], a1 = sb[32 + o], a2 = sb[64 + o];
#pragma unroll
        for (int f = 0; f < 16; f++) {
            float xv = x[f];
            a0 = fmaf(xv, sw[f * 96 + o], a0);
            a1 = fmaf(xv, sw[f * 96 + 32 + o], a1);
            a2 = fmaf(xv, sw[f * 96 + 64 + o], a2);
        }
        size_t p = (size_t)row * 32 + o;
        g_xa[p] = a0;
        g_xb[p] = a1;
        g_xres[p] = a2;
    }
}

// ---------------------------------------------------------------------------
// K2 v3: gated dilated causal convs via mma.sync split-bf16 (3-pass).
// One block per bn (1024 blocks), 512 threads = 16 warps; warp w owns taus
// [32w, 32w+32) = 2 m16 tiles.  out[tau][o] = sum_k A[tau][k] W[k][o],
// K=64 with k<32 -> x[tau-d][k] (tap0), k>=32 -> x[tau][k-32] (tap1).
// x stored bf16 hi/lo, rows 8..519 (rows 0..7 zero = causal pad), pitch 80B
// (20 words -> ldmatrix lane addrs land on distinct bank quads: 20i mod 32
// all distinct).  Dilation handled by per-lane ldmatrix row offset (-d on
// the tap0 k-chunks).  Weights hi/lo as k-pair words, pitch 33.
// smem byte offsets:
#define XAH_B 0         // x_a hi: 520 rows x 20 words = 41600 B
#define XAL_B 41600
#define XBH_B 83200
#define XBL_B 124800
#define WAH_B 166400    // 32 krows x 33 words = 4224 B
#define WAL_B 170624
#define WBH_B 174848
#define WBL_B 179072
#define CBA_B 183296    // 32 floats
#define CBB_B 183424
#define K2_SMEM 183552

__device__ __forceinline__ void conv_mma(uint32_t sbase, const char* smem,
                                         uint32_t xh, uint32_t xl,
                                         uint32_t wh, uint32_t wl,
                                         const float* __restrict__ bias,
                                         int tau0w, int lane, int d,
                                         float acc[2][4][4]) {
    // init with bias: frag (mt,nt,q) -> o = nt*8 + (lane&3)*2 + (q&1)
#pragma unroll
    for (int nt = 0; nt < 4; nt++) {
        float bq0 = bias[nt * 8 + (lane & 3) * 2];
        float bq1 = bias[nt * 8 + (lane & 3) * 2 + 1];
#pragma unroll
        for (int mt = 0; mt < 2; mt++) {
            acc[mt][nt][0] = bq0; acc[mt][nt][1] = bq1;
            acc[mt][nt][2] = bq0; acc[mt][nt][3] = bq1;
        }
    }
    int rbase = 8 + tau0w + (lane & 15);
    int chan = (lane >> 4) * 8;
#pragma unroll
    for (int ks = 0; ks < 4; ks++) {
        int tsh = (ks < 2) ? d : 0;
        int ch = chan + (ks & 1) * 16;
        uint32_t arow = (uint32_t)((rbase - tsh) * 80 + ch * 2);
        uint32_t ah[2][4], al[2][4];
        ldmat4(ah[0], sbase + xh + arow);
        ldmat4(ah[1], sbase + xh + arow + 16 * 80);
        ldmat4(al[0], sbase + xl + arow);
        ldmat4(al[1], sbase + xl + arow + 16 * 80);
        int krow = ks * 8 + (lane & 3);
#pragma unroll
        for (int nt = 0; nt < 4; nt++) {
            int wi = krow * 33 + nt * 8 + (lane >> 2);
            uint32_t b0h = *(const uint32_t*)(smem + wh + (size_t)wi * 4);
            uint32_t b1h = *(const uint32_t*)(smem + wh + (size_t)(wi + 132) * 4);
            uint32_t b0l = *(const uint32_t*)(smem + wl + (size_t)wi * 4);
            uint32_t b1l = *(const uint32_t*)(smem + wl + (size_t)(wi + 132) * 4);
#pragma unroll
            for (int mt = 0; mt < 2; mt++) {
                mma16816(acc[mt][nt], ah[mt], b0h, b1h);
                mma16816(acc[mt][nt], ah[mt], b0l, b1l);
                mma16816(acc[mt][nt], al[mt], b0h, b1h);
            }
        }
    }
}

__global__ void __launch_bounds__(512, 1) k_conv_t(const float* __restrict__ ct_w,
                                                   const float* __restrict__ ct_b,
                                                   const float* __restrict__ cs_w,
                                                   const float* __restrict__ cs_b) {
    extern __shared__ char smem[];
    uint32_t sbase = smem_u32(smem);
    int tid = threadIdx.x, lane = tid & 31, warp = tid >> 5;
    int bn = blockIdx.x, b = bn >> 7, n = bn & 127;
    int tau0w = warp * 32;

    // zero causal pad rows (rows 0..7 = 160 words per buffer)
    if (tid < 160) {
        ((uint32_t*)(smem + XAH_B))[tid] = 0;
        ((uint32_t*)(smem + XAL_B))[tid] = 0;
        ((uint32_t*)(smem + XBH_B))[tid] = 0;
        ((uint32_t*)(smem + XBL_B))[tid] = 0;
    }
    // stage x_a / x_b as bf16 hi/lo (read-only for all 4 layers)
    const float2* xa = (const float2*)(g_xa + (size_t)bn * 16384);
    const float2* xb = (const float2*)(g_xb + (size_t)bn * 16384);
    for (int i = tid; i < 8192; i += 512) {
        float2 va = xa[i];
        float2 vb = xb[i];
        int tau = i >> 4, cp = i & 15;
        uint32_t w = (uint32_t)((8 + tau) * 20 + cp);
        __nv_bfloat16 ax = __float2bfloat16(va.x), ay = __float2bfloat16(va.y);
        __nv_bfloat16 bx = __float2bfloat16(vb.x), by = __float2bfloat16(vb.y);
        ((uint32_t*)(smem + XAH_B))[w] = pack_bf16(ax, ay);
        ((uint32_t*)(smem + XAL_B))[w] =
            pack_bf16(__float2bfloat16(va.x - __bfloat162float(ax)),
                      __float2bfloat16(va.y - __bfloat162float(ay)));
        ((uint32_t*)(smem + XBH_B))[w] = pack_bf16(bx, by);
        ((uint32_t*)(smem + XBL_B))[w] =
            pack_bf16(__float2bfloat16(vb.x - __bfloat162float(bx)),
                      __float2bfloat16(vb.y - __bfloat162float(by)));
    }

    for (int l = 0; l < 4; l++) {
        __syncthreads();  // x staged (l=0) / prev layer's weight readers done
        // stage weights as bf16 hi/lo k-pair words: word(krow,o) =
        //   pack(W[2krow][o], W[2krow+1][o]), W[k][o] = w[tap=k>>5][c=k&31][o]
        for (int i = tid; i < 1024; i += 512) {
            int krow = i >> 5, o = i & 31;
            int k0 = krow * 2;
            const float* wa = ct_w + l * 2048 + (k0 >> 5) * 1024 + (k0 & 31) * 32 + o;
            const float* wb = cs_w + l * 2048 + (k0 >> 5) * 1024 + (k0 & 31) * 32 + o;
            float a0 = wa[0], a1 = wa[32], b0 = wb[0], b1 = wb[32];
            __nv_bfloat16 ah0 = __float2bfloat16(a0), ah1 = __float2bfloat16(a1);
            __nv_bfloat16 bh0 = __float2bfloat16(b0), bh1 = __float2bfloat16(b1);
            int wi = krow * 33 + o;
            ((uint32_t*)(smem + WAH_B))[wi] = pack_bf16(ah0, ah1);
            ((uint32_t*)(smem + WAL_B))[wi] =
                pack_bf16(__float2bfloat16(a0 - __bfloat162float(ah0)),
                          __float2bfloat16(a1 - __bfloat162float(ah1)));
            ((uint32_t*)(smem + WBH_B))[wi] = pack_bf16(bh0, bh1);
            ((uint32_t*)(smem + WBL_B))[wi] =
                pack_bf16(__float2bfloat16(b0 - __bfloat162float(bh0)),
                          __float2bfloat16(b1 - __bfloat162float(bh1)));
        }
        if (tid < 32) {
            ((float*)(smem + CBA_B))[tid] = ct_b[l * 32 + tid];
            ((float*)(smem + CBB_B))[tid] = cs_b[l * 32 + tid];
        }
        __syncthreads();
        int d = 1 << l;

        // conv_a -> tanh
        float ta[2][4][4];
        conv_mma(sbase, smem, XAH_B, XAL_B, WAH_B, WAL_B,
                 (const float*)(smem + CBA_B), tau0w, lane, d, ta);
#pragma unroll
        for (int mt = 0; mt < 2; mt++)
#pragma unroll
            for (int nt = 0; nt < 4; nt++)
#pragma unroll
                for (int q = 0; q < 4; q++) {
                    float a = ta[mt][nt][q];
                    float t = __expf(-2.f * fabsf(a));
                    float r = (1.f - t) / (1.f + t);
                    ta[mt][nt][q] = copysignf(r, a);
                }
        // conv_b -> sigmoid -> gate
        float sg[2][4][4];
        conv_mma(sbase, smem, XBH_B, XBL_B, WBH_B, WBL_B,
                 (const float*)(smem + CBB_B), tau0w, lane, d, sg);

        float* outl = g_tcn + (size_t)l * BTNH_ + ((size_t)b * 512) * 4096 + n * 32;
#pragma unroll
        for (int mt = 0; mt < 2; mt++)
#pragma unroll
            for (int nt = 0; nt < 4; nt++) {
                float v[4];
#pragma unroll
                for (int q = 0; q < 4; q++) {
                    float s = 1.f / (1.f + __expf(-sg[mt][nt][q]));
                    v[q] = ta[mt][nt][q] * s;
                }
                int r = tau0w + mt * 16 + (lane >> 2);
                int o0 = nt * 8 + (lane & 3) * 2;
                *(float2*)(outl + (size_t)r * 4096 + o0) = make_float2(v[0], v[1]);
                *(float2*)(outl + (size_t)(r + 8) * 4096 + o0) =
                    make_float2(v[2], v[3]);
            }
    }
}

// ---------------------------------------------------------------------------
// K3 v3b: HMMA A-mix + warp-tiled SIMT epilogue (round-9 form, PASSED)
// ---------------------------------------------------------------------------
#define SAH_B   0
#define SAL_B   34816
#define SX_B    69632
#define SXH_B   86528
#define SXL_B   95232
#define SAX_B   86528
#define K3_SMEM 104960

__global__ void __launch_bounds__(256, 2) k_layers_h(
    const float* __restrict__ A, const float* __restrict__ gcn_w,
    const float* __restrict__ gcn_b, const float* __restrict__ res_w,
    const float* __restrict__ res_b, const float* __restrict__ skip_w,
    const float* __restrict__ skip_b, const float* __restrict__ out1_w,
    const float* __restrict__ out1_b, const float* __restrict__ out2_w,
    const float* __restrict__ out2_b, float* __restrict__ out) {
    extern __shared__ char smem[];
    uint32_t sbase = smem_u32(smem);
    int tid = threadIdx.x;
    int lane = tid & 31;
    int g = tid >> 5;
    int o = lane;
    int row0 = g * 16;
    int bt = blockIdx.x;
    size_t base = (size_t)bt * 4096;

    float* sX = (float*)(smem + SX_B);
    float* sAX = (float*)(smem + SAX_B);

    for (int i = tid; i < 4096; i += 256) {
        int row = i >> 5, c4 = (i & 31) * 4;
        float4 v = ((const float4*)A)[i];
        __nv_bfloat16 h0 = __float2bfloat16(v.x);
        __nv_bfloat16 h1 = __float2bfloat16(v.y);
        __nv_bfloat16 h2 = __float2bfloat16(v.z);
        __nv_bfloat16 h3 = __float2bfloat16(v.w);
        __nv_bfloat16 l0 = __float2bfloat16(v.x - __bfloat162float(h0));
        __nv_bfloat16 l1 = __float2bfloat16(v.y - __bfloat162float(h1));
        __nv_bfloat16 l2 = __float2bfloat16(v.z - __bfloat162float(h2));
        __nv_bfloat16 l3 = __float2bfloat16(v.w - __bfloat162float(h3));
        uint32_t* ph = (uint32_t*)(smem + SAH_B + (row * 136 + c4) * 2);
        uint32_t* pl = (uint32_t*)(smem + SAL_B + (row * 136 + c4) * 2);
        ph[0] = pack_bf16(h0, h1); ph[1] = pack_bf16(h2, h3);
        pl[0] = pack_bf16(l0, l1); pl[1] = pack_bf16(l2, l3);
    }
    for (int i = tid; i < 4096; i += 256) {
        int j = i >> 5, oo = i & 31;
        sX[j * 33 + oo] = g_xres[base + i];
    }
    __syncthreads();  // (0) staging visible before first X-split read of sX

    int lrow = lane & 15, khalf = lane >> 4;
    uint32_t amh_base =
        sbase + SAH_B + (uint32_t)(((row0 + lrow) * 136 + khalf * 8) * 2);
    uint32_t aml_base =
        sbase + SAL_B + (uint32_t)(((row0 + lrow) * 136 + khalf * 8) * 2);
    int bn_row = ((lane >> 4) << 3) + (lane & 7);
    int bk_half = (lane >> 3) & 1;
    uint32_t bh_base =
        sbase + SXH_B + (uint32_t)((bn_row * 136 + bk_half * 8) * 2);
    uint32_t bl_base =
        sbase + SXL_B + (uint32_t)((bn_row * 136 + bk_half * 8) * 2);

    int xj = tid & 127;
    int xo0 = (tid >> 7) * 16;

    float skip[16];
#pragma unroll
    for (int ii = 0; ii < 16; ii++) skip[ii] = 0.f;

    for (int l = 0; l < 4; l++) {
#pragma unroll
        for (int oo = 0; oo < 16; oo++) {
            int oc = xo0 + oo;
            float v = sX[xj * 33 + oc];
            __nv_bfloat16 hi = __float2bfloat16(v);
            __nv_bfloat16 lo = __float2bfloat16(v - __bfloat162float(hi));
            *(__nv_bfloat16*)(smem + SXH_B + (oc * 136 + xj) * 2) = hi;
            *(__nv_bfloat16*)(smem + SXL_B + (oc * 136 + xj) * 2) = lo;
        }
        __syncthreads();  // (1) X-split visible

        float acc[4][4];
#pragma unroll
        for (int nt = 0; nt < 4; nt++)
#pragma unroll
            for (int q = 0; q < 4; q++) acc[nt][q] = 0.f;

#pragma unroll
        for (int ks = 0; ks < 8; ks++) {
            uint32_t kb = (uint32_t)(ks * 32);
            uint32_t ah[4], al[4], bh[2][4], bl[2][4];
            ldmat4(ah, amh_base + kb);
            ldmat4(al, aml_base + kb);
            ldmat4(bh[0], bh_base + kb);
            ldmat4(bh[1], bh_base + 16 * 272 + kb);
            ldmat4(bl[0], bl_base + kb);
            ldmat4(bl[1], bl_base + 16 * 272 + kb);
#pragma unroll
            for (int nt = 0; nt < 4; nt++) {
                uint32_t b0h = bh[nt >> 1][(nt & 1) * 2];
                uint32_t b1h = bh[nt >> 1][(nt & 1) * 2 + 1];
                uint32_t b0l = bl[nt >> 1][(nt & 1) * 2];
                uint32_t b1l = bl[nt >> 1][(nt & 1) * 2 + 1];
                mma16816(acc[nt], ah, b0h, b1h);
                mma16816(acc[nt], ah, b0l, b1l);
                mma16816(acc[nt], al, b0h, b1h);
            }
        }
        __syncthreads();  // (2) ldmatrix reads done before overlay

#pragma unroll
        for (int nt = 0; nt < 4; nt++) {
            int r0 = row0 + (lane >> 2);
            int c = nt * 8 + (lane & 3) * 2;
            *(float2*)&sAX[r0 * 36 + c] = make_float2(acc[nt][0], acc[nt][1]);
            *(float2*)&sAX[(r0 + 8) * 36 + c] = make_float2(acc[nt][2], acc[nt][3]);
        }
        __syncthreads();  // (3) sAX visible

        float w[32];
#pragma unroll
        for (int c = 0; c < 32; c++) w[c] = __ldg(&gcn_w[l * 1024 + c * 32 + o]);
        float bq = __ldg(&gcn_b[l * 32 + o]);
        const float* tcnp = g_tcn + (size_t)l * BTNH_ + base;
        float h[16];
#pragma unroll
        for (int ii = 0; ii < 16; ii++) {
            float s = bq;
            const float* rowp = &sAX[(row0 + ii) * 36];
#pragma unroll
            for (int c4 = 0; c4 < 8; c4++) {
                float4 v = *(const float4*)&rowp[c4 * 4];
                s = fmaf(v.x, w[4 * c4 + 0],
                    fmaf(v.y, w[4 * c4 + 1],
                    fmaf(v.z, w[4 * c4 + 2], fmaf(v.w, w[4 * c4 + 3], s))));
            }
            h[ii] = s + tcnp[(row0 + ii) * 32 + o];
        }
        __syncwarp();
#pragma unroll
        for (int ii = 0; ii < 16; ii++) sAX[(row0 + ii) * 36 + o] = h[ii];
        __syncwarp();

#pragma unroll
        for (int c = 0; c < 32; c++) w[c] = __ldg(&skip_w[l * 1024 + c * 32 + o]);
        float bs = __ldg(&skip_b[l * 32 + o]);
#pragma unroll
        for (int ii = 0; ii < 16; ii++) {
            float s = bs;
            const float* rowp = &sAX[(row0 + ii) * 36];
#pragma unroll
            for (int c4 = 0; c4 < 8; c4++) {
                float4 v = *(const float4*)&rowp[c4 * 4];
                s = fmaf(v.x, w[4 * c4 + 0],
                    fmaf(v.y, w[4 * c4 + 1],
                    fmaf(v.z, w[4 * c4 + 2], fmaf(v.w, w[4 * c4 + 3], s))));
            }
            skip[ii] += s;
        }

#pragma unroll
        for (int c = 0; c < 32; c++) w[c] = __ldg(&res_w[l * 1024 + c * 32 + o]);
        float br = __ldg(&res_b[l * 32 + o]);
        float xn[16];
#pragma unroll
        for (int ii = 0; ii < 16; ii++) {
            float s = br;
            const float* rowp = &sAX[(row0 + ii) * 36];
#pragma unroll
            for (int c4 = 0; c4 < 8; c4++) {
                float4 v = *(const float4*)&rowp[c4 * 4];
                s = fmaf(v.x, w[4 * c4 + 0],
                    fmaf(v.y, w[4 * c4 + 1],
                    fmaf(v.z, w[4 * c4 + 2], fmaf(v.w, w[4 * c4 + 3], s))));
            }
            xn[ii] = s + sX[(row0 + ii) * 33 + o];
        }
        __syncthreads();  // (4) reads of sX / sAX done
#pragma unroll
        for (int ii = 0; ii < 16; ii++) sX[(row0 + ii) * 33 + o] = xn[ii];
        __syncthreads();  // (5) sX update visible
    }

#pragma unroll
    for (int ii = 0; ii < 16; ii++)
        sAX[(row0 + ii) * 36 + o] = fmaxf(skip[ii], 0.f);
    __syncwarp();

    float w1r[32];
#pragma unroll
    for (int c = 0; c < 32; c++) w1r[c] = __ldg(&out1_w[c * 32 + o]);
    float b1 = __ldg(&out1_b[o]);
    float h2[16];
#pragma unroll
    for (int ii = 0; ii < 16; ii++) {
        float s = b1;
        const float* rowp = &sAX[(row0 + ii) * 36];
#pragma unroll
        for (int c4 = 0; c4 < 8; c4++) {
            float4 v = *(const float4*)&rowp[c4 * 4];
            s = fmaf(v.x, w1r[4 * c4 + 0],
                fmaf(v.y, w1r[4 * c4 + 1],
                fmaf(v.z, w1r[4 * c4 + 2], fmaf(v.w, w1r[4 * c4 + 3], s))));
        }
        h2[ii] = fmaxf(s, 0.f);
    }
    __syncwarp();
#pragma unroll
    for (int ii = 0; ii < 16; ii++) sAX[(row0 + ii) * 36 + o] = h2[ii];
    __syncwarp();

    if (o < 16) {
        float w2r[32];
#pragma unroll
        for (int c = 0; c < 32; c++) w2r[c] = __ldg(&out2_w[c * 16 + o]);
        float b2 = __ldg(&out2_b[o]);
        float* op = out + (size_t)bt * 2048;
#pragma unroll
        for (int ii = 0; ii < 16; ii++) {
            float s = b2;
            const float* rowp = &sAX[(row0 + ii) * 36];
#pragma unroll
            for (int c4 = 0; c4 < 8; c4++) {
                float4 v = *(const float4*)&rowp[c4 * 4];
                s = fmaf(v.x, w2r[4 * c4 + 0],
                    fmaf(v.y, w2r[4 * c4 + 1],
                    fmaf(v.z, w2r[4 * c4 + 2], fmaf(v.w, w2r[4 * c4 + 3], s))));
            }
            op[(row0 + ii) * 16 + o] = s;
        }
    }
}

// ---------------------------------------------------------------------------
extern "C" void kernel_launch(void* const* d_in, const int* in_sizes, int n_in,
                              void* d_out, int out_size) {
    const float* X = (const float*)d_in[0];
    const float* A = (const float*)d_in[1];
    const float* in_w = (const float*)d_in[2];
    const float* in_b = (const float*)d_in[3];
    const float* ct_w = (const float*)d_in[4];
    const float* ct_b = (const float*)d_in[5];
    const float* cs_w = (const float*)d_in[6];
    const float* cs_b = (const float*)d_in[7];
    const float* gcn_w = (const float*)d_in[8];
    const float* gcn_b = (const float*)d_in[9];
    const float* res_w = (const float*)d_in[10];
    const float* res_b = (const float*)d_in[11];
    const float* skip_w = (const float*)d_in[12];
    const float* skip_b = (const float*)d_in[13];
    const float* out1_w = (const float*)d_in[14];
    const float* out1_b = (const float*)d_in[15];
    const float* out2_w = (const float*)d_in[16];
    const float* out2_b = (const float*)d_in[17];
    float* out = (float*)d_out;

    cudaFuncSetAttribute(k_conv_t, cudaFuncAttributeMaxDynamicSharedMemorySize,
                         K2_SMEM);
    cudaFuncSetAttribute(k_layers_h, cudaFuncAttributeMaxDynamicSharedMemorySize,
                         K3_SMEM);

    k_inproj<<<8192, 256>>>(X, in_w, in_b);
    k_conv_t<<<1024, 512, K2_SMEM>>>(ct_w, ct_b, cs_w, cs_b);
    k_layers_h<<<4096, 256, K3_SMEM>>>(A, gcn_w, gcn_b, res_w, res_b, skip_w,
                                       skip_b, out1_w, out1_b, out2_w, out2_b,
                                       out);
}

// round 11
// speedup vs baseline: 2.2292x; 1.4383x over previous
#include <cuda_runtime.h>
#include <cuda_bf16.h>
#include <math.h>
#include <stdint.h>

// Problem constants: B=8, T=512, N=128, F=16, H=32, L=4
#define BTNH_ 16777216ull   // 8*512*128*32

// Scratch (allocation-free: static device globals)
__device__ float g_xa[16777216];
__device__ float g_xb[16777216];
__device__ float g_xres[16777216];
__device__ float g_tcn[4ull * 16777216ull];  // [l][b][t][n][o]

// ====================== common helpers ======================
__device__ __forceinline__ uint32_t smem_u32(const void* p) {
    uint32_t a;
    asm("{ .reg .u64 t; cvta.to.shared.u64 t, %1; cvt.u32.u64 %0, t; }"
        : "=r"(a) : "l"(p));
    return a;
}
__device__ __forceinline__ void ldmat4(uint32_t r[4], uint32_t addr) {
    asm volatile("ldmatrix.sync.aligned.m8n8.x4.shared.b16 {%0,%1,%2,%3}, [%4];"
                 : "=r"(r[0]), "=r"(r[1]), "=r"(r[2]), "=r"(r[3]) : "r"(addr));
}
__device__ __forceinline__ void mma16816(float d[4], const uint32_t a[4],
                                         uint32_t b0, uint32_t b1) {
    asm volatile(
        "mma.sync.aligned.m16n8k16.row.col.f32.bf16.bf16.f32 "
        "{%0,%1,%2,%3}, {%4,%5,%6,%7}, {%8,%9}, {%0,%1,%2,%3};"
        : "+f"(d[0]), "+f"(d[1]), "+f"(d[2]), "+f"(d[3])
        : "r"(a[0]), "r"(a[1]), "r"(a[2]), "r"(a[3]), "r"(b0), "r"(b1));
}
__device__ __forceinline__ uint32_t pack_bf16(__nv_bfloat16 lo, __nv_bfloat16 hi) {
    return (uint32_t)__bfloat16_as_ushort(lo) |
           ((uint32_t)__bfloat16_as_ushort(hi) << 16);
}
__device__ __forceinline__ void split2(float v0, float v1, uint32_t& hw,
                                       uint32_t& lw) {
    __nv_bfloat16 h0 = __float2bfloat16(v0), h1 = __float2bfloat16(v1);
    hw = pack_bf16(h0, h1);
    lw = pack_bf16(__float2bfloat16(v0 - __bfloat162float(h0)),
                   __float2bfloat16(v1 - __bfloat162float(h1)));
}

// ---------------------------------------------------------------------------
// K1: input projection (unchanged)
// ---------------------------------------------------------------------------
__global__ void __launch_bounds__(256) k_inproj(const float* __restrict__ X,
                                                const float* __restrict__ in_w,
                                                const float* __restrict__ in_b) {
    __shared__ float sw[1536];
    __shared__ float sb[96];
    for (int i = threadIdx.x; i < 1536; i += 256) sw[i] = in_w[i];
    if (threadIdx.x < 96) sb[threadIdx.x] = in_b[threadIdx.x];
    __syncthreads();

    int o = threadIdx.x & 31;
    int rsub = threadIdx.x >> 5;
#pragma unroll
    for (int gph = 0; gph < 8; gph++) {
        int row = blockIdx.x * 64 + gph * 8 + rsub;
        const float4* xr = (const float4*)(X + (size_t)row * 16);
        float4 v0 = xr[0], v1 = xr[1], v2 = xr[2], v3 = xr[3];
        float x[16] = {v0.x, v0.y, v0.z, v0.w, v1.x, v1.y, v1.z, v1.w,
                       v2.x, v2.y, v2.z, v2.w, v3.x, v3.y, v3.z, v3.w};
        float a0 = sb[o], a1 = sb[32 + o], a2 = sb[64 + o];
#pragma unroll
        for (int f = 0; f < 16; f++) {
            float xv = x[f];
            a0 = fmaf(xv, sw[f * 96 + o], a0);
            a1 = fmaf(xv, sw[f * 96 + 32 + o], a1);
            a2 = fmaf(xv, sw[f * 96 + 64 + o], a2);
        }
        size_t p = (size_t)row * 32 + o;
        g_xa[p] = a0;
        g_xb[p] = a1;
        g_xres[p] = a2;
    }
}

// ---------------------------------------------------------------------------
// K2: conv via mma.sync split-bf16 (round-10 form, PASSED, unchanged)
// ---------------------------------------------------------------------------
#define XAH_B 0
#define XAL_B 41600
#define XBH_B 83200
#define XBL_B 124800
#define WAH_B 166400
#define WAL_B 170624
#define WBH_B 174848
#define WBL_B 179072
#define CBA_B 183296
#define CBB_B 183424
#define K2_SMEM 183552

__device__ __forceinline__ void conv_mma(uint32_t sbase, const char* smem,
                                         uint32_t xh, uint32_t xl,
                                         uint32_t wh, uint32_t wl,
                                         const float* __restrict__ bias,
                                         int tau0w, int lane, int d,
                                         float acc[2][4][4]) {
#pragma unroll
    for (int nt = 0; nt < 4; nt++) {
        float bq0 = bias[nt * 8 + (lane & 3) * 2];
        float bq1 = bias[nt * 8 + (lane & 3) * 2 + 1];
#pragma unroll
        for (int mt = 0; mt < 2; mt++) {
            acc[mt][nt][0] = bq0; acc[mt][nt][1] = bq1;
            acc[mt][nt][2] = bq0; acc[mt][nt][3] = bq1;
        }
    }
    int rbase = 8 + tau0w + (lane & 15);
    int chan = (lane >> 4) * 8;
#pragma unroll
    for (int ks = 0; ks < 4; ks++) {
        int tsh = (ks < 2) ? d : 0;
        int ch = chan + (ks & 1) * 16;
        uint32_t arow = (uint32_t)((rbase - tsh) * 80 + ch * 2);
        uint32_t ah[2][4], al[2][4];
        ldmat4(ah[0], sbase + xh + arow);
        ldmat4(ah[1], sbase + xh + arow + 16 * 80);
        ldmat4(al[0], sbase + xl + arow);
        ldmat4(al[1], sbase + xl + arow + 16 * 80);
        int krow = ks * 8 + (lane & 3);
#pragma unroll
        for (int nt = 0; nt < 4; nt++) {
            int wi = krow * 33 + nt * 8 + (lane >> 2);
            uint32_t b0h = *(const uint32_t*)(smem + wh + (size_t)wi * 4);
            uint32_t b1h = *(const uint32_t*)(smem + wh + (size_t)(wi + 132) * 4);
            uint32_t b0l = *(const uint32_t*)(smem + wl + (size_t)wi * 4);
            uint32_t b1l = *(const uint32_t*)(smem + wl + (size_t)(wi + 132) * 4);
#pragma unroll
            for (int mt = 0; mt < 2; mt++) {
                mma16816(acc[mt][nt], ah[mt], b0h, b1h);
                mma16816(acc[mt][nt], ah[mt], b0l, b1l);
                mma16816(acc[mt][nt], al[mt], b0h, b1h);
            }
        }
    }
}

__global__ void __launch_bounds__(512, 1) k_conv_t(const float* __restrict__ ct_w,
                                                   const float* __restrict__ ct_b,
                                                   const float* __restrict__ cs_w,
                                                   const float* __restrict__ cs_b) {
    extern __shared__ char smem[];
    uint32_t sbase = smem_u32(smem);
    int tid = threadIdx.x, lane = tid & 31, warp = tid >> 5;
    int bn = blockIdx.x, b = bn >> 7, n = bn & 127;
    int tau0w = warp * 32;

    if (tid < 160) {
        ((uint32_t*)(smem + XAH_B))[tid] = 0;
        ((uint32_t*)(smem + XAL_B))[tid] = 0;
        ((uint32_t*)(smem + XBH_B))[tid] = 0;
        ((uint32_t*)(smem + XBL_B))[tid] = 0;
    }
    const float2* xa = (const float2*)(g_xa + (size_t)bn * 16384);
    const float2* xb = (const float2*)(g_xb + (size_t)bn * 16384);
    for (int i = tid; i < 8192; i += 512) {
        float2 va = xa[i];
        float2 vb = xb[i];
        int tau = i >> 4, cp = i & 15;
        uint32_t w = (uint32_t)((8 + tau) * 20 + cp);
        uint32_t hw, lw;
        split2(va.x, va.y, hw, lw);
        ((uint32_t*)(smem + XAH_B))[w] = hw;
        ((uint32_t*)(smem + XAL_B))[w] = lw;
        split2(vb.x, vb.y, hw, lw);
        ((uint32_t*)(smem + XBH_B))[w] = hw;
        ((uint32_t*)(smem + XBL_B))[w] = lw;
    }

    for (int l = 0; l < 4; l++) {
        __syncthreads();
        for (int i = tid; i < 1024; i += 512) {
            int krow = i >> 5, o = i & 31;
            int k0 = krow * 2;
            const float* wa = ct_w + l * 2048 + (k0 >> 5) * 1024 + (k0 & 31) * 32 + o;
            const float* wb = cs_w + l * 2048 + (k0 >> 5) * 1024 + (k0 & 31) * 32 + o;
            uint32_t hw, lw;
            int wi = krow * 33 + o;
            split2(wa[0], wa[32], hw, lw);
            ((uint32_t*)(smem + WAH_B))[wi] = hw;
            ((uint32_t*)(smem + WAL_B))[wi] = lw;
            split2(wb[0], wb[32], hw, lw);
            ((uint32_t*)(smem + WBH_B))[wi] = hw;
            ((uint32_t*)(smem + WBL_B))[wi] = lw;
        }
        if (tid < 32) {
            ((float*)(smem + CBA_B))[tid] = ct_b[l * 32 + tid];
            ((float*)(smem + CBB_B))[tid] = cs_b[l * 32 + tid];
        }
        __syncthreads();
        int d = 1 << l;

        float ta[2][4][4];
        conv_mma(sbase, smem, XAH_B, XAL_B, WAH_B, WAL_B,
                 (const float*)(smem + CBA_B), tau0w, lane, d, ta);
#pragma unroll
        for (int mt = 0; mt < 2; mt++)
#pragma unroll
            for (int nt = 0; nt < 4; nt++)
#pragma unroll
                for (int q = 0; q < 4; q++) {
                    float a = ta[mt][nt][q];
                    float t = __expf(-2.f * fabsf(a));
                    float r = (1.f - t) / (1.f + t);
                    ta[mt][nt][q] = copysignf(r, a);
                }
        float sg[2][4][4];
        conv_mma(sbase, smem, XBH_B, XBL_B, WBH_B, WBL_B,
                 (const float*)(smem + CBB_B), tau0w, lane, d, sg);

        float* outl = g_tcn + (size_t)l * BTNH_ + ((size_t)b * 512) * 4096 + n * 32;
#pragma unroll
        for (int mt = 0; mt < 2; mt++)
#pragma unroll
            for (int nt = 0; nt < 4; nt++) {
                float v[4];
#pragma unroll
                for (int q = 0; q < 4; q++) {
                    float s = 1.f / (1.f + __expf(-sg[mt][nt][q]));
                    v[q] = ta[mt][nt][q] * s;
                }
                int r = tau0w + mt * 16 + (lane >> 2);
                int o0 = nt * 8 + (lane & 3) * 2;
                *(float2*)(outl + (size_t)r * 4096 + o0) = make_float2(v[0], v[1]);
                *(float2*)(outl + (size_t)(r + 8) * 4096 + o0) =
                    make_float2(v[2], v[3]);
            }
    }
}

// ---------------------------------------------------------------------------
// K3 v4: fully-HMMA layer chain via D-frag -> A-frag identity.
// 256 threads (8 warps) per (b,t) CTA; warp g owns i-rows [16g,16g+16).
// xres / skip / h live in persistent D-frag registers.  Weights staged as
// B-frag words (pitch 17, double-buffered).  2 syncthreads per layer.
// smem bytes:
#define SAH_B   0         // A hi bf16 [128][136]
#define SAL_B   34816     // A lo
#define SXH_B   69632     // X^T hi bf16 [32 o][136 j]
#define SXL_B   78336
#define WGT_B   87040     // 2 bufs x 6 slots x 544 words (13056 B each)
#define K3_SMEM 113152

// GEMM: d += (Ah+Al)@(Wh+Wl), 3-pass, K=32 (2 kchunks), N=32 (4 ntiles)
__device__ __forceinline__ void gemm32(float d[4][4], const uint32_t ah[2][4],
                                       const uint32_t al[2][4],
                                       const uint32_t* __restrict__ wH,
                                       const uint32_t* __restrict__ wL,
                                       int lane) {
#pragma unroll
    for (int kc = 0; kc < 2; kc++)
#pragma unroll
        for (int nt = 0; nt < 4; nt++) {
            int wi = (nt * 8 + (lane >> 2)) * 17 + kc * 8 + (lane & 3);
            uint32_t b0h = wH[wi], b1h = wH[wi + 4];
            uint32_t b0l = wL[wi], b1l = wL[wi + 4];
            mma16816(d[nt], ah[kc], b0h, b1h);
            mma16816(d[nt], ah[kc], b0l, b1l);
            mma16816(d[nt], al[kc], b0h, b1h);
        }
}
// D-frag -> bf16 hi/lo A-frags (16x32: 2 kchunks)
__device__ __forceinline__ void conv_frags(const float d[4][4], uint32_t ah[2][4],
                                           uint32_t al[2][4]) {
#pragma unroll
    for (int kc = 0; kc < 2; kc++)
#pragma unroll
        for (int r = 0; r < 4; r++) {
            int nt = 2 * kc + (r >> 1), qs = (r & 1) * 2;
            split2(d[nt][qs], d[nt][qs + 1], ah[kc][r], al[kc][r]);
        }
}
__device__ __forceinline__ void bias_add(float d[4][4],
                                         const float* __restrict__ bptr,
                                         int lane) {
#pragma unroll
    for (int nt = 0; nt < 4; nt++) {
        float2 bv = __ldg((const float2*)(bptr + nt * 8 + 2 * (lane & 3)));
        d[nt][0] += bv.x; d[nt][1] += bv.y;
        d[nt][2] += bv.x; d[nt][3] += bv.y;
    }
}
// stage one 32x32 weight matrix (W[k][o], k-stride 32) as frag words hi/lo
__device__ __forceinline__ void stage_w(const float* __restrict__ W,
                                        uint32_t* __restrict__ dstH,
                                        uint32_t* __restrict__ dstL, int tid) {
    for (int i = tid; i < 512; i += 256) {
        int o = i >> 4, cp = i & 15;
        float w0 = __ldg(&W[(2 * cp) * 32 + o]);
        float w1 = __ldg(&W[(2 * cp + 1) * 32 + o]);
        uint32_t hw, lw;
        split2(w0, w1, hw, lw);
        int idx = o * 17 + cp;
        dstH[idx] = hw;
        dstL[idx] = lw;
    }
}

__global__ void __launch_bounds__(256, 2) k_layers_f(
    const float* __restrict__ A, const float* __restrict__ gcn_w,
    const float* __restrict__ gcn_b, const float* __restrict__ res_w,
    const float* __restrict__ res_b, const float* __restrict__ skip_w,
    const float* __restrict__ skip_b, const float* __restrict__ out1_w,
    const float* __restrict__ out1_b, const float* __restrict__ out2_w,
    const float* __restrict__ out2_b, float* __restrict__ out) {
    extern __shared__ char smem[];
    uint32_t sbase = smem_u32(smem);
    int tid = threadIdx.x;
    int lane = tid & 31;
    int g = tid >> 5;
    int row0 = g * 16;
    int bt = blockIdx.x;
    size_t base = (size_t)bt * 4096;

    // ---- stage A bf16 hi/lo (once) ----
    for (int i = tid; i < 4096; i += 256) {
        int row = i >> 5, c4 = (i & 31) * 4;
        float4 v = ((const float4*)A)[i];
        uint32_t* ph = (uint32_t*)(smem + SAH_B + (row * 136 + c4) * 2);
        uint32_t* pl = (uint32_t*)(smem + SAL_B + (row * 136 + c4) * 2);
        uint32_t hw, lw;
        split2(v.x, v.y, hw, lw); ph[0] = hw; pl[0] = lw;
        split2(v.z, v.w, hw, lw); ph[1] = hw; pl[1] = lw;
    }

    // ---- ldmatrix addressing (A-mix; validated round-9) ----
    int lrow = lane & 15, khalf = lane >> 4;
    uint32_t amh_base =
        sbase + SAH_B + (uint32_t)(((row0 + lrow) * 136 + khalf * 8) * 2);
    uint32_t aml_base =
        sbase + SAL_B + (uint32_t)(((row0 + lrow) * 136 + khalf * 8) * 2);
    int bn_row = ((lane >> 4) << 3) + (lane & 7);
    int bk_half = (lane >> 3) & 1;
    uint32_t bh_base =
        sbase + SXH_B + (uint32_t)((bn_row * 136 + bk_half * 8) * 2);
    uint32_t bl_base =
        sbase + SXL_B + (uint32_t)((bn_row * 136 + bk_half * 8) * 2);

    // ---- load xres into D-frag registers ----
    float xres[4][4];
    {
        const float* xrp = g_xres + base;
#pragma unroll
        for (int nt = 0; nt < 4; nt++)
#pragma unroll
            for (int rg = 0; rg < 2; rg++) {
                float2 v = *(const float2*)(xrp +
                    (size_t)(row0 + (lane >> 2) + rg * 8) * 32 + nt * 8 +
                    2 * (lane & 3));
                xres[nt][rg * 2] = v.x;
                xres[nt][rg * 2 + 1] = v.y;
            }
    }
    float skip[4][4];
#pragma unroll
    for (int nt = 0; nt < 4; nt++)
#pragma unroll
        for (int q = 0; q < 4; q++) skip[nt][q] = 0.f;

    for (int l = 0; l < 4; l++) {
        // ---- X-split write from xres frags into SXH/SXL ----
#pragma unroll
        for (int nt = 0; nt < 4; nt++)
#pragma unroll
            for (int q = 0; q < 4; q++) {
                int oc = nt * 8 + 2 * (lane & 3) + (q & 1);
                int ic = row0 + (lane >> 2) + (q >> 1) * 8;
                float v = xres[nt][q];
                __nv_bfloat16 hi = __float2bfloat16(v);
                __nv_bfloat16 lo = __float2bfloat16(v - __bfloat162float(hi));
                *(__nv_bfloat16*)(smem + SXH_B + (oc * 136 + ic) * 2) = hi;
                *(__nv_bfloat16*)(smem + SXL_B + (oc * 136 + ic) * 2) = lo;
            }
        // ---- stage this layer's weights (double-buffered) ----
        uint32_t* wbuf = (uint32_t*)(smem + WGT_B + (l & 1) * 13056);
        stage_w(gcn_w + l * 1024, wbuf, wbuf + 544, tid);
        stage_w(skip_w + l * 1024, wbuf + 1088, wbuf + 1632, tid);
        stage_w(res_w + l * 1024, wbuf + 2176, wbuf + 2720, tid);
        __syncthreads();  // (1) X-split + weights (+ first-iter A) visible

        // ---- A-mix MMA: acc = A @ X (3-pass split) ----
        float acc[4][4];
#pragma unroll
        for (int nt = 0; nt < 4; nt++)
#pragma unroll
            for (int q = 0; q < 4; q++) acc[nt][q] = 0.f;
#pragma unroll
        for (int ks = 0; ks < 8; ks++) {
            uint32_t kb = (uint32_t)(ks * 32);
            uint32_t ah[4], al[4], bh[2][4], bl[2][4];
            ldmat4(ah, amh_base + kb);
            ldmat4(al, aml_base + kb);
            ldmat4(bh[0], bh_base + kb);
            ldmat4(bh[1], bh_base + 16 * 272 + kb);
            ldmat4(bl[0], bl_base + kb);
            ldmat4(bl[1], bl_base + 16 * 272 + kb);
#pragma unroll
            for (int nt = 0; nt < 4; nt++) {
                uint32_t b0h = bh[nt >> 1][(nt & 1) * 2];
                uint32_t b1h = bh[nt >> 1][(nt & 1) * 2 + 1];
                uint32_t b0l = bl[nt >> 1][(nt & 1) * 2];
                uint32_t b1l = bl[nt >> 1][(nt & 1) * 2 + 1];
                mma16816(acc[nt], ah, b0h, b1h);
                mma16816(acc[nt], ah, b0l, b1l);
                mma16816(acc[nt], al, b0h, b1h);
            }
        }
        __syncthreads();  // (2) ldmatrix reads done (next layer may rewrite X)

        // ---- gcn: h = AX @ gcn_w + gcn_b + tcn  (frag chain, no smem) ----
        uint32_t fh[2][4], fl[2][4];
        conv_frags(acc, fh, fl);
        float h[4][4];
#pragma unroll
        for (int nt = 0; nt < 4; nt++) {
            float2 bv = __ldg((const float2*)(gcn_b + l * 32 + nt * 8 +
                                              2 * (lane & 3)));
            h[nt][0] = bv.x; h[nt][1] = bv.y;
            h[nt][2] = bv.x; h[nt][3] = bv.y;
        }
        gemm32(h, fh, fl, wbuf, wbuf + 544, lane);
        {
            const float* tcnp = g_tcn + (size_t)l * BTNH_ + base;
#pragma unroll
            for (int nt = 0; nt < 4; nt++)
#pragma unroll
                for (int rg = 0; rg < 2; rg++) {
                    float2 tv = *(const float2*)(tcnp +
                        (size_t)(row0 + (lane >> 2) + rg * 8) * 32 + nt * 8 +
                        2 * (lane & 3));
                    h[nt][rg * 2] += tv.x;
                    h[nt][rg * 2 + 1] += tv.y;
                }
        }
        // ---- skip += h @ skip_w + skip_b ;  xres += h @ res_w + res_b ----
        conv_frags(h, fh, fl);
        bias_add(skip, skip_b + l * 32, lane);
        gemm32(skip, fh, fl, wbuf + 1088, wbuf + 1632, lane);
        bias_add(xres, res_b + l * 32, lane);
        gemm32(xres, fh, fl, wbuf + 2176, wbuf + 2720, lane);
    }

    // ---- head: stage W1/W2 into buf0 (layer-2 buffer, reads done) ----
    {
        uint32_t* hw = (uint32_t*)(smem + WGT_B);
        stage_w(out1_w, hw, hw + 544, tid);
        for (int i = tid; i < 256; i += 256) {
            int o = i >> 4, cp = i & 15;
            float w0 = __ldg(&out2_w[(2 * cp) * 16 + o]);
            float w1 = __ldg(&out2_w[(2 * cp + 1) * 16 + o]);
            uint32_t hwv, lwv;
            split2(w0, w1, hwv, lwv);
            int idx = o * 17 + cp;
            hw[1088 + idx] = hwv;
            hw[1632 + idx] = lwv;
        }
        __syncthreads();  // head weights visible

        // relu(skip) -> W1 -> relu -> W2 -> out
        uint32_t fh[2][4], fl[2][4];
#pragma unroll
        for (int nt = 0; nt < 4; nt++)
#pragma unroll
            for (int q = 0; q < 4; q++) skip[nt][q] = fmaxf(skip[nt][q], 0.f);
        conv_frags(skip, fh, fl);
        float h2[4][4];
#pragma unroll
        for (int nt = 0; nt < 4; nt++) {
            float2 bv = __ldg((const float2*)(out1_b + nt * 8 + 2 * (lane & 3)));
            h2[nt][0] = bv.x; h2[nt][1] = bv.y;
            h2[nt][2] = bv.x; h2[nt][3] = bv.y;
        }
        gemm32(h2, fh, fl, hw, hw + 544, lane);
#pragma unroll
        for (int nt = 0; nt < 4; nt++)
#pragma unroll
            for (int q = 0; q < 4; q++) h2[nt][q] = fmaxf(h2[nt][q], 0.f);
        conv_frags(h2, fh, fl);

        float o2[2][4];
#pragma unroll
        for (int nt = 0; nt < 2; nt++) {
            float2 bv = __ldg((const float2*)(out2_b + nt * 8 + 2 * (lane & 3)));
            o2[nt][0] = bv.x; o2[nt][1] = bv.y;
            o2[nt][2] = bv.x; o2[nt][3] = bv.y;
        }
#pragma unroll
        for (int kc = 0; kc < 2; kc++)
#pragma unroll
            for (int nt = 0; nt < 2; nt++) {
                int wi = (nt * 8 + (lane >> 2)) * 17 + kc * 8 + (lane & 3);
                uint32_t b0h = hw[1088 + wi], b1h = hw[1088 + wi + 4];
                uint32_t b0l = hw[1632 + wi], b1l = hw[1632 + wi + 4];
                mma16816(o2[nt], fh[kc], b0h, b1h);
                mma16816(o2[nt], fh[kc], b0l, b1l);
                mma16816(o2[nt], fl[kc], b0h, b1h);
            }
        float* op = out + (size_t)bt * 2048;
#pragma unroll
        for (int nt = 0; nt < 2; nt++)
#pragma unroll
            for (int rg = 0; rg < 2; rg++)
                *(float2*)(op + (size_t)(row0 + (lane >> 2) + rg * 8) * 16 +
                           nt * 8 + 2 * (lane & 3)) =
                    make_float2(o2[nt][rg * 2], o2[nt][rg * 2 + 1]);
    }
}

// ---------------------------------------------------------------------------
extern "C" void kernel_launch(void* const* d_in, const int* in_sizes, int n_in,
                              void* d_out, int out_size) {
    const float* X = (const float*)d_in[0];
    const float* A = (const float*)d_in[1];
    const float* in_w = (const float*)d_in[2];
    const float* in_b = (const float*)d_in[3];
    const float* ct_w = (const float*)d_in[4];
    const float* ct_b = (const float*)d_in[5];
    const float* cs_w = (const float*)d_in[6];
    const float* cs_b = (const float*)d_in[7];
    const float* gcn_w = (const float*)d_in[8];
    const float* gcn_b = (const float*)d_in[9];
    const float* res_w = (const float*)d_in[10];
    const float* res_b = (const float*)d_in[11];
    const float* skip_w = (const float*)d_in[12];
    const float* skip_b = (const float*)d_in[13];
    const float* out1_w = (const float*)d_in[14];
    const float* out1_b = (const float*)d_in[15];
    const float* out2_w = (const float*)d_in[16];
    const float* out2_b = (const float*)d_in[17];
    float* out = (float*)d_out;

    cudaFuncSetAttribute(k_conv_t, cudaFuncAttributeMaxDynamicSharedMemorySize,
                         K2_SMEM);
    cudaFuncSetAttribute(k_layers_f, cudaFuncAttributeMaxDynamicSharedMemorySize,
                         K3_SMEM);

    k_inproj<<<8192, 256>>>(X, in_w, in_b);
    k_conv_t<<<1024, 512, K2_SMEM>>>(ct_w, ct_b, cs_w, cs_b);
    k_layers_f<<<4096, 256, K3_SMEM>>>(A, gcn_w, gcn_b, res_w, res_b, skip_w,
                                       skip_b, out1_w, out1_b, out2_w, out2_b,
                                       out);
}

// round 12
// speedup vs baseline: 2.2986x; 1.0311x over previous
#include <cuda_runtime.h>
#include <cuda_bf16.h>
#include <math.h>
#include <stdint.h>

// Problem constants: B=8, T=512, N=128, F=16, H=32, L=4
#define BTNH_ 16777216ull   // 8*512*128*32

// Scratch (allocation-free: static device global)
__device__ float g_tcn[4ull * 16777216ull];  // [l][b][t][n][o]

// ====================== common helpers ======================
__device__ __forceinline__ uint32_t smem_u32(const void* p) {
    uint32_t a;
    asm("{ .reg .u64 t; cvta.to.shared.u64 t, %1; cvt.u32.u64 %0, t; }"
        : "=r"(a) : "l"(p));
    return a;
}
__device__ __forceinline__ void ldmat4(uint32_t r[4], uint32_t addr) {
    asm volatile("ldmatrix.sync.aligned.m8n8.x4.shared.b16 {%0,%1,%2,%3}, [%4];"
                 : "=r"(r[0]), "=r"(r[1]), "=r"(r[2]), "=r"(r[3]) : "r"(addr));
}
__device__ __forceinline__ void mma16816(float d[4], const uint32_t a[4],
                                         uint32_t b0, uint32_t b1) {
    asm volatile(
        "mma.sync.aligned.m16n8k16.row.col.f32.bf16.bf16.f32 "
        "{%0,%1,%2,%3}, {%4,%5,%6,%7}, {%8,%9}, {%0,%1,%2,%3};"
        : "+f"(d[0]), "+f"(d[1]), "+f"(d[2]), "+f"(d[3])
        : "r"(a[0]), "r"(a[1]), "r"(a[2]), "r"(a[3]), "r"(b0), "r"(b1));
}
__device__ __forceinline__ uint32_t pack_bf16(__nv_bfloat16 lo, __nv_bfloat16 hi) {
    return (uint32_t)__bfloat16_as_ushort(lo) |
           ((uint32_t)__bfloat16_as_ushort(hi) << 16);
}
__device__ __forceinline__ void split2(float v0, float v1, uint32_t& hw,
                                       uint32_t& lw) {
    __nv_bfloat16 h0 = __float2bfloat16(v0), h1 = __float2bfloat16(v1);
    hw = pack_bf16(h0, h1);
    lw = pack_bf16(__float2bfloat16(v0 - __bfloat162float(h0)),
                   __float2bfloat16(v1 - __bfloat162float(h1)));
}

// ---------------------------------------------------------------------------
// K2: fused input-proj (x_a/x_b) + gated dilated causal convs (HMMA).
// Block bn consumes CONTIGUOUS X rows [bn*512, bn*512+512) (raw-reshape
// semantics).  Proj temp (raw X + in_w cols 0..63 + in_b) lives in the XBL
// region, which is dead until after the proj; x_b-lo words stash in regs.
// ---------------------------------------------------------------------------
#define XAH_B 0
#define XAL_B 41600
#define XBH_B 83200
#define XBL_B 124800
#define WAH_B 166400
#define WAL_B 170624
#define WBH_B 174848
#define WBL_B 179072
#define CBA_B 183296
#define CBB_B 183424
#define K2_SMEM 183552
// proj temp (inside XBL region, 41600 B available)
#define TXI_B XBL_B            // 512*17 floats = 34816 B
#define TWI_B (XBL_B + 34816)  // 16*64 floats  = 4096 B
#define TBI_B (XBL_B + 38912)  // 64 floats     = 256 B

__device__ __forceinline__ void conv_mma(uint32_t sbase, const char* smem,
                                         uint32_t xh, uint32_t xl,
                                         uint32_t wh, uint32_t wl,
                                         const float* __restrict__ bias,
                                         int tau0w, int lane, int d,
                                         float acc[2][4][4]) {
#pragma unroll
    for (int nt = 0; nt < 4; nt++) {
        float bq0 = bias[nt * 8 + (lane & 3) * 2];
        float bq1 = bias[nt * 8 + (lane & 3) * 2 + 1];
#pragma unroll
        for (int mt = 0; mt < 2; mt++) {
            acc[mt][nt][0] = bq0; acc[mt][nt][1] = bq1;
            acc[mt][nt][2] = bq0; acc[mt][nt][3] = bq1;
        }
    }
    int rbase = 8 + tau0w + (lane & 15);
    int chan = (lane >> 4) * 8;
#pragma unroll
    for (int ks = 0; ks < 4; ks++) {
        int tsh = (ks < 2) ? d : 0;
        int ch = chan + (ks & 1) * 16;
        uint32_t arow = (uint32_t)((rbase - tsh) * 80 + ch * 2);
        uint32_t ah[2][4], al[2][4];
        ldmat4(ah[0], sbase + xh + arow);
        ldmat4(ah[1], sbase + xh + arow + 16 * 80);
        ldmat4(al[0], sbase + xl + arow);
        ldmat4(al[1], sbase + xl + arow + 16 * 80);
        int krow = ks * 8 + (lane & 3);
#pragma unroll
        for (int nt = 0; nt < 4; nt++) {
            int wi = krow * 33 + nt * 8 + (lane >> 2);
            uint32_t b0h = *(const uint32_t*)(smem + wh + (size_t)wi * 4);
            uint32_t b1h = *(const uint32_t*)(smem + wh + (size_t)(wi + 132) * 4);
            uint32_t b0l = *(const uint32_t*)(smem + wl + (size_t)wi * 4);
            uint32_t b1l = *(const uint32_t*)(smem + wl + (size_t)(wi + 132) * 4);
#pragma unroll
            for (int mt = 0; mt < 2; mt++) {
                mma16816(acc[mt][nt], ah[mt], b0h, b1h);
                mma16816(acc[mt][nt], ah[mt], b0l, b1l);
                mma16816(acc[mt][nt], al[mt], b0h, b1h);
            }
        }
    }
}

__global__ void __launch_bounds__(512, 1) k_conv_t(const float* __restrict__ X,
                                                   const float* __restrict__ in_w,
                                                   const float* __restrict__ in_b,
                                                   const float* __restrict__ ct_w,
                                                   const float* __restrict__ ct_b,
                                                   const float* __restrict__ cs_w,
                                                   const float* __restrict__ cs_b) {
    extern __shared__ char smem[];
    uint32_t sbase = smem_u32(smem);
    int tid = threadIdx.x, lane = tid & 31, warp = tid >> 5;
    int bn = blockIdx.x, b = bn >> 7, n = bn & 127;
    int tau0w = warp * 32;

    // zero causal pads for XAH/XAL/XBH now (XBL region holds proj temp)
    if (tid < 160) {
        ((uint32_t*)(smem + XAH_B))[tid] = 0;
        ((uint32_t*)(smem + XAL_B))[tid] = 0;
        ((uint32_t*)(smem + XBH_B))[tid] = 0;
    }
    // ---- stage proj temp: raw X rows (contiguous!) + weights + bias ----
    {
        float* sXin = (float*)(smem + TXI_B);
        const float* Xb = X + (size_t)bn * 8192;  // 512 rows x 16 floats
        for (int i = tid; i < 8192; i += 512) {
            int t = i >> 4, f = i & 15;
            sXin[t * 17 + f] = Xb[i];
        }
        float* sWin = (float*)(smem + TWI_B);
        for (int i = tid; i < 1024; i += 512) {
            int f = i >> 6, o = i & 63;
            sWin[i] = in_w[f * 96 + o];
        }
        if (tid < 64) ((float*)(smem + TBI_B))[tid] = in_b[tid];
    }
    __syncthreads();

    // ---- in-kernel proj: thread = (col-pair tcp, tau-group) ----
    uint32_t xbl_st[16];
    {
        const float* sXin = (const float*)(smem + TXI_B);
        const float* sWin = (const float*)(smem + TWI_B);
        const float* sBin = (const float*)(smem + TBI_B);
        int tcp = tid & 15, tt0 = tid >> 4;
        float wa0[16], wa1[16], wb0[16], wb1[16];
#pragma unroll
        for (int f = 0; f < 16; f++) {
            const float* wr = sWin + f * 64 + 2 * tcp;
            wa0[f] = wr[0]; wa1[f] = wr[1];
            wb0[f] = wr[32]; wb1[f] = wr[33];
        }
        float ba0 = sBin[2 * tcp], ba1 = sBin[2 * tcp + 1];
        float bb0 = sBin[32 + 2 * tcp], bb1 = sBin[32 + 2 * tcp + 1];
#pragma unroll 2
        for (int it = 0; it < 16; it++) {
            int tau = it * 32 + tt0;
            const float* xr = sXin + tau * 17;
            float a0 = ba0, a1 = ba1, b0v = bb0, b1v = bb1;
#pragma unroll
            for (int f = 0; f < 16; f++) {
                float xv = xr[f];
                a0 = fmaf(xv, wa0[f], a0);
                a1 = fmaf(xv, wa1[f], a1);
                b0v = fmaf(xv, wb0[f], b0v);
                b1v = fmaf(xv, wb1[f], b1v);
            }
            uint32_t hw, lw;
            uint32_t w = (uint32_t)((8 + tau) * 20 + tcp);
            split2(a0, a1, hw, lw);
            ((uint32_t*)(smem + XAH_B))[w] = hw;
            ((uint32_t*)(smem + XAL_B))[w] = lw;
            split2(b0v, b1v, hw, xbl_st[it]);
            ((uint32_t*)(smem + XBH_B))[w] = hw;
        }
    }
    __syncthreads();  // proj temp reads done -> XBL region reusable
    if (tid < 160) ((uint32_t*)(smem + XBL_B))[tid] = 0;
    {
        int tcp = tid & 15, tt0 = tid >> 4;
#pragma unroll
        for (int it = 0; it < 16; it++) {
            uint32_t w = (uint32_t)((8 + it * 32 + tt0) * 20 + tcp);
            ((uint32_t*)(smem + XBL_B))[w] = xbl_st[it];
        }
    }

    for (int l = 0; l < 4; l++) {
        __syncthreads();
        for (int i = tid; i < 1024; i += 512) {
            int krow = i >> 5, o = i & 31;
            int k0 = krow * 2;
            const float* wa = ct_w + l * 2048 + (k0 >> 5) * 1024 + (k0 & 31) * 32 + o;
            const float* wb = cs_w + l * 2048 + (k0 >> 5) * 1024 + (k0 & 31) * 32 + o;
            uint32_t hw, lw;
            int wi = krow * 33 + o;
            split2(wa[0], wa[32], hw, lw);
            ((uint32_t*)(smem + WAH_B))[wi] = hw;
            ((uint32_t*)(smem + WAL_B))[wi] = lw;
            split2(wb[0], wb[32], hw, lw);
            ((uint32_t*)(smem + WBH_B))[wi] = hw;
            ((uint32_t*)(smem + WBL_B))[wi] = lw;
        }
        if (tid < 32) {
            ((float*)(smem + CBA_B))[tid] = ct_b[l * 32 + tid];
            ((float*)(smem + CBB_B))[tid] = cs_b[l * 32 + tid];
        }
        __syncthreads();
        int d = 1 << l;

        float ta[2][4][4];
        conv_mma(sbase, smem, XAH_B, XAL_B, WAH_B, WAL_B,
                 (const float*)(smem + CBA_B), tau0w, lane, d, ta);
#pragma unroll
        for (int mt = 0; mt < 2; mt++)
#pragma unroll
            for (int nt = 0; nt < 4; nt++)
#pragma unroll
                for (int q = 0; q < 4; q++) {
                    float a = ta[mt][nt][q];
                    float t = __expf(-2.f * fabsf(a));
                    float r = (1.f - t) / (1.f + t);
                    ta[mt][nt][q] = copysignf(r, a);
                }
        float sg[2][4][4];
        conv_mma(sbase, smem, XBH_B, XBL_B, WBH_B, WBL_B,
                 (const float*)(smem + CBB_B), tau0w, lane, d, sg);

        float* outl = g_tcn + (size_t)l * BTNH_ + ((size_t)b * 512) * 4096 + n * 32;
#pragma unroll
        for (int mt = 0; mt < 2; mt++)
#pragma unroll
            for (int nt = 0; nt < 4; nt++) {
                float v[4];
#pragma unroll
                for (int q = 0; q < 4; q++) {
                    float s = 1.f / (1.f + __expf(-sg[mt][nt][q]));
                    v[q] = ta[mt][nt][q] * s;
                }
                int r = tau0w + mt * 16 + (lane >> 2);
                int o0 = nt * 8 + (lane & 3) * 2;
                *(float2*)(outl + (size_t)r * 4096 + o0) = make_float2(v[0], v[1]);
                *(float2*)(outl + (size_t)(r + 8) * 4096 + o0) =
                    make_float2(v[2], v[3]);
            }
    }
}

// ---------------------------------------------------------------------------
// K3: fused x_res proj + fully-HMMA layer chain (round-11 core).
// Proj temp (X[b,t,:,:] contiguous 8KB + in_w cols 64..95 + bias) lives in
// the SAH region, dead until A staging.
// ---------------------------------------------------------------------------
#define SAH_B   0         // A hi bf16 [128][136]
#define SAL_B   34816     // A lo
#define SXH_B   69632     // X^T hi bf16 [32 o][136 j]
#define SXL_B   78336
#define WGT_B   87040     // 2 bufs x 6 slots x 544 words
#define K3_SMEM 113152

__device__ __forceinline__ void gemm32(float d[4][4], const uint32_t ah[2][4],
                                       const uint32_t al[2][4],
                                       const uint32_t* __restrict__ wH,
                                       const uint32_t* __restrict__ wL,
                                       int lane) {
#pragma unroll
    for (int kc = 0; kc < 2; kc++)
#pragma unroll
        for (int nt = 0; nt < 4; nt++) {
            int wi = (nt * 8 + (lane >> 2)) * 17 + kc * 8 + (lane & 3);
            uint32_t b0h = wH[wi], b1h = wH[wi + 4];
            uint32_t b0l = wL[wi], b1l = wL[wi + 4];
            mma16816(d[nt], ah[kc], b0h, b1h);
            mma16816(d[nt], ah[kc], b0l, b1l);
            mma16816(d[nt], al[kc], b0h, b1h);
        }
}
__device__ __forceinline__ void conv_frags(const float d[4][4], uint32_t ah[2][4],
                                           uint32_t al[2][4]) {
#pragma unroll
    for (int kc = 0; kc < 2; kc++)
#pragma unroll
        for (int r = 0; r < 4; r++) {
            int nt = 2 * kc + (r >> 1), qs = (r & 1) * 2;
            split2(d[nt][qs], d[nt][qs + 1], ah[kc][r], al[kc][r]);
        }
}
__device__ __forceinline__ void bias_add(float d[4][4],
                                         const float* __restrict__ bptr,
                                         int lane) {
#pragma unroll
    for (int nt = 0; nt < 4; nt++) {
        float2 bv = __ldg((const float2*)(bptr + nt * 8 + 2 * (lane & 3)));
        d[nt][0] += bv.x; d[nt][1] += bv.y;
        d[nt][2] += bv.x; d[nt][3] += bv.y;
    }
}
__device__ __forceinline__ void stage_w(const float* __restrict__ W,
                                        uint32_t* __restrict__ dstH,
                                        uint32_t* __restrict__ dstL, int tid) {
    for (int i = tid; i < 512; i += 256) {
        int o = i >> 4, cp = i & 15;
        float w0 = __ldg(&W[(2 * cp) * 32 + o]);
        float w1 = __ldg(&W[(2 * cp + 1) * 32 + o]);
        uint32_t hw, lw;
        split2(w0, w1, hw, lw);
        int idx = o * 17 + cp;
        dstH[idx] = hw;
        dstL[idx] = lw;
    }
}

__global__ void __launch_bounds__(256, 2) k_layers_f(
    const float* __restrict__ X, const float* __restrict__ in_w,
    const float* __restrict__ in_b, const float* __restrict__ A,
    const float* __restrict__ gcn_w, const float* __restrict__ gcn_b,
    const float* __restrict__ res_w, const float* __restrict__ res_b,
    const float* __restrict__ skip_w, const float* __restrict__ skip_b,
    const float* __restrict__ out1_w, const float* __restrict__ out1_b,
    const float* __restrict__ out2_w, const float* __restrict__ out2_b,
    float* __restrict__ out) {
    extern __shared__ char smem[];
    uint32_t sbase = smem_u32(smem);
    int tid = threadIdx.x;
    int lane = tid & 31;
    int g = tid >> 5;
    int row0 = g * 16;
    int bt = blockIdx.x;
    size_t base = (size_t)bt * 4096;

    // ---- x_res proj: temp in SAH region (dead until A staging) ----
    float xres[4][4];
    {
        float* sXin = (float*)(smem + SAH_B);           // 128*17 floats
        float* sWin = (float*)(smem + SAH_B + 8704);    // 16*32 floats
        float* sBin = (float*)(smem + SAH_B + 10752);   // 32 floats
        const float* Xbt = X + (size_t)bt * 2048;       // contiguous [128][16]
        for (int i = tid; i < 2048; i += 256) {
            int nn = i >> 4, f = i & 15;
            sXin[nn * 17 + f] = Xbt[i];
        }
        for (int i = tid; i < 512; i += 256) {
            int f = i >> 5, o = i & 31;
            sWin[i] = in_w[f * 96 + 64 + o];
        }
        if (tid < 32) sBin[tid] = in_b[64 + tid];
        __syncthreads();
#pragma unroll
        for (int nt = 0; nt < 4; nt++) {
            int oc0 = nt * 8 + 2 * (lane & 3);
            float b0 = sBin[oc0], b1 = sBin[oc0 + 1];
#pragma unroll
            for (int rg = 0; rg < 2; rg++) {
                int ic = row0 + (lane >> 2) + rg * 8;
                const float* xr = sXin + ic * 17;
                float s0 = b0, s1 = b1;
#pragma unroll
                for (int f = 0; f < 16; f++) {
                    float xv = xr[f];
                    s0 = fmaf(xv, sWin[f * 32 + oc0], s0);
                    s1 = fmaf(xv, sWin[f * 32 + oc0 + 1], s1);
                }
                xres[nt][rg * 2] = s0;
                xres[nt][rg * 2 + 1] = s1;
            }
        }
        __syncthreads();  // temp reads done before A staging overwrites
    }

    // ---- stage A bf16 hi/lo (once) ----
    for (int i = tid; i < 4096; i += 256) {
        int row = i >> 5, c4 = (i & 31) * 4;
        float4 v = ((const float4*)A)[i];
        uint32_t* ph = (uint32_t*)(smem + SAH_B + (row * 136 + c4) * 2);
        uint32_t* pl = (uint32_t*)(smem + SAL_B + (row * 136 + c4) * 2);
        uint32_t hw, lw;
        split2(v.x, v.y, hw, lw); ph[0] = hw; pl[0] = lw;
        split2(v.z, v.w, hw, lw); ph[1] = hw; pl[1] = lw;
    }

    // ---- ldmatrix addressing ----
    int lrow = lane & 15, khalf = lane >> 4;
    uint32_t amh_base =
        sbase + SAH_B + (uint32_t)(((row0 + lrow) * 136 + khalf * 8) * 2);
    uint32_t aml_base =
        sbase + SAL_B + (uint32_t)(((row0 + lrow) * 136 + khalf * 8) * 2);
    int bn_row = ((lane >> 4) << 3) + (lane & 7);
    int bk_half = (lane >> 3) & 1;
    uint32_t bh_base =
        sbase + SXH_B + (uint32_t)((bn_row * 136 + bk_half * 8) * 2);
    uint32_t bl_base =
        sbase + SXL_B + (uint32_t)((bn_row * 136 + bk_half * 8) * 2);

    float skip[4][4];
#pragma unroll
    for (int nt = 0; nt < 4; nt++)
#pragma unroll
        for (int q = 0; q < 4; q++) skip[nt][q] = 0.f;

    for (int l = 0; l < 4; l++) {
        // ---- X-split write from xres frags into SXH/SXL ----
#pragma unroll
        for (int nt = 0; nt < 4; nt++)
#pragma unroll
            for (int q = 0; q < 4; q++) {
                int oc = nt * 8 + 2 * (lane & 3) + (q & 1);
                int ic = row0 + (lane >> 2) + (q >> 1) * 8;
                float v = xres[nt][q];
                __nv_bfloat16 hi = __float2bfloat16(v);
                __nv_bfloat16 lo = __float2bfloat16(v - __bfloat162float(hi));
                *(__nv_bfloat16*)(smem + SXH_B + (oc * 136 + ic) * 2) = hi;
                *(__nv_bfloat16*)(smem + SXL_B + (oc * 136 + ic) * 2) = lo;
            }
        // ---- stage this layer's weights (double-buffered) ----
        uint32_t* wbuf = (uint32_t*)(smem + WGT_B + (l & 1) * 13056);
        stage_w(gcn_w + l * 1024, wbuf, wbuf + 544, tid);
        stage_w(skip_w + l * 1024, wbuf + 1088, wbuf + 1632, tid);
        stage_w(res_w + l * 1024, wbuf + 2176, wbuf + 2720, tid);
        __syncthreads();  // (1) X-split + weights (+ first-iter A) visible

        // ---- A-mix MMA: acc = A @ X (3-pass split) ----
        float acc[4][4];
#pragma unroll
        for (int nt = 0; nt < 4; nt++)
#pragma unroll
            for (int q = 0; q < 4; q++) acc[nt][q] = 0.f;
#pragma unroll
        for (int ks = 0; ks < 8; ks++) {
            uint32_t kb = (uint32_t)(ks * 32);
            uint32_t ah[4], al[4], bh[2][4], bl[2][4];
            ldmat4(ah, amh_base + kb);
            ldmat4(al, aml_base + kb);
            ldmat4(bh[0], bh_base + kb);
            ldmat4(bh[1], bh_base + 16 * 272 + kb);
            ldmat4(bl[0], bl_base + kb);
            ldmat4(bl[1], bl_base + 16 * 272 + kb);
#pragma unroll
            for (int nt = 0; nt < 4; nt++) {
                uint32_t b0h = bh[nt >> 1][(nt & 1) * 2];
                uint32_t b1h = bh[nt >> 1][(nt & 1) * 2 + 1];
                uint32_t b0l = bl[nt >> 1][(nt & 1) * 2];
                uint32_t b1l = bl[nt >> 1][(nt & 1) * 2 + 1];
                mma16816(acc[nt], ah, b0h, b1h);
                mma16816(acc[nt], ah, b0l, b1l);
                mma16816(acc[nt], al, b0h, b1h);
            }
        }
        __syncthreads();  // (2) ldmatrix reads done

        // ---- gcn: h = AX @ gcn_w + gcn_b + tcn ----
        uint32_t fh[2][4], fl[2][4];
        conv_frags(acc, fh, fl);
        float h[4][4];
#pragma unroll
        for (int nt = 0; nt < 4; nt++) {
            float2 bv = __ldg((const float2*)(gcn_b + l * 32 + nt * 8 +
                                              2 * (lane & 3)));
            h[nt][0] = bv.x; h[nt][1] = bv.y;
            h[nt][2] = bv.x; h[nt][3] = bv.y;
        }
        gemm32(h, fh, fl, wbuf, wbuf + 544, lane);
        {
            const float* tcnp = g_tcn + (size_t)l * BTNH_ + base;
#pragma unroll
            for (int nt = 0; nt < 4; nt++)
#pragma unroll
                for (int rg = 0; rg < 2; rg++) {
                    float2 tv = *(const float2*)(tcnp +
                        (size_t)(row0 + (lane >> 2) + rg * 8) * 32 + nt * 8 +
                        2 * (lane & 3));
                    h[nt][rg * 2] += tv.x;
                    h[nt][rg * 2 + 1] += tv.y;
                }
        }
        // ---- skip += h @ skip_w + b ;  xres += h @ res_w + b ----
        conv_frags(h, fh, fl);
        bias_add(skip, skip_b + l * 32, lane);
        gemm32(skip, fh, fl, wbuf + 1088, wbuf + 1632, lane);
        bias_add(xres, res_b + l * 32, lane);
        gemm32(xres, fh, fl, wbuf + 2176, wbuf + 2720, lane);
    }

    // ---- head ----
    {
        uint32_t* hw = (uint32_t*)(smem + WGT_B);
        stage_w(out1_w, hw, hw + 544, tid);
        for (int i = tid; i < 256; i += 256) {
            int o = i >> 4, cp = i & 15;
            float w0 = __ldg(&out2_w[(2 * cp) * 16 + o]);
            float w1 = __ldg(&out2_w[(2 * cp + 1) * 16 + o]);
            uint32_t hwv, lwv;
            split2(w0, w1, hwv, lwv);
            int idx = o * 17 + cp;
            hw[1088 + idx] = hwv;
            hw[1632 + idx] = lwv;
        }
        __syncthreads();

        uint32_t fh[2][4], fl[2][4];
#pragma unroll
        for (int nt = 0; nt < 4; nt++)
#pragma unroll
            for (int q = 0; q < 4; q++) skip[nt][q] = fmaxf(skip[nt][q], 0.f);
        conv_frags(skip, fh, fl);
        float h2[4][4];
#pragma unroll
        for (int nt = 0; nt < 4; nt++) {
            float2 bv = __ldg((const float2*)(out1_b + nt * 8 + 2 * (lane & 3)));
            h2[nt][0] = bv.x; h2[nt][1] = bv.y;
            h2[nt][2] = bv.x; h2[nt][3] = bv.y;
        }
        gemm32(h2, fh, fl, hw, hw + 544, lane);
#pragma unroll
        for (int nt = 0; nt < 4; nt++)
#pragma unroll
            for (int q = 0; q < 4; q++) h2[nt][q] = fmaxf(h2[nt][q], 0.f);
        conv_frags(h2, fh, fl);

        float o2[2][4];
#pragma unroll
        for (int nt = 0; nt < 2; nt++) {
            float2 bv = __ldg((const float2*)(out2_b + nt * 8 + 2 * (lane & 3)));
            o2[nt][0] = bv.x; o2[nt][1] = bv.y;
            o2[nt][2] = bv.x; o2[nt][3] = bv.y;
        }
#pragma unroll
        for (int kc = 0; kc < 2; kc++)
#pragma unroll
            for (int nt = 0; nt < 2; nt++) {
                int wi = (nt * 8 + (lane >> 2)) * 17 + kc * 8 + (lane & 3);
                uint32_t b0h = hw[1088 + wi], b1h = hw[1088 + wi + 4];
                uint32_t b0l = hw[1632 + wi], b1l = hw[1632 + wi + 4];
                mma16816(o2[nt], fh[kc], b0h, b1h);
                mma16816(o2[nt], fh[kc], b0l, b1l);
                mma16816(o2[nt], fl[kc], b0h, b1h);
            }
        float* op = out + (size_t)bt * 2048;
#pragma unroll
        for (int nt = 0; nt < 2; nt++)
#pragma unroll
            for (int rg = 0; rg < 2; rg++)
                *(float2*)(op + (size_t)(row0 + (lane >> 2) + rg * 8) * 16 +
                           nt * 8 + 2 * (lane & 3)) =
                    make_float2(o2[nt][rg * 2], o2[nt][rg * 2 + 1]);
    }
}

// ---------------------------------------------------------------------------
extern "C" void kernel_launch(void* const* d_in, const int* in_sizes, int n_in,
                              void* d_out, int out_size) {
    const float* X = (const float*)d_in[0];
    const float* A = (const float*)d_in[1];
    const float* in_w = (const float*)d_in[2];
    const float* in_b = (const float*)d_in[3];
    const float* ct_w = (const float*)d_in[4];
    const float* ct_b = (const float*)d_in[5];
    const float* cs_w = (const float*)d_in[6];
    const float* cs_b = (const float*)d_in[7];
    const float* gcn_w = (const float*)d_in[8];
    const float* gcn_b = (const float*)d_in[9];
    const float* res_w = (const float*)d_in[10];
    const float* res_b = (const float*)d_in[11];
    const float* skip_w = (const float*)d_in[12];
    const float* skip_b = (const float*)d_in[13];
    const float* out1_w = (const float*)d_in[14];
    const float* out1_b = (const float*)d_in[15];
    const float* out2_w = (const float*)d_in[16];
    const float* out2_b = (const float*)d_in[17];
    float* out = (float*)d_out;

    cudaFuncSetAttribute(k_conv_t, cudaFuncAttributeMaxDynamicSharedMemorySize,
                         K2_SMEM);
    cudaFuncSetAttribute(k_layers_f, cudaFuncAttributeMaxDynamicSharedMemorySize,
                         K3_SMEM);

    k_conv_t<<<1024, 512, K2_SMEM>>>(X, in_w, in_b, ct_w, ct_b, cs_w, cs_b);
    k_layers_f<<<4096, 256, K3_SMEM>>>(X, in_w, in_b, A, gcn_w, gcn_b, res_w,
                                       res_b, skip_w, skip_b, out1_w, out1_b,
                                       out2_w, out2_b, out);
}

// round 13
// speedup vs baseline: 2.5480x; 1.1085x over previous
#include <cuda_runtime.h>
#include <cuda_bf16.h>
#include <math.h>
#include <stdint.h>

// Problem constants: B=8, T=512, N=128, F=16, H=32, L=4
#define BTNH_ 16777216ull   // 8*512*128*32

// Scratch (allocation-free: static device global)
__device__ float g_tcn[4ull * 16777216ull];  // [l][b][t][n][o]

// ====================== common helpers ======================
__device__ __forceinline__ uint32_t smem_u32(const void* p) {
    uint32_t a;
    asm("{ .reg .u64 t; cvta.to.shared.u64 t, %1; cvt.u32.u64 %0, t; }"
        : "=r"(a) : "l"(p));
    return a;
}
__device__ __forceinline__ void ldmat4(uint32_t r[4], uint32_t addr) {
    asm volatile("ldmatrix.sync.aligned.m8n8.x4.shared.b16 {%0,%1,%2,%3}, [%4];"
                 : "=r"(r[0]), "=r"(r[1]), "=r"(r[2]), "=r"(r[3]) : "r"(addr));
}
__device__ __forceinline__ void mma16816(float d[4], const uint32_t a[4],
                                         uint32_t b0, uint32_t b1) {
    asm volatile(
        "mma.sync.aligned.m16n8k16.row.col.f32.bf16.bf16.f32 "
        "{%0,%1,%2,%3}, {%4,%5,%6,%7}, {%8,%9}, {%0,%1,%2,%3};"
        : "+f"(d[0]), "+f"(d[1]), "+f"(d[2]), "+f"(d[3])
        : "r"(a[0]), "r"(a[1]), "r"(a[2]), "r"(a[3]), "r"(b0), "r"(b1));
}
__device__ __forceinline__ uint32_t pack_bf16(__nv_bfloat16 lo, __nv_bfloat16 hi) {
    return (uint32_t)__bfloat16_as_ushort(lo) |
           ((uint32_t)__bfloat16_as_ushort(hi) << 16);
}
__device__ __forceinline__ void split2(float v0, float v1, uint32_t& hw,
                                       uint32_t& lw) {
    __nv_bfloat16 h0 = __float2bfloat16(v0), h1 = __float2bfloat16(v1);
    hw = pack_bf16(h0, h1);
    lw = pack_bf16(__float2bfloat16(v0 - __bfloat162float(h0)),
                   __float2bfloat16(v1 - __bfloat162float(h1)));
}

// ---------------------------------------------------------------------------
// K2: fused input-proj (x_a/x_b) + gated dilated causal convs (HMMA).
// Conv weights now in lane-keyed frag layout: entry (ks,nt,lane) -> uint2
// {word(ks*8+c, o), word(ks*8+c+4, o)}, c=lane&3, o=nt*8+(lane>>2),
// word(krow,o) = pack(W[2krow][o], W[2krow+1][o]).  Read = 1 LDS.64,
// conflict-free (was 4 LDS.32 at ~4-way conflict).
// ---------------------------------------------------------------------------
#define XAH_B 0
#define XAL_B 41600
#define XBH_B 83200
#define XBL_B 124800
#define WAH_B 166400   // 512 uint2 = 4096 B per half
#define WAL_B 170496
#define WBH_B 174592
#define WBL_B 178688
#define CBA_B 182784
#define CBB_B 182912
#define K2_SMEM 183040
// proj temp (inside XBL region, 41600 B available)
#define TXI_B XBL_B            // 512*17 floats = 34816 B
#define TWI_B (XBL_B + 34816)  // 16*64 floats  = 4096 B
#define TBI_B (XBL_B + 38912)  // 64 floats     = 256 B

__device__ __forceinline__ void conv_mma(uint32_t sbase, const char* smem,
                                         uint32_t xh, uint32_t xl,
                                         uint32_t wh, uint32_t wl,
                                         const float* __restrict__ bias,
                                         int tau0w, int lane, int d,
                                         float acc[2][4][4]) {
#pragma unroll
    for (int nt = 0; nt < 4; nt++) {
        float bq0 = bias[nt * 8 + (lane & 3) * 2];
        float bq1 = bias[nt * 8 + (lane & 3) * 2 + 1];
#pragma unroll
        for (int mt = 0; mt < 2; mt++) {
            acc[mt][nt][0] = bq0; acc[mt][nt][1] = bq1;
            acc[mt][nt][2] = bq0; acc[mt][nt][3] = bq1;
        }
    }
    const uint2* wH2 = (const uint2*)(smem + wh);
    const uint2* wL2 = (const uint2*)(smem + wl);
    int rbase = 8 + tau0w + (lane & 15);
    int chan = (lane >> 4) * 8;
#pragma unroll
    for (int ks = 0; ks < 4; ks++) {
        int tsh = (ks < 2) ? d : 0;
        int ch = chan + (ks & 1) * 16;
        uint32_t arow = (uint32_t)((rbase - tsh) * 80 + ch * 2);
        uint32_t ah[2][4], al[2][4];
        ldmat4(ah[0], sbase + xh + arow);
        ldmat4(ah[1], sbase + xh + arow + 16 * 80);
        ldmat4(al[0], sbase + xl + arow);
        ldmat4(al[1], sbase + xl + arow + 16 * 80);
#pragma unroll
        for (int nt = 0; nt < 4; nt++) {
            uint2 h2 = wH2[(ks * 4 + nt) * 32 + lane];
            uint2 l2 = wL2[(ks * 4 + nt) * 32 + lane];
#pragma unroll
            for (int mt = 0; mt < 2; mt++) {
                mma16816(acc[mt][nt], ah[mt], h2.x, h2.y);
                mma16816(acc[mt][nt], ah[mt], l2.x, l2.y);
                mma16816(acc[mt][nt], al[mt], h2.x, h2.y);
            }
        }
    }
}

__global__ void __launch_bounds__(512, 1) k_conv_t(const float* __restrict__ X,
                                                   const float* __restrict__ in_w,
                                                   const float* __restrict__ in_b,
                                                   const float* __restrict__ ct_w,
                                                   const float* __restrict__ ct_b,
                                                   const float* __restrict__ cs_w,
                                                   const float* __restrict__ cs_b) {
    extern __shared__ char smem[];
    uint32_t sbase = smem_u32(smem);
    int tid = threadIdx.x, lane = tid & 31, warp = tid >> 5;
    int bn = blockIdx.x, b = bn >> 7, n = bn & 127;
    int tau0w = warp * 32;

    // zero causal pads for XAH/XAL/XBH now (XBL region holds proj temp)
    if (tid < 160) {
        ((uint32_t*)(smem + XAH_B))[tid] = 0;
        ((uint32_t*)(smem + XAL_B))[tid] = 0;
        ((uint32_t*)(smem + XBH_B))[tid] = 0;
    }
    // ---- stage proj temp: raw X rows (contiguous!) + weights + bias ----
    {
        float* sXin = (float*)(smem + TXI_B);
        const float* Xb = X + (size_t)bn * 8192;  // 512 rows x 16 floats
        for (int i = tid; i < 8192; i += 512) {
            int t = i >> 4, f = i & 15;
            sXin[t * 17 + f] = Xb[i];
        }
        float* sWin = (float*)(smem + TWI_B);
        for (int i = tid; i < 1024; i += 512) {
            int f = i >> 6, o = i & 63;
            sWin[i] = in_w[f * 96 + o];
        }
        if (tid < 64) ((float*)(smem + TBI_B))[tid] = in_b[tid];
    }
    __syncthreads();

    // ---- in-kernel proj: thread = (col-pair tcp, tau-group) ----
    uint32_t xbl_st[16];
    {
        const float* sXin = (const float*)(smem + TXI_B);
        const float* sWin = (const float*)(smem + TWI_B);
        const float* sBin = (const float*)(smem + TBI_B);
        int tcp = tid & 15, tt0 = tid >> 4;
        float wa0[16], wa1[16], wb0[16], wb1[16];
#pragma unroll
        for (int f = 0; f < 16; f++) {
            const float* wr = sWin + f * 64 + 2 * tcp;
            wa0[f] = wr[0]; wa1[f] = wr[1];
            wb0[f] = wr[32]; wb1[f] = wr[33];
        }
        float ba0 = sBin[2 * tcp], ba1 = sBin[2 * tcp + 1];
        float bb0 = sBin[32 + 2 * tcp], bb1 = sBin[32 + 2 * tcp + 1];
#pragma unroll 2
        for (int it = 0; it < 16; it++) {
            int tau = it * 32 + tt0;
            const float* xr = sXin + tau * 17;
            float a0 = ba0, a1 = ba1, b0v = bb0, b1v = bb1;
#pragma unroll
            for (int f = 0; f < 16; f++) {
                float xv = xr[f];
                a0 = fmaf(xv, wa0[f], a0);
                a1 = fmaf(xv, wa1[f], a1);
                b0v = fmaf(xv, wb0[f], b0v);
                b1v = fmaf(xv, wb1[f], b1v);
            }
            uint32_t hw, lw;
            uint32_t w = (uint32_t)((8 + tau) * 20 + tcp);
            split2(a0, a1, hw, lw);
            ((uint32_t*)(smem + XAH_B))[w] = hw;
            ((uint32_t*)(smem + XAL_B))[w] = lw;
            split2(b0v, b1v, hw, xbl_st[it]);
            ((uint32_t*)(smem + XBH_B))[w] = hw;
        }
    }
    __syncthreads();  // proj temp reads done -> XBL region reusable
    if (tid < 160) ((uint32_t*)(smem + XBL_B))[tid] = 0;
    {
        int tcp = tid & 15, tt0 = tid >> 4;
#pragma unroll
        for (int it = 0; it < 16; it++) {
            uint32_t w = (uint32_t)((8 + it * 32 + tt0) * 20 + tcp);
            ((uint32_t*)(smem + XBL_B))[w] = xbl_st[it];
        }
    }

    for (int l = 0; l < 4; l++) {
        __syncthreads();
        // stage conv weights into lane-keyed frag layout
        for (int i = tid; i < 1024; i += 512) {
            int krow = i >> 5, o = i & 31;  // o-fastest: coalesced reads
            int k0 = krow * 2;
            const float* wa = ct_w + l * 2048 + (k0 >> 5) * 1024 + (k0 & 31) * 32 + o;
            const float* wb = cs_w + l * 2048 + (k0 >> 5) * 1024 + (k0 & 31) * 32 + o;
            uint32_t hw, lw;
            int ks = krow >> 3, r = krow & 7;
            int e = (ks * 4 + (o >> 3)) * 32 + (((o & 7) << 2) | (r & 3));
            int slot = e * 2 + (r >> 2);
            split2(wa[0], wa[32], hw, lw);
            ((uint32_t*)(smem + WAH_B))[slot] = hw;
            ((uint32_t*)(smem + WAL_B))[slot] = lw;
            split2(wb[0], wb[32], hw, lw);
            ((uint32_t*)(smem + WBH_B))[slot] = hw;
            ((uint32_t*)(smem + WBL_B))[slot] = lw;
        }
        if (tid < 32) {
            ((float*)(smem + CBA_B))[tid] = ct_b[l * 32 + tid];
            ((float*)(smem + CBB_B))[tid] = cs_b[l * 32 + tid];
        }
        __syncthreads();
        int d = 1 << l;

        float ta[2][4][4];
        conv_mma(sbase, smem, XAH_B, XAL_B, WAH_B, WAL_B,
                 (const float*)(smem + CBA_B), tau0w, lane, d, ta);
#pragma unroll
        for (int mt = 0; mt < 2; mt++)
#pragma unroll
            for (int nt = 0; nt < 4; nt++)
#pragma unroll
                for (int q = 0; q < 4; q++) {
                    float a = ta[mt][nt][q];
                    float t = __expf(-2.f * fabsf(a));
                    float r = (1.f - t) / (1.f + t);
                    ta[mt][nt][q] = copysignf(r, a);
                }
        float sg[2][4][4];
        conv_mma(sbase, smem, XBH_B, XBL_B, WBH_B, WBL_B,
                 (const float*)(smem + CBB_B), tau0w, lane, d, sg);

        float* outl = g_tcn + (size_t)l * BTNH_ + ((size_t)b * 512) * 4096 + n * 32;
#pragma unroll
        for (int mt = 0; mt < 2; mt++)
#pragma unroll
            for (int nt = 0; nt < 4; nt++) {
                float v[4];
#pragma unroll
                for (int q = 0; q < 4; q++) {
                    float s = 1.f / (1.f + __expf(-sg[mt][nt][q]));
                    v[q] = ta[mt][nt][q] * s;
                }
                int r = tau0w + mt * 16 + (lane >> 2);
                int o0 = nt * 8 + (lane & 3) * 2;
                *(float2*)(outl + (size_t)r * 4096 + o0) = make_float2(v[0], v[1]);
                *(float2*)(outl + (size_t)(r + 8) * 4096 + o0) =
                    make_float2(v[2], v[3]);
            }
    }
}

// ---------------------------------------------------------------------------
// K3: fused x_res proj + fully-HMMA layer chain.
// gemm weights in lane-keyed frag layout (LDS.64, conflict-free).
// WGT buffer layout (words): gcnH@0 gcnL@512 skipH@1024 skipL@1536
//                            resH@2048 resL@2560; buffer stride 3072 words.
// Head reuses buf0: out1H@0 out1L@512, out2H@1024 out2L@1280.
// ---------------------------------------------------------------------------
#define SAH_B   0         // A hi bf16 [128][136]
#define SAL_B   34816     // A lo
#define SXH_B   69632     // X^T hi bf16 [32 o][136 j]
#define SXL_B   78336
#define WGT_B   87040     // 2 bufs x 3072 words = 24576 B
#define K3_SMEM 111616

__device__ __forceinline__ void gemm32(float d[4][4], const uint32_t ah[2][4],
                                       const uint32_t al[2][4],
                                       const uint2* __restrict__ wH,
                                       const uint2* __restrict__ wL,
                                       int lane) {
#pragma unroll
    for (int kc = 0; kc < 2; kc++)
#pragma unroll
        for (int nt = 0; nt < 4; nt++) {
            uint2 h2 = wH[(kc * 4 + nt) * 32 + lane];
            uint2 l2 = wL[(kc * 4 + nt) * 32 + lane];
            mma16816(d[nt], ah[kc], h2.x, h2.y);
            mma16816(d[nt], ah[kc], l2.x, l2.y);
            mma16816(d[nt], al[kc], h2.x, h2.y);
        }
}
__device__ __forceinline__ void conv_frags(const float d[4][4], uint32_t ah[2][4],
                                           uint32_t al[2][4]) {
#pragma unroll
    for (int kc = 0; kc < 2; kc++)
#pragma unroll
        for (int r = 0; r < 4; r++) {
            int nt = 2 * kc + (r >> 1), qs = (r & 1) * 2;
            split2(d[nt][qs], d[nt][qs + 1], ah[kc][r], al[kc][r]);
        }
}
__device__ __forceinline__ void bias_add(float d[4][4],
                                         const float* __restrict__ bptr,
                                         int lane) {
#pragma unroll
    for (int nt = 0; nt < 4; nt++) {
        float2 bv = __ldg((const float2*)(bptr + nt * 8 + 2 * (lane & 3)));
        d[nt][0] += bv.x; d[nt][1] += bv.y;
        d[nt][2] += bv.x; d[nt][3] += bv.y;
    }
}
// stage 32x32 weight (W[k][o], k-stride 32) into lane-keyed frag layout
__device__ __forceinline__ void stage_w(const float* __restrict__ W,
                                        uint32_t* __restrict__ dstH,
                                        uint32_t* __restrict__ dstL, int tid) {
    for (int i = tid; i < 512; i += 256) {
        int cp = i >> 5, o = i & 31;  // o-fastest: coalesced global reads
        float w0 = __ldg(&W[(2 * cp) * 32 + o]);
        float w1 = __ldg(&W[(2 * cp + 1) * 32 + o]);
        uint32_t hw, lw;
        split2(w0, w1, hw, lw);
        int kc = cp >> 3, r = cp & 7;
        int e = (kc * 4 + (o >> 3)) * 32 + (((o & 7) << 2) | (r & 3));
        int slot = e * 2 + (r >> 2);
        dstH[slot] = hw;
        dstL[slot] = lw;
    }
}

__global__ void __launch_bounds__(256, 2) k_layers_f(
    const float* __restrict__ X, const float* __restrict__ in_w,
    const float* __restrict__ in_b, const float* __restrict__ A,
    const float* __restrict__ gcn_w, const float* __restrict__ gcn_b,
    const float* __restrict__ res_w, const float* __restrict__ res_b,
    const float* __restrict__ skip_w, const float* __restrict__ skip_b,
    const float* __restrict__ out1_w, const float* __restrict__ out1_b,
    const float* __restrict__ out2_w, const float* __restrict__ out2_b,
    float* __restrict__ out) {
    extern __shared__ char smem[];
    uint32_t sbase = smem_u32(smem);
    int tid = threadIdx.x;
    int lane = tid & 31;
    int g = tid >> 5;
    int row0 = g * 16;
    int bt = blockIdx.x;
    size_t base = (size_t)bt * 4096;

    // ---- x_res proj: temp in SAH region (dead until A staging) ----
    float xres[4][4];
    {
        float* sXin = (float*)(smem + SAH_B);           // 128*17 floats
        float* sWin = (float*)(smem + SAH_B + 8704);    // 16*32 floats
        float* sBin = (float*)(smem + SAH_B + 10752);   // 32 floats
        const float* Xbt = X + (size_t)bt * 2048;       // contiguous [128][16]
        for (int i = tid; i < 2048; i += 256) {
            int nn = i >> 4, f = i & 15;
            sXin[nn * 17 + f] = Xbt[i];
        }
        for (int i = tid; i < 512; i += 256) {
            int f = i >> 5, o = i & 31;
            sWin[i] = in_w[f * 96 + 64 + o];
        }
        if (tid < 32) sBin[tid] = in_b[64 + tid];
        __syncthreads();
#pragma unroll
        for (int nt = 0; nt < 4; nt++) {
            int oc0 = nt * 8 + 2 * (lane & 3);
            float b0 = sBin[oc0], b1 = sBin[oc0 + 1];
#pragma unroll
            for (int rg = 0; rg < 2; rg++) {
                int ic = row0 + (lane >> 2) + rg * 8;
                const float* xr = sXin + ic * 17;
                float s0 = b0, s1 = b1;
#pragma unroll
                for (int f = 0; f < 16; f++) {
                    float xv = xr[f];
                    s0 = fmaf(xv, sWin[f * 32 + oc0], s0);
                    s1 = fmaf(xv, sWin[f * 32 + oc0 + 1], s1);
                }
                xres[nt][rg * 2] = s0;
                xres[nt][rg * 2 + 1] = s1;
            }
        }
        __syncthreads();  // temp reads done before A staging overwrites
    }

    // ---- stage A bf16 hi/lo (once) ----
    for (int i = tid; i < 4096; i += 256) {
        int row = i >> 5, c4 = (i & 31) * 4;
        float4 v = ((const float4*)A)[i];
        uint32_t* ph = (uint32_t*)(smem + SAH_B + (row * 136 + c4) * 2);
        uint32_t* pl = (uint32_t*)(smem + SAL_B + (row * 136 + c4) * 2);
        uint32_t hw, lw;
        split2(v.x, v.y, hw, lw); ph[0] = hw; pl[0] = lw;
        split2(v.z, v.w, hw, lw); ph[1] = hw; pl[1] = lw;
    }

    // ---- ldmatrix addressing ----
    int lrow = lane & 15, khalf = lane >> 4;
    uint32_t amh_base =
        sbase + SAH_B + (uint32_t)(((row0 + lrow) * 136 + khalf * 8) * 2);
    uint32_t aml_base =
        sbase + SAL_B + (uint32_t)(((row0 + lrow) * 136 + khalf * 8) * 2);
    int bn_row = ((lane >> 4) << 3) + (lane & 7);
    int bk_half = (lane >> 3) & 1;
    uint32_t bh_base =
        sbase + SXH_B + (uint32_t)((bn_row * 136 + bk_half * 8) * 2);
    uint32_t bl_base =
        sbase + SXL_B + (uint32_t)((bn_row * 136 + bk_half * 8) * 2);

    float skip[4][4];
#pragma unroll
    for (int nt = 0; nt < 4; nt++)
#pragma unroll
        for (int q = 0; q < 4; q++) skip[nt][q] = 0.f;

    for (int l = 0; l < 4; l++) {
        // ---- X-split write from xres frags into SXH/SXL ----
#pragma unroll
        for (int nt = 0; nt < 4; nt++)
#pragma unroll
            for (int q = 0; q < 4; q++) {
                int oc = nt * 8 + 2 * (lane & 3) + (q & 1);
                int ic = row0 + (lane >> 2) + (q >> 1) * 8;
                float v = xres[nt][q];
                __nv_bfloat16 hi = __float2bfloat16(v);
                __nv_bfloat16 lo = __float2bfloat16(v - __bfloat162float(hi));
                *(__nv_bfloat16*)(smem + SXH_B + (oc * 136 + ic) * 2) = hi;
                *(__nv_bfloat16*)(smem + SXL_B + (oc * 136 + ic) * 2) = lo;
            }
        // ---- stage this layer's weights (double-buffered) ----
        uint32_t* wbuf = (uint32_t*)(smem + WGT_B) + (l & 1) * 3072;
        stage_w(gcn_w + l * 1024, wbuf, wbuf + 512, tid);
        stage_w(skip_w + l * 1024, wbuf + 1024, wbuf + 1536, tid);
        stage_w(res_w + l * 1024, wbuf + 2048, wbuf + 2560, tid);
        __syncthreads();  // (1) X-split + weights (+ first-iter A) visible

        // ---- A-mix MMA: acc = A @ X (3-pass split) ----
        float acc[4][4];
#pragma unroll
        for (int nt = 0; nt < 4; nt++)
#pragma unroll
            for (int q = 0; q < 4; q++) acc[nt][q] = 0.f;
#pragma unroll
        for (int ks = 0; ks < 8; ks++) {
            uint32_t kb = (uint32_t)(ks * 32);
            uint32_t ah[4], al[4], bh[2][4], bl[2][4];
            ldmat4(ah, amh_base + kb);
            ldmat4(al, aml_base + kb);
            ldmat4(bh[0], bh_base + kb);
            ldmat4(bh[1], bh_base + 16 * 272 + kb);
            ldmat4(bl[0], bl_base + kb);
            ldmat4(bl[1], bl_base + 16 * 272 + kb);
#pragma unroll
            for (int nt = 0; nt < 4; nt++) {
                uint32_t b0h = bh[nt >> 1][(nt & 1) * 2];
                uint32_t b1h = bh[nt >> 1][(nt & 1) * 2 + 1];
                uint32_t b0l = bl[nt >> 1][(nt & 1) * 2];
                uint32_t b1l = bl[nt >> 1][(nt & 1) * 2 + 1];
                mma16816(acc[nt], ah, b0h, b1h);
                mma16816(acc[nt], ah, b0l, b1l);
                mma16816(acc[nt], al, b0h, b1h);
            }
        }
        __syncthreads();  // (2) ldmatrix reads done

        // ---- gcn: h = AX @ gcn_w + gcn_b + tcn ----
        uint32_t fh[2][4], fl[2][4];
        conv_frags(acc, fh, fl);
        float h[4][4];
#pragma unroll
        for (int nt = 0; nt < 4; nt++) {
            float2 bv = __ldg((const float2*)(gcn_b + l * 32 + nt * 8 +
                                              2 * (lane & 3)));
            h[nt][0] = bv.x; h[nt][1] = bv.y;
            h[nt][2] = bv.x; h[nt][3] = bv.y;
        }
        gemm32(h, fh, fl, (const uint2*)wbuf, (const uint2*)(wbuf + 512), lane);
        {
            const float* tcnp = g_tcn + (size_t)l * BTNH_ + base;
#pragma unroll
            for (int nt = 0; nt < 4; nt++)
#pragma unroll
                for (int rg = 0; rg < 2; rg++) {
                    float2 tv = *(const float2*)(tcnp +
                        (size_t)(row0 + (lane >> 2) + rg * 8) * 32 + nt * 8 +
                        2 * (lane & 3));
                    h[nt][rg * 2] += tv.x;
                    h[nt][rg * 2 + 1] += tv.y;
                }
        }
        // ---- skip += h @ skip_w + b ;  xres += h @ res_w + b ----
        conv_frags(h, fh, fl);
        bias_add(skip, skip_b + l * 32, lane);
        gemm32(skip, fh, fl, (const uint2*)(wbuf + 1024),
               (const uint2*)(wbuf + 1536), lane);
        bias_add(xres, res_b + l * 32, lane);
        gemm32(xres, fh, fl, (const uint2*)(wbuf + 2048),
               (const uint2*)(wbuf + 2560), lane);
    }

    // ---- head ----
    {
        uint32_t* hw = (uint32_t*)(smem + WGT_B);  // buf0: layer-2 reads done
        stage_w(out1_w, hw, hw + 512, tid);
        if (tid < 256) {
            int i = tid;
            int cp = i >> 4, o = i & 15;
            float w0 = __ldg(&out2_w[(2 * cp) * 16 + o]);
            float w1 = __ldg(&out2_w[(2 * cp + 1) * 16 + o]);
            uint32_t hwv, lwv;
            split2(w0, w1, hwv, lwv);
            int kc = cp >> 3, r = cp & 7;
            int e = (kc * 2 + (o >> 3)) * 32 + (((o & 7) << 2) | (r & 3));
            int slot = e * 2 + (r >> 2);
            hw[1024 + slot] = hwv;
            hw[1280 + slot] = lwv;
        }
        __syncthreads();

        uint32_t fh[2][4], fl[2][4];
#pragma unroll
        for (int nt = 0; nt < 4; nt++)
#pragma unroll
            for (int q = 0; q < 4; q++) skip[nt][q] = fmaxf(skip[nt][q], 0.f);
        conv_frags(skip, fh, fl);
        float h2[4][4];
#pragma unroll
        for (int nt = 0; nt < 4; nt++) {
            float2 bv = __ldg((const float2*)(out1_b + nt * 8 + 2 * (lane & 3)));
            h2[nt][0] = bv.x; h2[nt][1] = bv.y;
            h2[nt][2] = bv.x; h2[nt][3] = bv.y;
        }
        gemm32(h2, fh, fl, (const uint2*)hw, (const uint2*)(hw + 512), lane);
#pragma unroll
        for (int nt = 0; nt < 4; nt++)
#pragma unroll
            for (int q = 0; q < 4; q++) h2[nt][q] = fmaxf(h2[nt][q], 0.f);
        conv_frags(h2, fh, fl);

        float o2[2][4];
#pragma unroll
        for (int nt = 0; nt < 2; nt++) {
            float2 bv = __ldg((const float2*)(out2_b + nt * 8 + 2 * (lane & 3)));
            o2[nt][0] = bv.x; o2[nt][1] = bv.y;
            o2[nt][2] = bv.x; o2[nt][3] = bv.y;
        }
        const uint2* w2H = (const uint2*)(hw + 1024);
        const uint2* w2L = (const uint2*)(hw + 1280);
#pragma unroll
        for (int kc = 0; kc < 2; kc++)
#pragma unroll
            for (int nt = 0; nt < 2; nt++) {
                uint2 h2w = w2H[(kc * 2 + nt) * 32 + lane];
                uint2 l2w = w2L[(kc * 2 + nt) * 32 + lane];
                mma16816(o2[nt], fh[kc], h2w.x, h2w.y);
                mma16816(o2[nt], fh[kc], l2w.x, l2w.y);
                mma16816(o2[nt], fl[kc], h2w.x, h2w.y);
            }
        float* op = out + (size_t)bt * 2048;
#pragma unroll
        for (int nt = 0; nt < 2; nt++)
#pragma unroll
            for (int rg = 0; rg < 2; rg++)
                *(float2*)(op + (size_t)(row0 + (lane >> 2) + rg * 8) * 16 +
                           nt * 8 + 2 * (lane & 3)) =
                    make_float2(o2[nt][rg * 2], o2[nt][rg * 2 + 1]);
    }
}

// ---------------------------------------------------------------------------
extern "C" void kernel_launch(void* const* d_in, const int* in_sizes, int n_in,
                              void* d_out, int out_size) {
    const float* X = (const float*)d_in[0];
    const float* A = (const float*)d_in[1];
    const float* in_w = (const float*)d_in[2];
    const float* in_b = (const float*)d_in[3];
    const float* ct_w = (const float*)d_in[4];
    const float* ct_b = (const float*)d_in[5];
    const float* cs_w = (const float*)d_in[6];
    const float* cs_b = (const float*)d_in[7];
    const float* gcn_w = (const float*)d_in[8];
    const float* gcn_b = (const float*)d_in[9];
    const float* res_w = (const float*)d_in[10];
    const float* res_b = (const float*)d_in[11];
    const float* skip_w = (const float*)d_in[12];
    const float* skip_b = (const float*)d_in[13];
    const float* out1_w = (const float*)d_in[14];
    const float* out1_b = (const float*)d_in[15];
    const float* out2_w = (const float*)d_in[16];
    const float* out2_b = (const float*)d_in[17];
    float* out = (float*)d_out;

    cudaFuncSetAttribute(k_conv_t, cudaFuncAttributeMaxDynamicSharedMemorySize,
                         K2_SMEM);
    cudaFuncSetAttribute(k_layers_f, cudaFuncAttributeMaxDynamicSharedMemorySize,
                         K3_SMEM);

    k_conv_t<<<1024, 512, K2_SMEM>>>(X, in_w, in_b, ct_w, ct_b, cs_w, cs_b);
    k_layers_f<<<4096, 256, K3_SMEM>>>(X, in_w, in_b, A, gcn_w, gcn_b, res_w,
                                       res_b, skip_w, skip_b, out1_w, out1_b,
                                       out2_w, out2_b, out);
}

// round 14
// speedup vs baseline: 3.2008x; 1.2562x over previous
#include <cuda_runtime.h>
#include <cuda_bf16.h>
#include <math.h>
#include <stdint.h>

// Problem constants: B=8, T=512, N=128, F=16, H=32, L=4
#define BTNH_ 16777216ull   // 8*512*128*32

// Scratch (allocation-free: static device globals)
__device__ float g_tcn[4ull * 16777216ull];  // [l][b][t][n][o]
// Precomputed constant fragments (filled by k_prep each launch)
__device__ uint32_t g_afragH[8192];  // A frags: [mt8][ks8][lane32][4]
__device__ uint32_t g_afragL[8192];
__device__ uint32_t g_wH32[6912];    // gemm wts: 12x512 + out1@6144 + out2@6656
__device__ uint32_t g_wL32[6912];
__device__ uint32_t g_cwH[8192];     // conv wts: [(l*2+conv)]x1024
__device__ uint32_t g_cwL[8192];

// ====================== common helpers ======================
__device__ __forceinline__ uint32_t smem_u32(const void* p) {
    uint32_t a;
    asm("{ .reg .u64 t; cvta.to.shared.u64 t, %1; cvt.u32.u64 %0, t; }"
        : "=r"(a) : "l"(p));
    return a;
}
__device__ __forceinline__ void ldmat4(uint32_t r[4], uint32_t addr) {
    asm volatile("ldmatrix.sync.aligned.m8n8.x4.shared.b16 {%0,%1,%2,%3}, [%4];"
                 : "=r"(r[0]), "=r"(r[1]), "=r"(r[2]), "=r"(r[3]) : "r"(addr));
}
__device__ __forceinline__ void mma16816(float d[4], const uint32_t a[4],
                                         uint32_t b0, uint32_t b1) {
    asm volatile(
        "mma.sync.aligned.m16n8k16.row.col.f32.bf16.bf16.f32 "
        "{%0,%1,%2,%3}, {%4,%5,%6,%7}, {%8,%9}, {%0,%1,%2,%3};"
        : "+f"(d[0]), "+f"(d[1]), "+f"(d[2]), "+f"(d[3])
        : "r"(a[0]), "r"(a[1]), "r"(a[2]), "r"(a[3]), "r"(b0), "r"(b1));
}
__device__ __forceinline__ uint32_t pack_bf16(__nv_bfloat16 lo, __nv_bfloat16 hi) {
    return (uint32_t)__bfloat16_as_ushort(lo) |
           ((uint32_t)__bfloat16_as_ushort(hi) << 16);
}
__device__ __forceinline__ void split2(float v0, float v1, uint32_t& hw,
                                       uint32_t& lw) {
    __nv_bfloat16 h0 = __float2bfloat16(v0), h1 = __float2bfloat16(v1);
    hw = pack_bf16(h0, h1);
    lw = pack_bf16(__float2bfloat16(v0 - __bfloat162float(h0)),
                   __float2bfloat16(v1 - __bfloat162float(h1)));
}

// ---------------------------------------------------------------------------
// K0: fragment prep — A frags, gemm-weight frags, conv-weight frags.
// Same mapping code as the old per-CTA staging -> bit-identical numerics.
// ---------------------------------------------------------------------------
__global__ void k_prep(const float* __restrict__ A,
                       const float* __restrict__ gcn_w,
                       const float* __restrict__ skip_w,
                       const float* __restrict__ res_w,
                       const float* __restrict__ out1_w,
                       const float* __restrict__ out2_w,
                       const float* __restrict__ ct_w,
                       const float* __restrict__ cs_w) {
    int tid = blockIdx.x * blockDim.x + threadIdx.x;
    int nthr = gridDim.x * blockDim.x;

    // A frags: m16n8k16 A-operand layout, 8 mtiles x 8 ks x 32 lanes x 4 words
    for (int idx = tid; idx < 2048; idx += nthr) {
        int mt = idx >> 8, ks = (idx >> 5) & 7, lane = idx & 31;
        int r = lane >> 2, c = lane & 3;
        int row = mt * 16 + r, k = ks * 16 + 2 * c;
        uint32_t base = (uint32_t)idx * 4;
#pragma unroll
        for (int j = 0; j < 4; j++) {
            int rr = row + (j & 1) * 8;
            int kk = k + (j >> 1) * 8;
            uint32_t hw, lw;
            split2(A[rr * 128 + kk], A[rr * 128 + kk + 1], hw, lw);
            g_afragH[base + j] = hw;
            g_afragL[base + j] = lw;
        }
    }
    // gemm weights: 13 matrices x 512 words (lane-keyed frag layout)
    for (int idx = tid; idx < 6656; idx += nthr) {
        int m = idx >> 9, i = idx & 511;
        const float* W;
        if (m == 12) W = out1_w;
        else {
            int l = m / 3, kind = m % 3;
            W = (kind == 0 ? gcn_w : kind == 1 ? skip_w : res_w) + l * 1024;
        }
        int cp = i >> 5, o = i & 31;
        uint32_t hw, lw;
        split2(W[(2 * cp) * 32 + o], W[(2 * cp + 1) * 32 + o], hw, lw);
        int kc = cp >> 3, r = cp & 7;
        int e = (kc * 4 + (o >> 3)) * 32 + (((o & 7) << 2) | (r & 3));
        int slot = m * 512 + e * 2 + (r >> 2);
        g_wH32[slot] = hw;
        g_wL32[slot] = lw;
    }
    // out2: 256 words at offset 6656
    for (int idx = tid; idx < 256; idx += nthr) {
        int cp = idx >> 4, o = idx & 15;
        uint32_t hw, lw;
        split2(out2_w[(2 * cp) * 16 + o], out2_w[(2 * cp + 1) * 16 + o], hw, lw);
        int kc = cp >> 3, r = cp & 7;
        int e = (kc * 2 + (o >> 3)) * 32 + (((o & 7) << 2) | (r & 3));
        g_wH32[6656 + e * 2 + (r >> 2)] = hw;
        g_wL32[6656 + e * 2 + (r >> 2)] = lw;
    }
    // conv weights: 8 matrices (l*2+conv) x 1024 words
    for (int idx = tid; idx < 8192; idx += nthr) {
        int cv = idx >> 10, i = idx & 1023;
        int l = cv >> 1;
        const float* W = ((cv & 1) ? cs_w : ct_w) + l * 2048;
        int krow = i >> 5, o = i & 31;
        int k0 = krow * 2;
        const float* src = W + (k0 >> 5) * 1024 + (k0 & 31) * 32 + o;
        uint32_t hw, lw;
        split2(src[0], src[32], hw, lw);
        int ks = krow >> 3, r = krow & 7;
        int e = (ks * 4 + (o >> 3)) * 32 + (((o & 7) << 2) | (r & 3));
        int slot = cv * 1024 + e * 2 + (r >> 2);
        g_cwH[slot] = hw;
        g_cwL[slot] = lw;
    }
}

// ---------------------------------------------------------------------------
// K2: fused input-proj (x_a/x_b) + gated dilated causal convs (HMMA).
// Conv weights via __ldg from global frags -> no per-layer staging, no
// per-layer barriers (X buffers read-only across layers).
// ---------------------------------------------------------------------------
#define XAH_B 0
#define XAL_B 41600
#define XBH_B 83200
#define XBL_B 124800
#define K2_SMEM 166400
// proj temp (inside XBL region, 41600 B available)
#define TXI_B XBL_B            // 512*17 floats = 34816 B
#define TWI_B (XBL_B + 34816)  // 16*64 floats  = 4096 B
#define TBI_B (XBL_B + 38912)  // 64 floats     = 256 B

__device__ __forceinline__ void conv_mma(uint32_t sbase,
                                         uint32_t xh, uint32_t xl,
                                         const uint2* __restrict__ wH2,
                                         const uint2* __restrict__ wL2,
                                         const float* __restrict__ bias,
                                         int tau0w, int lane, int d,
                                         float acc[2][4][4]) {
#pragma unroll
    for (int nt = 0; nt < 4; nt++) {
        float2 bv = __ldg((const float2*)(bias + nt * 8 + (lane & 3) * 2));
#pragma unroll
        for (int mt = 0; mt < 2; mt++) {
            acc[mt][nt][0] = bv.x; acc[mt][nt][1] = bv.y;
            acc[mt][nt][2] = bv.x; acc[mt][nt][3] = bv.y;
        }
    }
    int rbase = 8 + tau0w + (lane & 15);
    int chan = (lane >> 4) * 8;
#pragma unroll
    for (int ks = 0; ks < 4; ks++) {
        int tsh = (ks < 2) ? d : 0;
        int ch = chan + (ks & 1) * 16;
        uint32_t arow = (uint32_t)((rbase - tsh) * 80 + ch * 2);
        uint32_t ah[2][4], al[2][4];
        ldmat4(ah[0], sbase + xh + arow);
        ldmat4(ah[1], sbase + xh + arow + 16 * 80);
        ldmat4(al[0], sbase + xl + arow);
        ldmat4(al[1], sbase + xl + arow + 16 * 80);
#pragma unroll
        for (int nt = 0; nt < 4; nt++) {
            uint2 h2 = __ldg(&wH2[(ks * 4 + nt) * 32 + lane]);
            uint2 l2 = __ldg(&wL2[(ks * 4 + nt) * 32 + lane]);
#pragma unroll
            for (int mt = 0; mt < 2; mt++) {
                mma16816(acc[mt][nt], ah[mt], h2.x, h2.y);
                mma16816(acc[mt][nt], ah[mt], l2.x, l2.y);
                mma16816(acc[mt][nt], al[mt], h2.x, h2.y);
            }
        }
    }
}

__global__ void __launch_bounds__(512, 1) k_conv_t(const float* __restrict__ X,
                                                   const float* __restrict__ in_w,
                                                   const float* __restrict__ in_b,
                                                   const float* __restrict__ ct_b,
                                                   const float* __restrict__ cs_b) {
    extern __shared__ char smem[];
    uint32_t sbase = smem_u32(smem);
    int tid = threadIdx.x, lane = tid & 31, warp = tid >> 5;
    int bn = blockIdx.x, b = bn >> 7, n = bn & 127;
    int tau0w = warp * 32;

    // zero causal pads for XAH/XAL/XBH now (XBL region holds proj temp)
    if (tid < 160) {
        ((uint32_t*)(smem + XAH_B))[tid] = 0;
        ((uint32_t*)(smem + XAL_B))[tid] = 0;
        ((uint32_t*)(smem + XBH_B))[tid] = 0;
    }
    // ---- stage proj temp: raw X rows (contiguous!) + weights + bias ----
    {
        float* sXin = (float*)(smem + TXI_B);
        const float* Xb = X + (size_t)bn * 8192;  // 512 rows x 16 floats
        for (int i = tid; i < 8192; i += 512) {
            int t = i >> 4, f = i & 15;
            sXin[t * 17 + f] = Xb[i];
        }
        float* sWin = (float*)(smem + TWI_B);
        for (int i = tid; i < 1024; i += 512) {
            int f = i >> 6, o = i & 63;
            sWin[i] = in_w[f * 96 + o];
        }
        if (tid < 64) ((float*)(smem + TBI_B))[tid] = in_b[tid];
    }
    __syncthreads();

    // ---- in-kernel proj: thread = (col-pair tcp, tau-group) ----
    uint32_t xbl_st[16];
    {
        const float* sXin = (const float*)(smem + TXI_B);
        const float* sWin = (const float*)(smem + TWI_B);
        const float* sBin = (const float*)(smem + TBI_B);
        int tcp = tid & 15, tt0 = tid >> 4;
        float wa0[16], wa1[16], wb0[16], wb1[16];
#pragma unroll
        for (int f = 0; f < 16; f++) {
            const float* wr = sWin + f * 64 + 2 * tcp;
            wa0[f] = wr[0]; wa1[f] = wr[1];
            wb0[f] = wr[32]; wb1[f] = wr[33];
        }
        float ba0 = sBin[2 * tcp], ba1 = sBin[2 * tcp + 1];
        float bb0 = sBin[32 + 2 * tcp], bb1 = sBin[32 + 2 * tcp + 1];
#pragma unroll 2
        for (int it = 0; it < 16; it++) {
            int tau = it * 32 + tt0;
            const float* xr = sXin + tau * 17;
            float a0 = ba0, a1 = ba1, b0v = bb0, b1v = bb1;
#pragma unroll
            for (int f = 0; f < 16; f++) {
                float xv = xr[f];
                a0 = fmaf(xv, wa0[f], a0);
                a1 = fmaf(xv, wa1[f], a1);
                b0v = fmaf(xv, wb0[f], b0v);
                b1v = fmaf(xv, wb1[f], b1v);
            }
            uint32_t hw, lw;
            uint32_t w = (uint32_t)((8 + tau) * 20 + tcp);
            split2(a0, a1, hw, lw);
            ((uint32_t*)(smem + XAH_B))[w] = hw;
            ((uint32_t*)(smem + XAL_B))[w] = lw;
            split2(b0v, b1v, hw, xbl_st[it]);
            ((uint32_t*)(smem + XBH_B))[w] = hw;
        }
    }
    __syncthreads();  // proj temp reads done -> XBL region reusable
    if (tid < 160) ((uint32_t*)(smem + XBL_B))[tid] = 0;
    {
        int tcp = tid & 15, tt0 = tid >> 4;
#pragma unroll
        for (int it = 0; it < 16; it++) {
            uint32_t w = (uint32_t)((8 + it * 32 + tt0) * 20 + tcp);
            ((uint32_t*)(smem + XBL_B))[w] = xbl_st[it];
        }
    }
    __syncthreads();  // XBL staged; layers are barrier-free from here

#pragma unroll 1
    for (int l = 0; l < 4; l++) {
        int d = 1 << l;
        float ta[2][4][4];
        conv_mma(sbase, XAH_B, XAL_B, (const uint2*)(g_cwH + (l * 2) * 1024),
                 (const uint2*)(g_cwL + (l * 2) * 1024), ct_b + l * 32, tau0w,
                 lane, d, ta);
#pragma unroll
        for (int mt = 0; mt < 2; mt++)
#pragma unroll
            for (int nt = 0; nt < 4; nt++)
#pragma unroll
                for (int q = 0; q < 4; q++) {
                    float a = ta[mt][nt][q];
                    float t = __expf(-2.f * fabsf(a));
                    float r = (1.f - t) / (1.f + t);
                    ta[mt][nt][q] = copysignf(r, a);
                }
        float sg[2][4][4];
        conv_mma(sbase, XBH_B, XBL_B, (const uint2*)(g_cwH + (l * 2 + 1) * 1024),
                 (const uint2*)(g_cwL + (l * 2 + 1) * 1024), cs_b + l * 32, tau0w,
                 lane, d, sg);

        float* outl = g_tcn + (size_t)l * BTNH_ + ((size_t)b * 512) * 4096 + n * 32;
#pragma unroll
        for (int mt = 0; mt < 2; mt++)
#pragma unroll
            for (int nt = 0; nt < 4; nt++) {
                float v[4];
#pragma unroll
                for (int q = 0; q < 4; q++) {
                    float s = 1.f / (1.f + __expf(-sg[mt][nt][q]));
                    v[q] = ta[mt][nt][q] * s;
                }
                int r = tau0w + mt * 16 + (lane >> 2);
                int o0 = nt * 8 + (lane & 3) * 2;
                *(float2*)(outl + (size_t)r * 4096 + o0) = make_float2(v[0], v[1]);
                *(float2*)(outl + (size_t)(r + 8) * 4096 + o0) =
                    make_float2(v[2], v[3]);
            }
    }
}

// ---------------------------------------------------------------------------
// K3: fused x_res proj + fully-HMMA layer chain.
// A-operand frags + all weights via __ldg global (L1-resident) -> smem is
// only the X-split buffers (17.4 KB).
// ---------------------------------------------------------------------------
#define SXH_B   0         // X^T hi bf16 [32 o][136 j]
#define SXL_B   8704
#define K3_SMEM 17408

__device__ __forceinline__ void gemm32(float d[4][4], const uint32_t ah[2][4],
                                       const uint32_t al[2][4],
                                       const uint2* __restrict__ wH,
                                       const uint2* __restrict__ wL,
                                       int lane) {
#pragma unroll
    for (int kc = 0; kc < 2; kc++)
#pragma unroll
        for (int nt = 0; nt < 4; nt++) {
            uint2 h2 = __ldg(&wH[(kc * 4 + nt) * 32 + lane]);
            uint2 l2 = __ldg(&wL[(kc * 4 + nt) * 32 + lane]);
            mma16816(d[nt], ah[kc], h2.x, h2.y);
            mma16816(d[nt], ah[kc], l2.x, l2.y);
            mma16816(d[nt], al[kc], h2.x, h2.y);
        }
}
__device__ __forceinline__ void conv_frags(const float d[4][4], uint32_t ah[2][4],
                                           uint32_t al[2][4]) {
#pragma unroll
    for (int kc = 0; kc < 2; kc++)
#pragma unroll
        for (int r = 0; r < 4; r++) {
            int nt = 2 * kc + (r >> 1), qs = (r & 1) * 2;
            split2(d[nt][qs], d[nt][qs + 1], ah[kc][r], al[kc][r]);
        }
}
__device__ __forceinline__ void bias_add(float d[4][4],
                                         const float* __restrict__ bptr,
                                         int lane) {
#pragma unroll
    for (int nt = 0; nt < 4; nt++) {
        float2 bv = __ldg((const float2*)(bptr + nt * 8 + 2 * (lane & 3)));
        d[nt][0] += bv.x; d[nt][1] += bv.y;
        d[nt][2] += bv.x; d[nt][3] += bv.y;
    }
}

__global__ void __launch_bounds__(256, 2) k_layers_f(
    const float* __restrict__ X, const float* __restrict__ in_w,
    const float* __restrict__ in_b, const float* __restrict__ gcn_b,
    const float* __restrict__ res_b, const float* __restrict__ skip_b,
    const float* __restrict__ out1_b, const float* __restrict__ out2_b,
    float* __restrict__ out) {
    extern __shared__ char smem[];
    uint32_t sbase = smem_u32(smem);
    int tid = threadIdx.x;
    int lane = tid & 31;
    int g = tid >> 5;
    int row0 = g * 16;
    int bt = blockIdx.x;
    size_t base = (size_t)bt * 4096;

    // ---- x_res proj: temp in SXH/SXL region (dead until first X-split) ----
    float xres[4][4];
    {
        float* sXin = (float*)(smem);            // 128*17 floats = 8704 B
        float* sWin = (float*)(smem + 8704);     // 16*32 floats  = 2048 B
        float* sBin = (float*)(smem + 10752);    // 32 floats
        const float* Xbt = X + (size_t)bt * 2048;  // contiguous [128][16]
        for (int i = tid; i < 2048; i += 256) {
            int nn = i >> 4, f = i & 15;
            sXin[nn * 17 + f] = Xbt[i];
        }
        for (int i = tid; i < 512; i += 256) {
            int f = i >> 5, o = i & 31;
            sWin[i] = in_w[f * 96 + 64 + o];
        }
        if (tid < 32) sBin[tid] = in_b[64 + tid];
        __syncthreads();
#pragma unroll
        for (int nt = 0; nt < 4; nt++) {
            int oc0 = nt * 8 + 2 * (lane & 3);
            float b0 = sBin[oc0], b1 = sBin[oc0 + 1];
#pragma unroll
            for (int rg = 0; rg < 2; rg++) {
                int ic = row0 + (lane >> 2) + rg * 8;
                const float* xr = sXin + ic * 17;
                float s0 = b0, s1 = b1;
#pragma unroll
                for (int f = 0; f < 16; f++) {
                    float xv = xr[f];
                    s0 = fmaf(xv, sWin[f * 32 + oc0], s0);
                    s1 = fmaf(xv, sWin[f * 32 + oc0 + 1], s1);
                }
                xres[nt][rg * 2] = s0;
                xres[nt][rg * 2 + 1] = s1;
            }
        }
        __syncthreads();  // temp reads done before X-split overwrites
    }

    // ---- B-operand ldmatrix addressing (X-split smem) ----
    int bn_row = ((lane >> 4) << 3) + (lane & 7);
    int bk_half = (lane >> 3) & 1;
    uint32_t bh_base =
        sbase + SXH_B + (uint32_t)((bn_row * 136 + bk_half * 8) * 2);
    uint32_t bl_base =
        sbase + SXL_B + (uint32_t)((bn_row * 136 + bk_half * 8) * 2);

    float skip[4][4];
#pragma unroll
    for (int nt = 0; nt < 4; nt++)
#pragma unroll
        for (int q = 0; q < 4; q++) skip[nt][q] = 0.f;

    const uint4* aH4 = (const uint4*)g_afragH;
    const uint4* aL4 = (const uint4*)g_afragL;

    for (int l = 0; l < 4; l++) {
        // ---- X-split write from xres frags into SXH/SXL ----
#pragma unroll
        for (int nt = 0; nt < 4; nt++)
#pragma unroll
            for (int q = 0; q < 4; q++) {
                int oc = nt * 8 + 2 * (lane & 3) + (q & 1);
                int ic = row0 + (lane >> 2) + (q >> 1) * 8;
                float v = xres[nt][q];
                __nv_bfloat16 hi = __float2bfloat16(v);
                __nv_bfloat16 lo = __float2bfloat16(v - __bfloat162float(hi));
                *(__nv_bfloat16*)(smem + SXH_B + (oc * 136 + ic) * 2) = hi;
                *(__nv_bfloat16*)(smem + SXL_B + (oc * 136 + ic) * 2) = lo;
            }
        __syncthreads();  // (1) X-split visible

        // ---- A-mix MMA: acc = A @ X (3-pass split); A frags via LDG ----
        float acc[4][4];
#pragma unroll
        for (int nt = 0; nt < 4; nt++)
#pragma unroll
            for (int q = 0; q < 4; q++) acc[nt][q] = 0.f;
#pragma unroll
        for (int ks = 0; ks < 8; ks++) {
            uint32_t kb = (uint32_t)(ks * 32);
            uint32_t ah[4], al[4], bh[2][4], bl[2][4];
            uint4 va = __ldg(&aH4[(g * 8 + ks) * 32 + lane]);
            uint4 vl = __ldg(&aL4[(g * 8 + ks) * 32 + lane]);
            ah[0] = va.x; ah[1] = va.y; ah[2] = va.z; ah[3] = va.w;
            al[0] = vl.x; al[1] = vl.y; al[2] = vl.z; al[3] = vl.w;
            ldmat4(bh[0], bh_base + kb);
            ldmat4(bh[1], bh_base + 16 * 272 + kb);
            ldmat4(bl[0], bl_base + kb);
            ldmat4(bl[1], bl_base + 16 * 272 + kb);
#pragma unroll
            for (int nt = 0; nt < 4; nt++) {
                uint32_t b0h = bh[nt >> 1][(nt & 1) * 2];
                uint32_t b1h = bh[nt >> 1][(nt & 1) * 2 + 1];
                uint32_t b0l = bl[nt >> 1][(nt & 1) * 2];
                uint32_t b1l = bl[nt >> 1][(nt & 1) * 2 + 1];
                mma16816(acc[nt], ah, b0h, b1h);
                mma16816(acc[nt], ah, b0l, b1l);
                mma16816(acc[nt], al, b0h, b1h);
            }
        }
        __syncthreads();  // (2) ldmatrix reads done (next layer rewrites X)

        // ---- gcn: h = AX @ gcn_w + gcn_b + tcn ----
        uint32_t fh[2][4], fl[2][4];
        conv_frags(acc, fh, fl);
        float h[4][4];
#pragma unroll
        for (int nt = 0; nt < 4; nt++) {
            float2 bv = __ldg((const float2*)(gcn_b + l * 32 + nt * 8 +
                                              2 * (lane & 3)));
            h[nt][0] = bv.x; h[nt][1] = bv.y;
            h[nt][2] = bv.x; h[nt][3] = bv.y;
        }
        gemm32(h, fh, fl, (const uint2*)(g_wH32 + (l * 3) * 512),
               (const uint2*)(g_wL32 + (l * 3) * 512), lane);
        {
            const float* tcnp = g_tcn + (size_t)l * BTNH_ + base;
#pragma unroll
            for (int nt = 0; nt < 4; nt++)
#pragma unroll
                for (int rg = 0; rg < 2; rg++) {
                    float2 tv = *(const float2*)(tcnp +
                        (size_t)(row0 + (lane >> 2) + rg * 8) * 32 + nt * 8 +
                        2 * (lane & 3));
                    h[nt][rg * 2] += tv.x;
                    h[nt][rg * 2 + 1] += tv.y;
                }
        }
        // ---- skip += h @ skip_w + b ;  xres += h @ res_w + b ----
        conv_frags(h, fh, fl);
        bias_add(skip, skip_b + l * 32, lane);
        gemm32(skip, fh, fl, (const uint2*)(g_wH32 + (l * 3 + 1) * 512),
               (const uint2*)(g_wL32 + (l * 3 + 1) * 512), lane);
        bias_add(xres, res_b + l * 32, lane);
        gemm32(xres, fh, fl, (const uint2*)(g_wH32 + (l * 3 + 2) * 512),
               (const uint2*)(g_wL32 + (l * 3 + 2) * 512), lane);
    }

    // ---- head (all operands in regs/global; no barriers) ----
    {
        uint32_t fh[2][4], fl[2][4];
#pragma unroll
        for (int nt = 0; nt < 4; nt++)
#pragma unroll
            for (int q = 0; q < 4; q++) skip[nt][q] = fmaxf(skip[nt][q], 0.f);
        conv_frags(skip, fh, fl);
        float h2[4][4];
#pragma unroll
        for (int nt = 0; nt < 4; nt++) {
            float2 bv = __ldg((const float2*)(out1_b + nt * 8 + 2 * (lane & 3)));
            h2[nt][0] = bv.x; h2[nt][1] = bv.y;
            h2[nt][2] = bv.x; h2[nt][3] = bv.y;
        }
        gemm32(h2, fh, fl, (const uint2*)(g_wH32 + 6144),
               (const uint2*)(g_wL32 + 6144), lane);
#pragma unroll
        for (int nt = 0; nt < 4; nt++)
#pragma unroll
            for (int q = 0; q < 4; q++) h2[nt][q] = fmaxf(h2[nt][q], 0.f);
        conv_frags(h2, fh, fl);

        float o2[2][4];
#pragma unroll
        for (int nt = 0; nt < 2; nt++) {
            float2 bv = __ldg((const float2*)(out2_b + nt * 8 + 2 * (lane & 3)));
            o2[nt][0] = bv.x; o2[nt][1] = bv.y;
            o2[nt][2] = bv.x; o2[nt][3] = bv.y;
        }
        const uint2* w2H = (const uint2*)(g_wH32 + 6656);
        const uint2* w2L = (const uint2*)(g_wL32 + 6656);
#pragma unroll
        for (int kc = 0; kc < 2; kc++)
#pragma unroll
            for (int nt = 0; nt < 2; nt++) {
                uint2 h2w = __ldg(&w2H[(kc * 2 + nt) * 32 + lane]);
                uint2 l2w = __ldg(&w2L[(kc * 2 + nt) * 32 + lane]);
                mma16816(o2[nt], fh[kc], h2w.x, h2w.y);
                mma16816(o2[nt], fh[kc], l2w.x, l2w.y);
                mma16816(o2[nt], fl[kc], h2w.x, h2w.y);
            }
        float* op = out + (size_t)bt * 2048;
#pragma unroll
        for (int nt = 0; nt < 2; nt++)
#pragma unroll
            for (int rg = 0; rg < 2; rg++)
                *(float2*)(op + (size_t)(row0 + (lane >> 2) + rg * 8) * 16 +
                           nt * 8 + 2 * (lane & 3)) =
                    make_float2(o2[nt][rg * 2], o2[nt][rg * 2 + 1]);
    }
}

// ---------------------------------------------------------------------------
extern "C" void kernel_launch(void* const* d_in, const int* in_sizes, int n_in,
                              void* d_out, int out_size) {
    const float* X = (const float*)d_in[0];
    const float* A = (const float*)d_in[1];
    const float* in_w = (const float*)d_in[2];
    const float* in_b = (const float*)d_in[3];
    const float* ct_w = (const float*)d_in[4];
    const float* ct_b = (const float*)d_in[5];
    const float* cs_w = (const float*)d_in[6];
    const float* cs_b = (const float*)d_in[7];
    const float* gcn_w = (const float*)d_in[8];
    const float* gcn_b = (const float*)d_in[9];
    const float* res_w = (const float*)d_in[10];
    const float* res_b = (const float*)d_in[11];
    const float* skip_w = (const float*)d_in[12];
    const float* skip_b = (const float*)d_in[13];
    const float* out1_w = (const float*)d_in[14];
    const float* out1_b = (const float*)d_in[15];
    const float* out2_w = (const float*)d_in[16];
    const float* out2_b = (const float*)d_in[17];
    float* out = (float*)d_out;

    cudaFuncSetAttribute(k_conv_t, cudaFuncAttributeMaxDynamicSharedMemorySize,
                         K2_SMEM);
    cudaFuncSetAttribute(k_layers_f, cudaFuncAttributeMaxDynamicSharedMemorySize,
                         K3_SMEM);

    k_prep<<<128, 256>>>(A, gcn_w, skip_w, res_w, out1_w, out2_w, ct_w, cs_w);
    k_conv_t<<<1024, 512, K2_SMEM>>>(X, in_w, in_b, ct_b, cs_b);
    k_layers_f<<<4096, 256, K3_SMEM>>>(X, in_w, in_b, gcn_b, res_b, skip_b,
                                       out1_b, out2_b, out);
}

// round 15
// speedup vs baseline: 3.4927x; 1.0912x over previous
#include <cuda_runtime.h>
#include <cuda_bf16.h>
#include <math.h>
#include <stdint.h>

// Problem constants: B=8, T=512, N=128, F=16, H=32, L=4
#define BTNH_ 16777216ull   // 8*512*128*32

// Scratch (allocation-free: static device globals)
__device__ float g_tcn[4ull * 16777216ull];  // [l][b][t][n][o]
// Precomputed constant fragments (filled by k_prep each launch)
__device__ uint32_t g_afragH[8192];  // A frags: [mt8][ks8][lane32][4]
__device__ uint32_t g_afragL[8192];
__device__ uint32_t g_wH32[6912];    // gemm wts: 12x512 + out1@6144 + out2@6656
__device__ uint32_t g_wL32[6912];
__device__ uint32_t g_cwH[8192];     // conv wts: [(l*2+conv)]x1024
__device__ uint32_t g_cwL[8192];

// ====================== common helpers ======================
__device__ __forceinline__ uint32_t smem_u32(const void* p) {
    uint32_t a;
    asm("{ .reg .u64 t; cvta.to.shared.u64 t, %1; cvt.u32.u64 %0, t; }"
        : "=r"(a) : "l"(p));
    return a;
}
__device__ __forceinline__ void ldmat4(uint32_t r[4], uint32_t addr) {
    asm volatile("ldmatrix.sync.aligned.m8n8.x4.shared.b16 {%0,%1,%2,%3}, [%4];"
                 : "=r"(r[0]), "=r"(r[1]), "=r"(r[2]), "=r"(r[3]) : "r"(addr));
}
__device__ __forceinline__ void mma16816(float d[4], const uint32_t a[4],
                                         uint32_t b0, uint32_t b1) {
    asm volatile(
        "mma.sync.aligned.m16n8k16.row.col.f32.bf16.bf16.f32 "
        "{%0,%1,%2,%3}, {%4,%5,%6,%7}, {%8,%9}, {%0,%1,%2,%3};"
        : "+f"(d[0]), "+f"(d[1]), "+f"(d[2]), "+f"(d[3])
        : "r"(a[0]), "r"(a[1]), "r"(a[2]), "r"(a[3]), "r"(b0), "r"(b1));
}
__device__ __forceinline__ uint32_t pack_bf16(__nv_bfloat16 lo, __nv_bfloat16 hi) {
    return (uint32_t)__bfloat16_as_ushort(lo) |
           ((uint32_t)__bfloat16_as_ushort(hi) << 16);
}
__device__ __forceinline__ void split2(float v0, float v1, uint32_t& hw,
                                       uint32_t& lw) {
    __nv_bfloat16 h0 = __float2bfloat16(v0), h1 = __float2bfloat16(v1);
    hw = pack_bf16(h0, h1);
    lw = pack_bf16(__float2bfloat16(v0 - __bfloat162float(h0)),
                   __float2bfloat16(v1 - __bfloat162float(h1)));
}

// ---------------------------------------------------------------------------
// K0: fragment prep — A frags, gemm-weight frags, conv-weight frags.
// ---------------------------------------------------------------------------
__global__ void k_prep(const float* __restrict__ A,
                       const float* __restrict__ gcn_w,
                       const float* __restrict__ skip_w,
                       const float* __restrict__ res_w,
                       const float* __restrict__ out1_w,
                       const float* __restrict__ out2_w,
                       const float* __restrict__ ct_w,
                       const float* __restrict__ cs_w) {
    int tid = blockIdx.x * blockDim.x + threadIdx.x;
    int nthr = gridDim.x * blockDim.x;

    // A frags: m16n8k16 A-operand layout, 8 mtiles x 8 ks x 32 lanes x 4 words
    for (int idx = tid; idx < 2048; idx += nthr) {
        int mt = idx >> 8, ks = (idx >> 5) & 7, lane = idx & 31;
        int r = lane >> 2, c = lane & 3;
        int row = mt * 16 + r, k = ks * 16 + 2 * c;
        uint32_t base = (uint32_t)idx * 4;
#pragma unroll
        for (int j = 0; j < 4; j++) {
            int rr = row + (j & 1) * 8;
            int kk = k + (j >> 1) * 8;
            uint32_t hw, lw;
            split2(A[rr * 128 + kk], A[rr * 128 + kk + 1], hw, lw);
            g_afragH[base + j] = hw;
            g_afragL[base + j] = lw;
        }
    }
    // gemm weights: 13 matrices x 512 words (lane-keyed frag layout)
    for (int idx = tid; idx < 6656; idx += nthr) {
        int m = idx >> 9, i = idx & 511;
        const float* W;
        if (m == 12) W = out1_w;
        else {
            int l = m / 3, kind = m % 3;
            W = (kind == 0 ? gcn_w : kind == 1 ? skip_w : res_w) + l * 1024;
        }
        int cp = i >> 5, o = i & 31;
        uint32_t hw, lw;
        split2(W[(2 * cp) * 32 + o], W[(2 * cp + 1) * 32 + o], hw, lw);
        int kc = cp >> 3, r = cp & 7;
        int e = (kc * 4 + (o >> 3)) * 32 + (((o & 7) << 2) | (r & 3));
        int slot = m * 512 + e * 2 + (r >> 2);
        g_wH32[slot] = hw;
        g_wL32[slot] = lw;
    }
    // out2: 256 words at offset 6656
    for (int idx = tid; idx < 256; idx += nthr) {
        int cp = idx >> 4, o = idx & 15;
        uint32_t hw, lw;
        split2(out2_w[(2 * cp) * 16 + o], out2_w[(2 * cp + 1) * 16 + o], hw, lw);
        int kc = cp >> 3, r = cp & 7;
        int e = (kc * 2 + (o >> 3)) * 32 + (((o & 7) << 2) | (r & 3));
        g_wH32[6656 + e * 2 + (r >> 2)] = hw;
        g_wL32[6656 + e * 2 + (r >> 2)] = lw;
    }
    // conv weights: 8 matrices (l*2+conv) x 1024 words
    for (int idx = tid; idx < 8192; idx += nthr) {
        int cv = idx >> 10, i = idx & 1023;
        int l = cv >> 1;
        const float* W = ((cv & 1) ? cs_w : ct_w) + l * 2048;
        int krow = i >> 5, o = i & 31;
        int k0 = krow * 2;
        const float* src = W + (k0 >> 5) * 1024 + (k0 & 31) * 32 + o;
        uint32_t hw, lw;
        split2(src[0], src[32], hw, lw);
        int ks = krow >> 3, r = krow & 7;
        int e = (ks * 4 + (o >> 3)) * 32 + (((o & 7) << 2) | (r & 3));
        int slot = cv * 1024 + e * 2 + (r >> 2);
        g_cwH[slot] = hw;
        g_cwL[slot] = lw;
    }
}

// ---------------------------------------------------------------------------
// K2: fused input-proj (x_a/x_b) + gated dilated causal convs (HMMA).
// Activations use MUFU-based __fdividef (no IEEE div sequences).
// ---------------------------------------------------------------------------
#define XAH_B 0
#define XAL_B 41600
#define XBH_B 83200
#define XBL_B 124800
#define K2_SMEM 166400
// proj temp (inside XBL region, 41600 B available)
#define TXI_B XBL_B            // 512*17 floats = 34816 B
#define TWI_B (XBL_B + 34816)  // 16*64 floats  = 4096 B
#define TBI_B (XBL_B + 38912)  // 64 floats     = 256 B

__device__ __forceinline__ void conv_mma(uint32_t sbase,
                                         uint32_t xh, uint32_t xl,
                                         const uint2* __restrict__ wH2,
                                         const uint2* __restrict__ wL2,
                                         const float* __restrict__ bias,
                                         int tau0w, int lane, int d,
                                         float acc[2][4][4]) {
#pragma unroll
    for (int nt = 0; nt < 4; nt++) {
        float2 bv = __ldg((const float2*)(bias + nt * 8 + (lane & 3) * 2));
#pragma unroll
        for (int mt = 0; mt < 2; mt++) {
            acc[mt][nt][0] = bv.x; acc[mt][nt][1] = bv.y;
            acc[mt][nt][2] = bv.x; acc[mt][nt][3] = bv.y;
        }
    }
    int rbase = 8 + tau0w + (lane & 15);
    int chan = (lane >> 4) * 8;
#pragma unroll
    for (int ks = 0; ks < 4; ks++) {
        int tsh = (ks < 2) ? d : 0;
        int ch = chan + (ks & 1) * 16;
        uint32_t arow = (uint32_t)((rbase - tsh) * 80 + ch * 2);
        uint32_t ah[2][4], al[2][4];
        ldmat4(ah[0], sbase + xh + arow);
        ldmat4(ah[1], sbase + xh + arow + 16 * 80);
        ldmat4(al[0], sbase + xl + arow);
        ldmat4(al[1], sbase + xl + arow + 16 * 80);
#pragma unroll
        for (int nt = 0; nt < 4; nt++) {
            uint2 h2 = __ldg(&wH2[(ks * 4 + nt) * 32 + lane]);
            uint2 l2 = __ldg(&wL2[(ks * 4 + nt) * 32 + lane]);
#pragma unroll
            for (int mt = 0; mt < 2; mt++) {
                mma16816(acc[mt][nt], ah[mt], h2.x, h2.y);
                mma16816(acc[mt][nt], ah[mt], l2.x, l2.y);
                mma16816(acc[mt][nt], al[mt], h2.x, h2.y);
            }
        }
    }
}

__global__ void __launch_bounds__(512, 1) k_conv_t(const float* __restrict__ X,
                                                   const float* __restrict__ in_w,
                                                   const float* __restrict__ in_b,
                                                   const float* __restrict__ ct_b,
                                                   const float* __restrict__ cs_b) {
    extern __shared__ char smem[];
    uint32_t sbase = smem_u32(smem);
    int tid = threadIdx.x, lane = tid & 31, warp = tid >> 5;
    int bn = blockIdx.x, b = bn >> 7, n = bn & 127;
    int tau0w = warp * 32;

    // zero causal pads for XAH/XAL/XBH now (XBL region holds proj temp)
    if (tid < 160) {
        ((uint32_t*)(smem + XAH_B))[tid] = 0;
        ((uint32_t*)(smem + XAL_B))[tid] = 0;
        ((uint32_t*)(smem + XBH_B))[tid] = 0;
    }
    // ---- stage proj temp: raw X rows (contiguous!) + weights + bias ----
    {
        float* sXin = (float*)(smem + TXI_B);
        const float* Xb = X + (size_t)bn * 8192;  // 512 rows x 16 floats
        for (int i = tid; i < 8192; i += 512) {
            int t = i >> 4, f = i & 15;
            sXin[t * 17 + f] = Xb[i];
        }
        float* sWin = (float*)(smem + TWI_B);
        for (int i = tid; i < 1024; i += 512) {
            int f = i >> 6, o = i & 63;
            sWin[i] = in_w[f * 96 + o];
        }
        if (tid < 64) ((float*)(smem + TBI_B))[tid] = in_b[tid];
    }
    __syncthreads();

    // ---- in-kernel proj: thread = (col-pair tcp, tau-group) ----
    uint32_t xbl_st[16];
    {
        const float* sXin = (const float*)(smem + TXI_B);
        const float* sWin = (const float*)(smem + TWI_B);
        const float* sBin = (const float*)(smem + TBI_B);
        int tcp = tid & 15, tt0 = tid >> 4;
        float wa0[16], wa1[16], wb0[16], wb1[16];
#pragma unroll
        for (int f = 0; f < 16; f++) {
            const float* wr = sWin + f * 64 + 2 * tcp;
            wa0[f] = wr[0]; wa1[f] = wr[1];
            wb0[f] = wr[32]; wb1[f] = wr[33];
        }
        float ba0 = sBin[2 * tcp], ba1 = sBin[2 * tcp + 1];
        float bb0 = sBin[32 + 2 * tcp], bb1 = sBin[32 + 2 * tcp + 1];
#pragma unroll 2
        for (int it = 0; it < 16; it++) {
            int tau = it * 32 + tt0;
            const float* xr = sXin + tau * 17;
            float a0 = ba0, a1 = ba1, b0v = bb0, b1v = bb1;
#pragma unroll
            for (int f = 0; f < 16; f++) {
                float xv = xr[f];
                a0 = fmaf(xv, wa0[f], a0);
                a1 = fmaf(xv, wa1[f], a1);
                b0v = fmaf(xv, wb0[f], b0v);
                b1v = fmaf(xv, wb1[f], b1v);
            }
            uint32_t hw, lw;
            uint32_t w = (uint32_t)((8 + tau) * 20 + tcp);
            split2(a0, a1, hw, lw);
            ((uint32_t*)(smem + XAH_B))[w] = hw;
            ((uint32_t*)(smem + XAL_B))[w] = lw;
            split2(b0v, b1v, hw, xbl_st[it]);
            ((uint32_t*)(smem + XBH_B))[w] = hw;
        }
    }
    __syncthreads();  // proj temp reads done -> XBL region reusable
    if (tid < 160) ((uint32_t*)(smem + XBL_B))[tid] = 0;
    {
        int tcp = tid & 15, tt0 = tid >> 4;
#pragma unroll
        for (int it = 0; it < 16; it++) {
            uint32_t w = (uint32_t)((8 + it * 32 + tt0) * 20 + tcp);
            ((uint32_t*)(smem + XBL_B))[w] = xbl_st[it];
        }
    }
    __syncthreads();  // XBL staged; layers are barrier-free from here

#pragma unroll 1
    for (int l = 0; l < 4; l++) {
        int d = 1 << l;
        float ta[2][4][4];
        conv_mma(sbase, XAH_B, XAL_B, (const uint2*)(g_cwH + (l * 2) * 1024),
                 (const uint2*)(g_cwL + (l * 2) * 1024), ct_b + l * 32, tau0w,
                 lane, d, ta);
#pragma unroll
        for (int mt = 0; mt < 2; mt++)
#pragma unroll
            for (int nt = 0; nt < 4; nt++)
#pragma unroll
                for (int q = 0; q < 4; q++) {
                    float a = ta[mt][nt][q];
                    float t = __expf(-2.f * fabsf(a));
                    float r = __fdividef(1.f - t, 1.f + t);
                    ta[mt][nt][q] = copysignf(r, a);
                }
        float sg[2][4][4];
        conv_mma(sbase, XBH_B, XBL_B, (const uint2*)(g_cwH + (l * 2 + 1) * 1024),
                 (const uint2*)(g_cwL + (l * 2 + 1) * 1024), cs_b + l * 32, tau0w,
                 lane, d, sg);

        float* outl = g_tcn + (size_t)l * BTNH_ + ((size_t)b * 512) * 4096 + n * 32;
#pragma unroll
        for (int mt = 0; mt < 2; mt++)
#pragma unroll
            for (int nt = 0; nt < 4; nt++) {
                float v[4];
#pragma unroll
                for (int q = 0; q < 4; q++) {
                    float s = __fdividef(1.f, 1.f + __expf(-sg[mt][nt][q]));
                    v[q] = ta[mt][nt][q] * s;
                }
                int r = tau0w + mt * 16 + (lane >> 2);
                int o0 = nt * 8 + (lane & 3) * 2;
                *(float2*)(outl + (size_t)r * 4096 + o0) = make_float2(v[0], v[1]);
                *(float2*)(outl + (size_t)(r + 8) * 4096 + o0) =
                    make_float2(v[2], v[3]);
            }
    }
}

// ---------------------------------------------------------------------------
// K3: fused x_res proj + fully-HMMA layer chain (round-14 form, unchanged).
// ---------------------------------------------------------------------------
#define SXH_B   0         // X^T hi bf16 [32 o][136 j]
#define SXL_B   8704
#define K3_SMEM 17408

__device__ __forceinline__ void gemm32(float d[4][4], const uint32_t ah[2][4],
                                       const uint32_t al[2][4],
                                       const uint2* __restrict__ wH,
                                       const uint2* __restrict__ wL,
                                       int lane) {
#pragma unroll
    for (int kc = 0; kc < 2; kc++)
#pragma unroll
        for (int nt = 0; nt < 4; nt++) {
            uint2 h2 = __ldg(&wH[(kc * 4 + nt) * 32 + lane]);
            uint2 l2 = __ldg(&wL[(kc * 4 + nt) * 32 + lane]);
            mma16816(d[nt], ah[kc], h2.x, h2.y);
            mma16816(d[nt], ah[kc], l2.x, l2.y);
            mma16816(d[nt], al[kc], h2.x, h2.y);
        }
}
__device__ __forceinline__ void conv_frags(const float d[4][4], uint32_t ah[2][4],
                                           uint32_t al[2][4]) {
#pragma unroll
    for (int kc = 0; kc < 2; kc++)
#pragma unroll
        for (int r = 0; r < 4; r++) {
            int nt = 2 * kc + (r >> 1), qs = (r & 1) * 2;
            split2(d[nt][qs], d[nt][qs + 1], ah[kc][r], al[kc][r]);
        }
}
__device__ __forceinline__ void bias_add(float d[4][4],
                                         const float* __restrict__ bptr,
                                         int lane) {
#pragma unroll
    for (int nt = 0; nt < 4; nt++) {
        float2 bv = __ldg((const float2*)(bptr + nt * 8 + 2 * (lane & 3)));
        d[nt][0] += bv.x; d[nt][1] += bv.y;
        d[nt][2] += bv.x; d[nt][3] += bv.y;
    }
}

__global__ void __launch_bounds__(256, 2) k_layers_f(
    const float* __restrict__ X, const float* __restrict__ in_w,
    const float* __restrict__ in_b, const float* __restrict__ gcn_b,
    const float* __restrict__ res_b, const float* __restrict__ skip_b,
    const float* __restrict__ out1_b, const float* __restrict__ out2_b,
    float* __restrict__ out) {
    extern __shared__ char smem[];
    uint32_t sbase = smem_u32(smem);
    int tid = threadIdx.x;
    int lane = tid & 31;
    int g = tid >> 5;
    int row0 = g * 16;
    int bt = blockIdx.x;
    size_t base = (size_t)bt * 4096;

    // ---- x_res proj: temp in SXH/SXL region (dead until first X-split) ----
    float xres[4][4];
    {
        float* sXin = (float*)(smem);            // 128*17 floats = 8704 B
        float* sWin = (float*)(smem + 8704);     // 16*32 floats  = 2048 B
        float* sBin = (float*)(smem + 10752);    // 32 floats
        const float* Xbt = X + (size_t)bt * 2048;  // contiguous [128][16]
        for (int i = tid; i < 2048; i += 256) {
            int nn = i >> 4, f = i & 15;
            sXin[nn * 17 + f] = Xbt[i];
        }
        for (int i = tid; i < 512; i += 256) {
            int f = i >> 5, o = i & 31;
            sWin[i] = in_w[f * 96 + 64 + o];
        }
        if (tid < 32) sBin[tid] = in_b[64 + tid];
        __syncthreads();
#pragma unroll
        for (int nt = 0; nt < 4; nt++) {
            int oc0 = nt * 8 + 2 * (lane & 3);
            float b0 = sBin[oc0], b1 = sBin[oc0 + 1];
#pragma unroll
            for (int rg = 0; rg < 2; rg++) {
                int ic = row0 + (lane >> 2) + rg * 8;
                const float* xr = sXin + ic * 17;
                float s0 = b0, s1 = b1;
#pragma unroll
                for (int f = 0; f < 16; f++) {
                    float xv = xr[f];
                    s0 = fmaf(xv, sWin[f * 32 + oc0], s0);
                    s1 = fmaf(xv, sWin[f * 32 + oc0 + 1], s1);
                }
                xres[nt][rg * 2] = s0;
                xres[nt][rg * 2 + 1] = s1;
            }
        }
        __syncthreads();  // temp reads done before X-split overwrites
    }

    // ---- B-operand ldmatrix addressing (X-split smem) ----
    int bn_row = ((lane >> 4) << 3) + (lane & 7);
    int bk_half = (lane >> 3) & 1;
    uint32_t bh_base =
        sbase + SXH_B + (uint32_t)((bn_row * 136 + bk_half * 8) * 2);
    uint32_t bl_base =
        sbase + SXL_B + (uint32_t)((bn_row * 136 + bk_half * 8) * 2);

    float skip[4][4];
#pragma unroll
    for (int nt = 0; nt < 4; nt++)
#pragma unroll
        for (int q = 0; q < 4; q++) skip[nt][q] = 0.f;

    const uint4* aH4 = (const uint4*)g_afragH;
    const uint4* aL4 = (const uint4*)g_afragL;

    for (int l = 0; l < 4; l++) {
        // ---- X-split write from xres frags into SXH/SXL ----
#pragma unroll
        for (int nt = 0; nt < 4; nt++)
#pragma unroll
            for (int q = 0; q < 4; q++) {
                int oc = nt * 8 + 2 * (lane & 3) + (q & 1);
                int ic = row0 + (lane >> 2) + (q >> 1) * 8;
                float v = xres[nt][q];
                __nv_bfloat16 hi = __float2bfloat16(v);
                __nv_bfloat16 lo = __float2bfloat16(v - __bfloat162float(hi));
                *(__nv_bfloat16*)(smem + SXH_B + (oc * 136 + ic) * 2) = hi;
                *(__nv_bfloat16*)(smem + SXL_B + (oc * 136 + ic) * 2) = lo;
            }
        __syncthreads();  // (1) X-split visible

        // ---- A-mix MMA: acc = A @ X (3-pass split); A frags via LDG ----
        float acc[4][4];
#pragma unroll
        for (int nt = 0; nt < 4; nt++)
#pragma unroll
            for (int q = 0; q < 4; q++) acc[nt][q] = 0.f;
#pragma unroll
        for (int ks = 0; ks < 8; ks++) {
            uint32_t kb = (uint32_t)(ks * 32);
            uint32_t ah[4], al[4], bh[2][4], bl[2][4];
            uint4 va = __ldg(&aH4[(g * 8 + ks) * 32 + lane]);
            uint4 vl = __ldg(&aL4[(g * 8 + ks) * 32 + lane]);
            ah[0] = va.x; ah[1] = va.y; ah[2] = va.z; ah[3] = va.w;
            al[0] = vl.x; al[1] = vl.y; al[2] = vl.z; al[3] = vl.w;
            ldmat4(bh[0], bh_base + kb);
            ldmat4(bh[1], bh_base + 16 * 272 + kb);
            ldmat4(bl[0], bl_base + kb);
            ldmat4(bl[1], bl_base + 16 * 272 + kb);
#pragma unroll
            for (int nt = 0; nt < 4; nt++) {
                uint32_t b0h = bh[nt >> 1][(nt & 1) * 2];
                uint32_t b1h = bh[nt >> 1][(nt & 1) * 2 + 1];
                uint32_t b0l = bl[nt >> 1][(nt & 1) * 2];
                uint32_t b1l = bl[nt >> 1][(nt & 1) * 2 + 1];
                mma16816(acc[nt], ah, b0h, b1h);
                mma16816(acc[nt], ah, b0l, b1l);
                mma16816(acc[nt], al, b0h, b1h);
            }
        }
        __syncthreads();  // (2) ldmatrix reads done (next layer rewrites X)

        // ---- gcn: h = AX @ gcn_w + gcn_b + tcn ----
        uint32_t fh[2][4], fl[2][4];
        conv_frags(acc, fh, fl);
        float h[4][4];
#pragma unroll
        for (int nt = 0; nt < 4; nt++) {
            float2 bv = __ldg((const float2*)(gcn_b + l * 32 + nt * 8 +
                                              2 * (lane & 3)));
            h[nt][0] = bv.x; h[nt][1] = bv.y;
            h[nt][2] = bv.x; h[nt][3] = bv.y;
        }
        gemm32(h, fh, fl, (const uint2*)(g_wH32 + (l * 3) * 512),
               (const uint2*)(g_wL32 + (l * 3) * 512), lane);
        {
            const float* tcnp = g_tcn + (size_t)l * BTNH_ + base;
#pragma unroll
            for (int nt = 0; nt < 4; nt++)
#pragma unroll
                for (int rg = 0; rg < 2; rg++) {
                    float2 tv = *(const float2*)(tcnp +
                        (size_t)(row0 + (lane >> 2) + rg * 8) * 32 + nt * 8 +
                        2 * (lane & 3));
                    h[nt][rg * 2] += tv.x;
                    h[nt][rg * 2 + 1] += tv.y;
                }
        }
        // ---- skip += h @ skip_w + b ;  xres += h @ res_w + b ----
        conv_frags(h, fh, fl);
        bias_add(skip, skip_b + l * 32, lane);
        gemm32(skip, fh, fl, (const uint2*)(g_wH32 + (l * 3 + 1) * 512),
               (const uint2*)(g_wL32 + (l * 3 + 1) * 512), lane);
        bias_add(xres, res_b + l * 32, lane);
        gemm32(xres, fh, fl, (const uint2*)(g_wH32 + (l * 3 + 2) * 512),
               (const uint2*)(g_wL32 + (l * 3 + 2) * 512), lane);
    }

    // ---- head (all operands in regs/global; no barriers) ----
    {
        uint32_t fh[2][4], fl[2][4];
#pragma unroll
        for (int nt = 0; nt < 4; nt++)
#pragma unroll
            for (int q = 0; q < 4; q++) skip[nt][q] = fmaxf(skip[nt][q], 0.f);
        conv_frags(skip, fh, fl);
        float h2[4][4];
#pragma unroll
        for (int nt = 0; nt < 4; nt++) {
            float2 bv = __ldg((const float2*)(out1_b + nt * 8 + 2 * (lane & 3)));
            h2[nt][0] = bv.x; h2[nt][1] = bv.y;
            h2[nt][2] = bv.x; h2[nt][3] = bv.y;
        }
        gemm32(h2, fh, fl, (const uint2*)(g_wH32 + 6144),
               (const uint2*)(g_wL32 + 6144), lane);
#pragma unroll
        for (int nt = 0; nt < 4; nt++)
#pragma unroll
            for (int q = 0; q < 4; q++) h2[nt][q] = fmaxf(h2[nt][q], 0.f);
        conv_frags(h2, fh, fl);

        float o2[2][4];
#pragma unroll
        for (int nt = 0; nt < 2; nt++) {
            float2 bv = __ldg((const float2*)(out2_b + nt * 8 + 2 * (lane & 3)));
            o2[nt][0] = bv.x; o2[nt][1] = bv.y;
            o2[nt][2] = bv.x; o2[nt][3] = bv.y;
        }
        const uint2* w2H = (const uint2*)(g_wH32 + 6656);
        const uint2* w2L = (const uint2*)(g_wL32 + 6656);
#pragma unroll
        for (int kc = 0; kc < 2; kc++)
#pragma unroll
            for (int nt = 0; nt < 2; nt++) {
                uint2 h2w = __ldg(&w2H[(kc * 2 + nt) * 32 + lane]);
                uint2 l2w = __ldg(&w2L[(kc * 2 + nt) * 32 + lane]);
                mma16816(o2[nt], fh[kc], h2w.x, h2w.y);
                mma16816(o2[nt], fh[kc], l2w.x, l2w.y);
                mma16816(o2[nt], fl[kc], h2w.x, h2w.y);
            }
        float* op = out + (size_t)bt * 2048;
#pragma unroll
        for (int nt = 0; nt < 2; nt++)
#pragma unroll
            for (int rg = 0; rg < 2; rg++)
                *(float2*)(op + (size_t)(row0 + (lane >> 2) + rg * 8) * 16 +
                           nt * 8 + 2 * (lane & 3)) =
                    make_float2(o2[nt][rg * 2], o2[nt][rg * 2 + 1]);
    }
}

// ---------------------------------------------------------------------------
extern "C" void kernel_launch(void* const* d_in, const int* in_sizes, int n_in,
                              void* d_out, int out_size) {
    const float* X = (const float*)d_in[0];
    const float* A = (const float*)d_in[1];
    const float* in_w = (const float*)d_in[2];
    const float* in_b = (const float*)d_in[3];
    const float* ct_w = (const float*)d_in[4];
    const float* ct_b = (const float*)d_in[5];
    const float* cs_w = (const float*)d_in[6];
    const float* cs_b = (const float*)d_in[7];
    const float* gcn_w = (const float*)d_in[8];
    const float* gcn_b = (const float*)d_in[9];
    const float* res_w = (const float*)d_in[10];
    const float* res_b = (const float*)d_in[11];
    const float* skip_w = (const float*)d_in[12];
    const float* skip_b = (const float*)d_in[13];
    const float* out1_w = (const float*)d_in[14];
    const float* out1_b = (const float*)d_in[15];
    const float* out2_w = (const float*)d_in[16];
    const float* out2_b = (const float*)d_in[17];
    float* out = (float*)d_out;

    cudaFuncSetAttribute(k_conv_t, cudaFuncAttributeMaxDynamicSharedMemorySize,
                         K2_SMEM);
    cudaFuncSetAttribute(k_layers_f, cudaFuncAttributeMaxDynamicSharedMemorySize,
                         K3_SMEM);

    k_prep<<<128, 256>>>(A, gcn_w, skip_w, res_w, out1_w, out2_w, ct_w, cs_w);
    k_conv_t<<<1024, 512, K2_SMEM>>>(X, in_w, in_b, ct_b, cs_b);
    k_layers_f<<<4096, 256, K3_SMEM>>>(X, in_w, in_b, gcn_b, res_b, skip_b,
                                       out1_b, out2_b, out);
}